// round 2
// baseline (speedup 1.0000x reference)
#include <cuda_runtime.h>
#include <cuda_bf16.h>
#include <math.h>

// Problem constants
#define B_   16
#define C_   128
#define N_   1024      // 32*32
#define H_   4
#define D_   32
#define CN   (C_*N_)   // 131072 elements per (proj, batch)

// ---------------- scratch (device globals; no allocations) ----------------
__device__ float g_conv[3][B_*CN];        // conv outputs, [p][b][c][n]
__device__ float g_qkv [3][B_*CN];        // head-major [p][(b*4+h)][n][d]
__device__ float g_mean[48];
__device__ float g_rstd[48];
__device__ double g_part[1536][2];
__device__ float g_bias4[H_*N_*N_];       // [h][n][m]  (16 MB, L2 resident)
__device__ float g_attn[B_*N_*C_];        // [b][n][c]

// bf16 split buffers
// padded input: [b][ci][34 rows][40 cols], row idx = y+1, col idx = x+1 (zeros elsewhere)
__device__ __align__(16) __nv_bfloat16 g_xpad_hi[B_*C_*34*40];
__device__ __align__(16) __nv_bfloat16 g_xpad_lo[B_*C_*34*40];
// weights: [p][((ky*3+kx)*128+co)*128+ci]
__device__ __align__(16) __nv_bfloat16 g_w_hi[3][9*128*128];
__device__ __align__(16) __nv_bfloat16 g_w_lo[3][9*128*128];

// =====================================================================
// Prep: split x into padded bf16 hi/lo
// =====================================================================
__global__ __launch_bounds__(256) void prep_x_kernel(const float* __restrict__ x)
{
    const int total = B_*C_*34*40;
    for (int e = blockIdx.x*256 + threadIdx.x; e < total; e += gridDim.x*256) {
        int xx = e % 40;
        int t  = e / 40;
        int yy = t % 34;
        int bc = t / 34;             // b*128+ci
        int y = yy - 1, c = xx - 1;
        float v = 0.f;
        if ((unsigned)y < 32u && (unsigned)c < 32u)
            v = x[(size_t)bc*1024 + y*32 + c];
        __nv_bfloat16 h = __float2bfloat16(v);
        float lo = v - __bfloat162float(h);
        g_xpad_hi[e] = h;
        g_xpad_lo[e] = __float2bfloat16(lo);
    }
}

// =====================================================================
// Prep: split + transpose weights
// =====================================================================
__global__ __launch_bounds__(256) void prep_w_kernel(
    const float* __restrict__ wq, const float* __restrict__ wk,
    const float* __restrict__ wv)
{
    int e = blockIdx.x*256 + threadIdx.x;   // 3*128*128*9 = 442368
    if (e >= 3*128*128*9) return;
    int kx = e % 3; int t = e / 3;
    int ky = t % 3; t /= 3;
    int ci = t % 128; t /= 128;
    int co = t % 128;
    int p  = t / 128;
    const float* w = (p == 0) ? wq : (p == 1) ? wk : wv;
    float v = w[((co*128 + ci)*3 + ky)*3 + kx];
    __nv_bfloat16 h = __float2bfloat16(v);
    float lo = v - __bfloat162float(h);
    int dst = ((ky*3 + kx)*128 + co)*128 + ci;
    g_w_hi[p][dst] = h;
    g_w_lo[p][dst] = __float2bfloat16(lo);
}

// =====================================================================
// bf16 mma helper
// =====================================================================
__device__ __forceinline__ void mma_bf16(float* d, const unsigned* A,
                                         unsigned b0, unsigned b1)
{
    asm volatile(
        "mma.sync.aligned.m16n8k16.row.col.f32.bf16.bf16.f32 "
        "{%0,%1,%2,%3},{%4,%5,%6,%7},{%8,%9},{%0,%1,%2,%3};"
        : "+f"(d[0]), "+f"(d[1]), "+f"(d[2]), "+f"(d[3])
        : "r"(A[0]), "r"(A[1]), "r"(A[2]), "r"(A[3]), "r"(b0), "r"(b1));
}

// =====================================================================
// Kernel 1: conv3x3 as bf16x3 tensor-core GEMM.
// Block: 128 co x 128 spatial (4 image rows). Grid (8 sp, 16 b, 3 p).
// 8 warps = 4(m) x 2(n); warp tile 32co x 64n.
// K loop: ky(3) x ci-chunk(8 of 16) x kx(3).
// =====================================================================
__global__ __launch_bounds__(256) void conv_mma_kernel()
{
    // a_sm: [split(2)][kx(3)][co(128)][k pad 24]  (ushort bf16 bits)
    __shared__ __align__(16) unsigned short a_sm[2*3*128*24];   // 36864 B
    // b_sm: [split(2)][ci(16)][r(4)][40]
    __shared__ __align__(16) unsigned short b_sm[2*16*4*40];    // 10240 B

    const int sp = blockIdx.x, b = blockIdx.y, p = blockIdx.z;
    const int tid = threadIdx.x, lane = tid & 31, wid = tid >> 5;
    const int wm = wid & 3, wn = wid >> 2;
    const int r0 = sp * 4;        // image row base
    const int n0 = sp * 128;      // spatial base

    const __nv_bfloat16* whi = g_w_hi[p];
    const __nv_bfloat16* wlo = g_w_lo[p];
    const __nv_bfloat16* xhi = g_xpad_hi + (size_t)b * (128*34*40);
    const __nv_bfloat16* xlo = g_xpad_lo + (size_t)b * (128*34*40);

    float acc[2][8][4];
#pragma unroll
    for (int mi = 0; mi < 2; mi++)
#pragma unroll
        for (int ni = 0; ni < 8; ni++)
#pragma unroll
            for (int j = 0; j < 4; j++) acc[mi][ni][j] = 0.f;

    const int ar  = lane >> 2;
    const int akq = (lane & 3) * 2;
    const int bn  = lane >> 2;
    const int k0  = (lane & 3) * 2;

    for (int ky = 0; ky < 3; ky++) {
        for (int ci0 = 0; ci0 < 128; ci0 += 16) {
            __syncthreads();
            // ---- stage A: all 3 kx, both splits : 1536 uint4 ----
            for (int u = tid; u < 1536; u += 256) {
                int half = u & 1;
                int co   = (u >> 1) & 127;
                int sk   = u >> 8;             // split*3+kx
                int split = sk / 3, kx = sk - split * 3;
                const __nv_bfloat16* src = (split ? wlo : whi)
                    + ((ky*3 + kx)*128 + co)*128 + ci0 + half*8;
                uint4 v = *reinterpret_cast<const uint4*>(src);
                *reinterpret_cast<uint4*>(
                    &a_sm[((sk*128) + co)*24 + half*8]) = v;
            }
            // ---- stage B: 640 uint4 ----
            for (int u = tid; u < 640; u += 256) {
                int seg = u % 5; int t = u / 5;
                int r  = t & 3;
                int ci = (t >> 2) & 15;
                int split = t >> 6;
                const __nv_bfloat16* src = (split ? xlo : xhi)
                    + ((size_t)(ci0 + ci)*34 + (r0 + r + ky))*40 + seg*8;
                uint4 v = *reinterpret_cast<const uint4*>(src);
                *reinterpret_cast<uint4*>(
                    &b_sm[(((split*16 + ci)*4 + r)*40) + seg*8]) = v;
            }
            __syncthreads();

#pragma unroll
            for (int kx = 0; kx < 3; kx++) {
                // A fragments (2 m-tiles, hi+lo)
                unsigned Ahi[2][4], Alo[2][4];
#pragma unroll
                for (int mi = 0; mi < 2; mi++) {
                    int co = wm*32 + mi*16 + ar;
                    int bh = (kx*128 + co)*24;            // split 0
                    int bl = ((3 + kx)*128 + co)*24;      // split 1
                    Ahi[mi][0] = *reinterpret_cast<const unsigned*>(&a_sm[bh + akq]);
                    Ahi[mi][1] = *reinterpret_cast<const unsigned*>(&a_sm[bh + 8*24 + akq]);
                    Ahi[mi][2] = *reinterpret_cast<const unsigned*>(&a_sm[bh + akq + 8]);
                    Ahi[mi][3] = *reinterpret_cast<const unsigned*>(&a_sm[bh + 8*24 + akq + 8]);
                    Alo[mi][0] = *reinterpret_cast<const unsigned*>(&a_sm[bl + akq]);
                    Alo[mi][1] = *reinterpret_cast<const unsigned*>(&a_sm[bl + 8*24 + akq]);
                    Alo[mi][2] = *reinterpret_cast<const unsigned*>(&a_sm[bl + akq + 8]);
                    Alo[mi][3] = *reinterpret_cast<const unsigned*>(&a_sm[bl + 8*24 + akq + 8]);
                }
#pragma unroll
                for (int ni = 0; ni < 8; ni++) {
                    int n  = wn*64 + ni*8 + bn;
                    int rr = n >> 5;
                    int cc = (n & 31) + kx;
                    int o00 = ((k0      )*4 + rr)*40 + cc;          // split 0
                    int o10 = (((16+k0) )*4 + rr)*40 + cc;          // split 1
                    unsigned h0 = b_sm[o00];
                    unsigned h1 = b_sm[o00 + 160];       // k0+1 : +4*40
                    unsigned h8 = b_sm[o00 + 1280];      // k0+8 : +8*4*40
                    unsigned h9 = b_sm[o00 + 1440];      // k0+9
                    unsigned Bh0 = h0 | (h1 << 16);
                    unsigned Bh1 = h8 | (h9 << 16);
                    unsigned l0 = b_sm[o10];
                    unsigned l1 = b_sm[o10 + 160];
                    unsigned l8 = b_sm[o10 + 1280];
                    unsigned l9 = b_sm[o10 + 1440];
                    unsigned Bl0 = l0 | (l1 << 16);
                    unsigned Bl1 = l8 | (l9 << 16);
#pragma unroll
                    for (int mi = 0; mi < 2; mi++) {
                        mma_bf16(acc[mi][ni], Ahi[mi], Bh0, Bh1);
                        mma_bf16(acc[mi][ni], Ahi[mi], Bl0, Bl1);
                        mma_bf16(acc[mi][ni], Alo[mi], Bh0, Bh1);
                    }
                }
            }
        }
    }

    // epilogue
    float* outb = &g_conv[p][(size_t)b * CN];
#pragma unroll
    for (int mi = 0; mi < 2; mi++) {
        int row = wm*32 + mi*16 + ar;
#pragma unroll
        for (int ni = 0; ni < 8; ni++) {
            int col = n0 + wn*64 + ni*8 + (lane & 3)*2;
            float2 v0; v0.x = acc[mi][ni][0]; v0.y = acc[mi][ni][1];
            float2 v1; v1.x = acc[mi][ni][2]; v1.y = acc[mi][ni][3];
            *reinterpret_cast<float2*>(&outb[(size_t)row*1024 + col])     = v0;
            *reinterpret_cast<float2*>(&outb[(size_t)(row+8)*1024 + col]) = v1;
        }
    }
}

// =====================================================================
// Kernel 2a/2b: deterministic two-stage mean/var per (proj, batch)
// =====================================================================
__global__ __launch_bounds__(256) void gn_reduce1_kernel()
{
    const int blk = blockIdx.x;           // 1536 = 48 pb * 32 segs
    const int pb = blk >> 5, seg = blk & 31;
    const float* src = &g_conv[0][0] + (size_t)pb*CN + seg*4096;
    const int tid = threadIdx.x;
    double s = 0.0, s2 = 0.0;
    for (int i = tid; i < 4096; i += 256) {
        float v = src[i];
        s += (double)v; s2 += (double)v * (double)v;
    }
    __shared__ double a[256], a2[256];
    a[tid] = s; a2[tid] = s2;
    __syncthreads();
    for (int st = 128; st > 0; st >>= 1) {
        if (tid < st) { a[tid] += a[tid + st]; a2[tid] += a2[tid + st]; }
        __syncthreads();
    }
    if (tid == 0) { g_part[blk][0] = a[0]; g_part[blk][1] = a2[0]; }
}

__global__ void gn_reduce2_kernel()
{
    const int pb = blockIdx.x;            // 48
    const int l = threadIdx.x;            // 32
    double s  = g_part[pb*32 + l][0];
    double s2 = g_part[pb*32 + l][1];
    for (int off = 16; off > 0; off >>= 1) {
        s  += __shfl_down_sync(0xffffffffu, s, off);
        s2 += __shfl_down_sync(0xffffffffu, s2, off);
    }
    if (l == 0) {
        double mean = s / (double)CN;
        double var  = s2 / (double)CN - mean * mean;
        g_mean[pb] = (float)mean;
        g_rstd[pb] = (float)(1.0 / sqrt(var + 1e-6));
    }
}

// =====================================================================
// Kernel 3: GroupNorm apply + exact GELU + transpose to head-major layout
// =====================================================================
__global__ __launch_bounds__(256) void norm_gelu_kernel(
    const float* __restrict__ gq, const float* __restrict__ bq,
    const float* __restrict__ gk, const float* __restrict__ bk,
    const float* __restrict__ gv, const float* __restrict__ bv)
{
    const int pb = blockIdx.z;
    const int p = pb >> 4, b = pb & 15;
    const int h = blockIdx.y;
    const int n0 = blockIdx.x * 64;
    const int tid = threadIdx.x;

    const float* gamma = (p == 0) ? gq : (p == 1) ? gk : gv;
    const float* beta  = (p == 0) ? bq : (p == 1) ? bk : bv;
    const float mean = g_mean[pb];
    const float rstd = g_rstd[pb];

    __shared__ float s[32][65];

    const float* src = g_conv[p] + ((size_t)b * 128 + h * 32) * N_;
    for (int e = tid; e < 2048; e += 256) {
        int d = e >> 6, nn = e & 63;
        float v = src[(size_t)d * N_ + n0 + nn];
        int c = h * 32 + d;
        v = (v - mean) * rstd * gamma[c] + beta[c];
        v = 0.5f * v * (1.0f + erff(v * 0.70710678118654752f));
        s[d][nn] = v;
    }
    __syncthreads();
    float* dst = g_qkv[p] + ((size_t)(b * 4 + h) * N_ + n0) * D_;
    for (int e = tid; e < 2048; e += 256) {
        int nn = e >> 5, d = e & 31;
        dst[nn * D_ + d] = s[d][nn];
    }
}

// =====================================================================
// Kernel 4: materialize bias[h][n][m] from table gather
// =====================================================================
__global__ __launch_bounds__(256) void bias_kernel(
    const float* __restrict__ table, const int* __restrict__ rel_index)
{
    const int n = blockIdx.x;
    for (int m = threadIdx.x; m < N_; m += 256) {
        int idx = rel_index[n * N_ + m];
        float4 t = *reinterpret_cast<const float4*>(table + idx * 4);
        g_bias4[(0 * N_ + n) * N_ + m] = t.x;
        g_bias4[(1 * N_ + n) * N_ + m] = t.y;
        g_bias4[(2 * N_ + n) * N_ + m] = t.z;
        g_bias4[(3 * N_ + n) * N_ + m] = t.w;
    }
}

// =====================================================================
// Kernel 5: attention (flash-style, online softmax).
// =====================================================================
__global__ __launch_bounds__(256) void attn_kernel()
{
    __shared__ float Qs[64 * 32];
    __shared__ float Ks[64 * 33];
    __shared__ float Vs[64 * 33];
    __shared__ float Ps[64 * 64];

    const int tid  = threadIdx.x;
    const int lane = tid & 31;
    const int wrp  = tid >> 5;
    const int qt   = blockIdx.x;
    const int bh   = blockIdx.y;
    const int b    = bh >> 2;
    const int h    = bh & 3;

    const float* qbase = g_qkv[0] + (size_t)bh * N_ * D_;
    const float* kbase = g_qkv[1] + (size_t)bh * N_ * D_;
    const float* vbase = g_qkv[2] + (size_t)bh * N_ * D_;

    for (int e = tid; e < 2048; e += 256)
        Qs[e] = qbase[qt * 64 * D_ + e];

    float m_run[8], l_run[8], acc[8];
#pragma unroll
    for (int rr = 0; rr < 8; rr++) {
        m_run[rr] = -INFINITY; l_run[rr] = 0.f; acc[rr] = 0.f;
    }

    for (int kc = 0; kc < 16; kc++) {
        const int m0 = kc * 64;
        __syncthreads();
        for (int e = tid; e < 2048; e += 256) {
            int mm = e >> 5, d = e & 31;
            Ks[mm * 33 + d] = kbase[(m0 + mm) * D_ + d];
            Vs[mm * 33 + d] = vbase[(m0 + mm) * D_ + d];
        }
        __syncthreads();

#pragma unroll
        for (int pass = 0; pass < 2; pass++) {
            const int mloc = pass * 32 + lane;
            float kreg[32];
#pragma unroll
            for (int kk = 0; kk < 32; kk++) kreg[kk] = Ks[mloc * 33 + kk];
#pragma unroll
            for (int rr = 0; rr < 8; rr++) {
                const int r = wrp * 8 + rr;
                const float4* qp = reinterpret_cast<const float4*>(Qs + r * 32);
                float s = 0.f;
#pragma unroll
                for (int q4 = 0; q4 < 8; q4++) {
                    float4 qv = qp[q4];
                    s += qv.x * kreg[q4 * 4 + 0];
                    s += qv.y * kreg[q4 * 4 + 1];
                    s += qv.z * kreg[q4 * 4 + 2];
                    s += qv.w * kreg[q4 * 4 + 3];
                }
                s += g_bias4[((size_t)h * N_ + qt * 64 + r) * N_ + m0 + mloc];
                Ps[r * 64 + mloc] = s;
            }
        }
        __syncwarp();

#pragma unroll
        for (int rr = 0; rr < 8; rr++) {
            const int r = wrp * 8 + rr;
            float s0 = Ps[r * 64 + lane];
            float s1 = Ps[r * 64 + lane + 32];
            float cm = fmaxf(s0, s1);
#pragma unroll
            for (int off = 16; off > 0; off >>= 1)
                cm = fmaxf(cm, __shfl_xor_sync(0xffffffffu, cm, off));
            float mnew = fmaxf(m_run[rr], cm);
            float corr = expf(m_run[rr] - mnew);
            float p0 = expf(s0 - mnew);
            float p1 = expf(s1 - mnew);
            Ps[r * 64 + lane]      = p0;
            Ps[r * 64 + lane + 32] = p1;
            float ls = p0 + p1;
#pragma unroll
            for (int off = 16; off > 0; off >>= 1)
                ls += __shfl_xor_sync(0xffffffffu, ls, off);
            l_run[rr] = l_run[rr] * corr + ls;
            m_run[rr] = mnew;
            acc[rr]  *= corr;
        }
        __syncwarp();

#pragma unroll
        for (int sub = 0; sub < 2; sub++) {
            float vreg[32];
#pragma unroll
            for (int i = 0; i < 32; i++)
                vreg[i] = Vs[(sub * 32 + i) * 33 + lane];
#pragma unroll
            for (int rr = 0; rr < 8; rr++) {
                const int r = wrp * 8 + rr;
                const float4* pp = reinterpret_cast<const float4*>(Ps + r * 64 + sub * 32);
                float a = acc[rr];
#pragma unroll
                for (int i4 = 0; i4 < 8; i4++) {
                    float4 pv = pp[i4];
                    a += pv.x * vreg[i4 * 4 + 0];
                    a += pv.y * vreg[i4 * 4 + 1];
                    a += pv.z * vreg[i4 * 4 + 2];
                    a += pv.w * vreg[i4 * 4 + 3];
                }
                acc[rr] = a;
            }
        }
    }

#pragma unroll
    for (int rr = 0; rr < 8; rr++) {
        const int n = qt * 64 + wrp * 8 + rr;
        g_attn[((size_t)b * N_ + n) * C_ + h * 32 + lane] = acc[rr] / l_run[rr];
    }
}

// =====================================================================
// Kernel 6: 1x1 conv (GEMM) + bias
// =====================================================================
__global__ __launch_bounds__(256) void outconv_kernel(
    const float* __restrict__ w, const float* __restrict__ bias,
    float* __restrict__ out)
{
    __shared__ float a_t[128][33];
    __shared__ float w_t[128][32];

    const int b  = blockIdx.y;
    const int n0 = blockIdx.x * 128;
    const int tid = threadIdx.x;
    const int nl  = tid & 63;
    const int cog = tid >> 6;

    float acc0[32], acc1[32];
#pragma unroll
    for (int j = 0; j < 32; j++) { acc0[j] = 0.f; acc1[j] = 0.f; }

    for (int c0 = 0; c0 < 128; c0 += 32) {
        __syncthreads();
        for (int e = tid; e < 4096; e += 256) {
            int nn = e >> 5, cc = e & 31;
            a_t[nn][cc] = g_attn[((size_t)b * N_ + n0 + nn) * C_ + c0 + cc];
        }
        for (int e = tid; e < 4096; e += 256) {
            int co = e >> 5, cc = e & 31;
            w_t[co][cc] = w[co * 128 + c0 + cc];
        }
        __syncthreads();
#pragma unroll
        for (int cc = 0; cc < 32; cc++) {
            float a0 = a_t[nl][cc];
            float a1 = a_t[nl + 64][cc];
#pragma unroll
            for (int j = 0; j < 32; j++) {
                float wv = w_t[cog * 32 + j][cc];
                acc0[j] += a0 * wv;
                acc1[j] += a1 * wv;
            }
        }
    }
#pragma unroll
    for (int j = 0; j < 32; j++) {
        int co = cog * 32 + j;
        float bv = bias[co];
        out[((size_t)b * 128 + co) * N_ + n0 + nl]      = acc0[j] + bv;
        out[((size_t)b * 128 + co) * N_ + n0 + nl + 64] = acc1[j] + bv;
    }
}

// =====================================================================
extern "C" void kernel_launch(void* const* d_in, const int* in_sizes, int n_in,
                              void* d_out, int out_size)
{
    const float* x      = (const float*)d_in[0];
    const float* wq     = (const float*)d_in[1];
    const float* gq     = (const float*)d_in[2];
    const float* bq     = (const float*)d_in[3];
    const float* wk     = (const float*)d_in[4];
    const float* gk     = (const float*)d_in[5];
    const float* bk     = (const float*)d_in[6];
    const float* wv     = (const float*)d_in[7];
    const float* gv     = (const float*)d_in[8];
    const float* bv     = (const float*)d_in[9];
    const float* table  = (const float*)d_in[10];
    const int*   relidx = (const int*)  d_in[11];
    const float* out_w  = (const float*)d_in[12];
    const float* out_b  = (const float*)d_in[13];
    float* out = (float*)d_out;

    prep_x_kernel<<<2048, 256>>>(x);
    prep_w_kernel<<<1728, 256>>>(wq, wk, wv);

    conv_mma_kernel<<<dim3(8, 16, 3), 256>>>();

    gn_reduce1_kernel<<<1536, 256>>>();
    gn_reduce2_kernel<<<48, 32>>>();

    norm_gelu_kernel<<<dim3(16, 4, 48), 256>>>(gq, bq, gk, bk, gv, bv);

    bias_kernel<<<1024, 256>>>(table, relidx);

    attn_kernel<<<dim3(16, 64), 256>>>();

    outconv_kernel<<<dim3(8, 16), 256>>>(out_w, out_b, out);
}

// round 3
// speedup vs baseline: 1.0734x; 1.0734x over previous
#include <cuda_runtime.h>
#include <cuda_bf16.h>
#include <math.h>

// Problem constants
#define B_   16
#define C_   128
#define N_   1024      // 32*32
#define H_   4
#define D_   32
#define CN   (C_*N_)   // 131072 elements per (proj, batch)

typedef unsigned short ushort_t;

// ---------------- scratch (device globals; no allocations) ----------------
__device__ float g_conv[3][B_*CN];        // conv outputs, [p][b][c][n]
__device__ float g_qkv [3][B_*CN];        // head-major [p][(b*4+h)][n][d]
__device__ float g_mean[48];
__device__ float g_rstd[48];
__device__ float g_partf[1536][2];
__device__ float g_bias4[H_*N_*N_];       // [h][n][m]  (16 MB, L2 resident)
__device__ float g_attn[B_*N_*C_];        // [b][n][c]

// bf16 split buffers
__device__ __align__(16) __nv_bfloat16 g_xpad_hi[B_*C_*34*40];
__device__ __align__(16) __nv_bfloat16 g_xpad_lo[B_*C_*34*40];
__device__ __align__(16) __nv_bfloat16 g_w_hi[3][9*128*128];
__device__ __align__(16) __nv_bfloat16 g_w_lo[3][9*128*128];

// =====================================================================
// Prep: split x into padded bf16 hi/lo
// =====================================================================
__global__ __launch_bounds__(256) void prep_x_kernel(const float* __restrict__ x)
{
    const int total = B_*C_*34*40;
    for (int e = blockIdx.x*256 + threadIdx.x; e < total; e += gridDim.x*256) {
        int xx = e % 40;
        int t  = e / 40;
        int yy = t % 34;
        int bc = t / 34;
        int y = yy - 1, c = xx - 1;
        float v = 0.f;
        if ((unsigned)y < 32u && (unsigned)c < 32u)
            v = x[(size_t)bc*1024 + y*32 + c];
        __nv_bfloat16 h = __float2bfloat16(v);
        float lo = v - __bfloat162float(h);
        g_xpad_hi[e] = h;
        g_xpad_lo[e] = __float2bfloat16(lo);
    }
}

// =====================================================================
// Prep: split + transpose weights
// =====================================================================
__global__ __launch_bounds__(256) void prep_w_kernel(
    const float* __restrict__ wq, const float* __restrict__ wk,
    const float* __restrict__ wv)
{
    int e = blockIdx.x*256 + threadIdx.x;   // 3*128*128*9 = 442368
    if (e >= 3*128*128*9) return;
    int kx = e % 3; int t = e / 3;
    int ky = t % 3; t /= 3;
    int ci = t % 128; t /= 128;
    int co = t % 128;
    int p  = t / 128;
    const float* w = (p == 0) ? wq : (p == 1) ? wk : wv;
    float v = w[((co*128 + ci)*3 + ky)*3 + kx];
    __nv_bfloat16 h = __float2bfloat16(v);
    float lo = v - __bfloat162float(h);
    int dst = ((ky*3 + kx)*128 + co)*128 + ci;
    g_w_hi[p][dst] = h;
    g_w_lo[p][dst] = __float2bfloat16(lo);
}

// =====================================================================
// mma / ldmatrix helpers
// =====================================================================
__device__ __forceinline__ void mma_bf16(float* d, const unsigned* A,
                                         unsigned b0, unsigned b1)
{
    asm volatile(
        "mma.sync.aligned.m16n8k16.row.col.f32.bf16.bf16.f32 "
        "{%0,%1,%2,%3},{%4,%5,%6,%7},{%8,%9},{%0,%1,%2,%3};"
        : "+f"(d[0]), "+f"(d[1]), "+f"(d[2]), "+f"(d[3])
        : "r"(A[0]), "r"(A[1]), "r"(A[2]), "r"(A[3]), "r"(b0), "r"(b1));
}

__device__ __forceinline__ void ldmatrix_x4(unsigned* r, const ushort_t* p)
{
    unsigned addr = (unsigned)__cvta_generic_to_shared((void*)p);
    asm volatile("ldmatrix.sync.aligned.m8n8.x4.shared.b16 {%0,%1,%2,%3}, [%4];"
        : "=r"(r[0]), "=r"(r[1]), "=r"(r[2]), "=r"(r[3]) : "r"(addr));
}

// =====================================================================
// Kernel: conv3x3 as bf16x3 tensor-core GEMM. v2
// Block: 128 co x 128 spatial (4 image rows). Grid (8 sp, 16 b, 3 p).
// 8 warps = 2(m:64co) x 4(n:32sp); A via ldmatrix, split-pass ordering.
// =====================================================================
__global__ __launch_bounds__(256) void conv_mma_kernel()
{
    // a_sm: [split(2)*3+kx][co(128)][k pad 24]
    __shared__ __align__(16) ushort_t a_sm[2*3*128*24];   // 36864 B
    // b_sm: [split(2)][ci(16)][r(4)][40]
    __shared__ __align__(16) ushort_t b_sm[2*16*4*40];    // 10240 B

    const int sp = blockIdx.x, b = blockIdx.y, p = blockIdx.z;
    const int tid = threadIdx.x, lane = tid & 31, wid = tid >> 5;
    const int wm = wid & 1, wn = wid >> 1;
    const int r0 = sp * 4;
    const int n0 = sp * 128;

    const __nv_bfloat16* whi = g_w_hi[p];
    const __nv_bfloat16* wlo = g_w_lo[p];
    const __nv_bfloat16* xhi = g_xpad_hi + (size_t)b * (128*34*40);
    const __nv_bfloat16* xlo = g_xpad_lo + (size_t)b * (128*34*40);

    float acc[4][4][4];
#pragma unroll
    for (int mi = 0; mi < 4; mi++)
#pragma unroll
        for (int ni = 0; ni < 4; ni++)
#pragma unroll
            for (int j = 0; j < 4; j++) acc[mi][ni][j] = 0.f;

    const int a_row = lane & 15;          // co offset within 16-row tile
    const int a_col = (lane >> 4) * 8;    // 0 or 8 (k element)
    const int bk = (lane & 3) * 2;        // k0
    const int bn = lane >> 2;             // n within 8

    for (int ky = 0; ky < 3; ky++) {
        for (int ci0 = 0; ci0 < 128; ci0 += 16) {
            __syncthreads();
            // ---- stage A: 1536 uint4 ----
            for (int u = tid; u < 1536; u += 256) {
                int half = u & 1;
                int co   = (u >> 1) & 127;
                int sk   = u >> 8;             // split*3+kx
                int split = sk / 3, kx = sk - split * 3;
                const __nv_bfloat16* src = (split ? wlo : whi)
                    + ((ky*3 + kx)*128 + co)*128 + ci0 + half*8;
                uint4 v = *reinterpret_cast<const uint4*>(src);
                *reinterpret_cast<uint4*>(
                    &a_sm[((sk*128) + co)*24 + half*8]) = v;
            }
            // ---- stage B: 640 uint4 ----
            for (int u = tid; u < 640; u += 256) {
                int seg = u % 5; int t = u / 5;
                int r  = t & 3;
                int ci = (t >> 2) & 15;
                int split = t >> 6;
                const __nv_bfloat16* src = (split ? xlo : xhi)
                    + ((size_t)(ci0 + ci)*34 + (r0 + r + ky))*40 + seg*8;
                uint4 v = *reinterpret_cast<const uint4*>(src);
                *reinterpret_cast<uint4*>(
                    &b_sm[(((split*16 + ci)*4 + r)*40) + seg*8]) = v;
            }
            __syncthreads();

#pragma unroll
            for (int kx = 0; kx < 3; kx++) {
                // ---- pass 1: A = hi split; do Ahi*Bhi + Ahi*Blo ----
                unsigned Af[4][4];
#pragma unroll
                for (int mi = 0; mi < 4; mi++)
                    ldmatrix_x4(Af[mi],
                        &a_sm[((kx*128) + wm*64 + mi*16 + a_row)*24 + a_col]);
#pragma unroll
                for (int ni = 0; ni < 4; ni++) {
                    int n  = wn*32 + ni*8 + bn;
                    int rr = n >> 5;
                    int cc = (n & 31) + kx;
                    int o0 = (bk*4 + rr)*40 + cc;        // hi split
                    int o1 = o0 + 16*4*40;               // lo split
                    unsigned h0 = b_sm[o0];
                    unsigned h1 = b_sm[o0 + 160];
                    unsigned h8 = b_sm[o0 + 1280];
                    unsigned h9 = b_sm[o0 + 1440];
                    unsigned Bh0 = h0 | (h1 << 16);
                    unsigned Bh1 = h8 | (h9 << 16);
                    unsigned l0 = b_sm[o1];
                    unsigned l1 = b_sm[o1 + 160];
                    unsigned l8 = b_sm[o1 + 1280];
                    unsigned l9 = b_sm[o1 + 1440];
                    unsigned Bl0 = l0 | (l1 << 16);
                    unsigned Bl1 = l8 | (l9 << 16);
#pragma unroll
                    for (int mi = 0; mi < 4; mi++) {
                        mma_bf16(acc[mi][ni], Af[mi], Bh0, Bh1);
                        mma_bf16(acc[mi][ni], Af[mi], Bl0, Bl1);
                    }
                }
                // ---- pass 2: A = lo split; do Alo*Bhi ----
#pragma unroll
                for (int mi = 0; mi < 4; mi++)
                    ldmatrix_x4(Af[mi],
                        &a_sm[(((3 + kx)*128) + wm*64 + mi*16 + a_row)*24 + a_col]);
#pragma unroll
                for (int ni = 0; ni < 4; ni++) {
                    int n  = wn*32 + ni*8 + bn;
                    int rr = n >> 5;
                    int cc = (n & 31) + kx;
                    int o0 = (bk*4 + rr)*40 + cc;
                    unsigned h0 = b_sm[o0];
                    unsigned h1 = b_sm[o0 + 160];
                    unsigned h8 = b_sm[o0 + 1280];
                    unsigned h9 = b_sm[o0 + 1440];
                    unsigned Bh0 = h0 | (h1 << 16);
                    unsigned Bh1 = h8 | (h9 << 16);
#pragma unroll
                    for (int mi = 0; mi < 4; mi++)
                        mma_bf16(acc[mi][ni], Af[mi], Bh0, Bh1);
                }
            }
        }
    }

    // epilogue
    float* outb = &g_conv[p][(size_t)b * CN];
#pragma unroll
    for (int mi = 0; mi < 4; mi++) {
        int row = wm*64 + mi*16 + (lane >> 2);
#pragma unroll
        for (int ni = 0; ni < 4; ni++) {
            int col = n0 + wn*32 + ni*8 + (lane & 3)*2;
            float2 v0; v0.x = acc[mi][ni][0]; v0.y = acc[mi][ni][1];
            float2 v1; v1.x = acc[mi][ni][2]; v1.y = acc[mi][ni][3];
            *reinterpret_cast<float2*>(&outb[(size_t)row*1024 + col])     = v0;
            *reinterpret_cast<float2*>(&outb[(size_t)(row+8)*1024 + col]) = v1;
        }
    }
}

// =====================================================================
// Deterministic two-stage mean/var per (proj, batch), fp32
// =====================================================================
__global__ __launch_bounds__(256) void gn_reduce1_kernel()
{
    const int blk = blockIdx.x;           // 1536 = 48 pb * 32 segs
    const int pb = blk >> 5, seg = blk & 31;
    const float* src = &g_conv[0][0] + (size_t)pb*CN + seg*4096;
    const int tid = threadIdx.x;
    float s = 0.f, s2 = 0.f;
    for (int i = tid; i < 4096; i += 256) {
        float v = src[i];
        s += v; s2 = fmaf(v, v, s2);
    }
    __shared__ float a[256], a2[256];
    a[tid] = s; a2[tid] = s2;
    __syncthreads();
    for (int st = 128; st > 0; st >>= 1) {
        if (tid < st) { a[tid] += a[tid + st]; a2[tid] += a2[tid + st]; }
        __syncthreads();
    }
    if (tid == 0) { g_partf[blk][0] = a[0]; g_partf[blk][1] = a2[0]; }
}

__global__ void gn_reduce2_kernel()
{
    const int pb = blockIdx.x;            // 48
    const int l = threadIdx.x;            // 32
    float s  = g_partf[pb*32 + l][0];
    float s2 = g_partf[pb*32 + l][1];
    for (int off = 16; off > 0; off >>= 1) {
        s  += __shfl_down_sync(0xffffffffu, s, off);
        s2 += __shfl_down_sync(0xffffffffu, s2, off);
    }
    if (l == 0) {
        float mean = s / (float)CN;
        float var  = s2 / (float)CN - mean * mean;
        g_mean[pb] = mean;
        g_rstd[pb] = rsqrtf(var + 1e-6f);
    }
}

// =====================================================================
// GroupNorm apply + exact GELU + transpose to head-major layout
// =====================================================================
__global__ __launch_bounds__(256) void norm_gelu_kernel(
    const float* __restrict__ gq, const float* __restrict__ bq,
    const float* __restrict__ gk, const float* __restrict__ bk,
    const float* __restrict__ gv, const float* __restrict__ bv)
{
    const int pb = blockIdx.z;
    const int p = pb >> 4, b = pb & 15;
    const int h = blockIdx.y;
    const int n0 = blockIdx.x * 64;
    const int tid = threadIdx.x;

    const float* gamma = (p == 0) ? gq : (p == 1) ? gk : gv;
    const float* beta  = (p == 0) ? bq : (p == 1) ? bk : bv;
    const float mean = g_mean[pb];
    const float rstd = g_rstd[pb];

    __shared__ float s[32][65];

    const float* src = g_conv[p] + ((size_t)b * 128 + h * 32) * N_;
    for (int e = tid; e < 2048; e += 256) {
        int d = e >> 6, nn = e & 63;
        float v = src[(size_t)d * N_ + n0 + nn];
        int c = h * 32 + d;
        v = (v - mean) * rstd * gamma[c] + beta[c];
        v = 0.5f * v * (1.0f + erff(v * 0.70710678118654752f));
        s[d][nn] = v;
    }
    __syncthreads();
    float* dst = g_qkv[p] + ((size_t)(b * 4 + h) * N_ + n0) * D_;
    for (int e = tid; e < 2048; e += 256) {
        int nn = e >> 5, d = e & 31;
        dst[nn * D_ + d] = s[d][nn];
    }
}

// =====================================================================
// Materialize bias[h][n][m] from table gather
// =====================================================================
__global__ __launch_bounds__(256) void bias_kernel(
    const float* __restrict__ table, const int* __restrict__ rel_index)
{
    const int n = blockIdx.x;
    for (int m = threadIdx.x; m < N_; m += 256) {
        int idx = rel_index[n * N_ + m];
        float4 t = *reinterpret_cast<const float4*>(table + idx * 4);
        g_bias4[(0 * N_ + n) * N_ + m] = t.x;
        g_bias4[(1 * N_ + n) * N_ + m] = t.y;
        g_bias4[(2 * N_ + n) * N_ + m] = t.z;
        g_bias4[(3 * N_ + n) * N_ + m] = t.w;
    }
}

// =====================================================================
// Attention (flash-style, online softmax)
// =====================================================================
__global__ __launch_bounds__(256) void attn_kernel()
{
    __shared__ float Qs[64 * 32];
    __shared__ float Ks[64 * 33];
    __shared__ float Vs[64 * 33];
    __shared__ float Ps[64 * 64];

    const int tid  = threadIdx.x;
    const int lane = tid & 31;
    const int wrp  = tid >> 5;
    const int qt   = blockIdx.x;
    const int bh   = blockIdx.y;
    const int b    = bh >> 2;
    const int h    = bh & 3;

    const float* qbase = g_qkv[0] + (size_t)bh * N_ * D_;
    const float* kbase = g_qkv[1] + (size_t)bh * N_ * D_;
    const float* vbase = g_qkv[2] + (size_t)bh * N_ * D_;

    for (int e = tid; e < 2048; e += 256)
        Qs[e] = qbase[qt * 64 * D_ + e];

    float m_run[8], l_run[8], acc[8];
#pragma unroll
    for (int rr = 0; rr < 8; rr++) {
        m_run[rr] = -INFINITY; l_run[rr] = 0.f; acc[rr] = 0.f;
    }

    for (int kc = 0; kc < 16; kc++) {
        const int m0 = kc * 64;
        __syncthreads();
        for (int e = tid; e < 2048; e += 256) {
            int mm = e >> 5, d = e & 31;
            Ks[mm * 33 + d] = kbase[(m0 + mm) * D_ + d];
            Vs[mm * 33 + d] = vbase[(m0 + mm) * D_ + d];
        }
        __syncthreads();

#pragma unroll
        for (int pass = 0; pass < 2; pass++) {
            const int mloc = pass * 32 + lane;
            float kreg[32];
#pragma unroll
            for (int kk = 0; kk < 32; kk++) kreg[kk] = Ks[mloc * 33 + kk];
#pragma unroll
            for (int rr = 0; rr < 8; rr++) {
                const int r = wrp * 8 + rr;
                const float4* qp = reinterpret_cast<const float4*>(Qs + r * 32);
                float s = 0.f;
#pragma unroll
                for (int q4 = 0; q4 < 8; q4++) {
                    float4 qv = qp[q4];
                    s += qv.x * kreg[q4 * 4 + 0];
                    s += qv.y * kreg[q4 * 4 + 1];
                    s += qv.z * kreg[q4 * 4 + 2];
                    s += qv.w * kreg[q4 * 4 + 3];
                }
                s += g_bias4[((size_t)h * N_ + qt * 64 + r) * N_ + m0 + mloc];
                Ps[r * 64 + mloc] = s;
            }
        }
        __syncwarp();

#pragma unroll
        for (int rr = 0; rr < 8; rr++) {
            const int r = wrp * 8 + rr;
            float s0 = Ps[r * 64 + lane];
            float s1 = Ps[r * 64 + lane + 32];
            float cm = fmaxf(s0, s1);
#pragma unroll
            for (int off = 16; off > 0; off >>= 1)
                cm = fmaxf(cm, __shfl_xor_sync(0xffffffffu, cm, off));
            float mnew = fmaxf(m_run[rr], cm);
            float corr = __expf(m_run[rr] - mnew);
            float p0 = __expf(s0 - mnew);
            float p1 = __expf(s1 - mnew);
            Ps[r * 64 + lane]      = p0;
            Ps[r * 64 + lane + 32] = p1;
            float ls = p0 + p1;
#pragma unroll
            for (int off = 16; off > 0; off >>= 1)
                ls += __shfl_xor_sync(0xffffffffu, ls, off);
            l_run[rr] = l_run[rr] * corr + ls;
            m_run[rr] = mnew;
            acc[rr]  *= corr;
        }
        __syncwarp();

#pragma unroll
        for (int sub = 0; sub < 2; sub++) {
            float vreg[32];
#pragma unroll
            for (int i = 0; i < 32; i++)
                vreg[i] = Vs[(sub * 32 + i) * 33 + lane];
#pragma unroll
            for (int rr = 0; rr < 8; rr++) {
                const int r = wrp * 8 + rr;
                const float4* pp = reinterpret_cast<const float4*>(Ps + r * 64 + sub * 32);
                float a = acc[rr];
#pragma unroll
                for (int i4 = 0; i4 < 8; i4++) {
                    float4 pv = pp[i4];
                    a += pv.x * vreg[i4 * 4 + 0];
                    a += pv.y * vreg[i4 * 4 + 1];
                    a += pv.z * vreg[i4 * 4 + 2];
                    a += pv.w * vreg[i4 * 4 + 3];
                }
                acc[rr] = a;
            }
        }
    }

#pragma unroll
    for (int rr = 0; rr < 8; rr++) {
        const int n = qt * 64 + wrp * 8 + rr;
        g_attn[((size_t)b * N_ + n) * C_ + h * 32 + lane] = acc[rr] / l_run[rr];
    }
}

// =====================================================================
// 1x1 conv (GEMM) + bias
// =====================================================================
__global__ __launch_bounds__(256) void outconv_kernel(
    const float* __restrict__ w, const float* __restrict__ bias,
    float* __restrict__ out)
{
    __shared__ float a_t[128][33];
    __shared__ float w_t[128][32];

    const int b  = blockIdx.y;
    const int n0 = blockIdx.x * 128;
    const int tid = threadIdx.x;
    const int nl  = tid & 63;
    const int cog = tid >> 6;

    float acc0[32], acc1[32];
#pragma unroll
    for (int j = 0; j < 32; j++) { acc0[j] = 0.f; acc1[j] = 0.f; }

    for (int c0 = 0; c0 < 128; c0 += 32) {
        __syncthreads();
        for (int e = tid; e < 4096; e += 256) {
            int nn = e >> 5, cc = e & 31;
            a_t[nn][cc] = g_attn[((size_t)b * N_ + n0 + nn) * C_ + c0 + cc];
        }
        for (int e = tid; e < 4096; e += 256) {
            int co = e >> 5, cc = e & 31;
            w_t[co][cc] = w[co * 128 + c0 + cc];
        }
        __syncthreads();
#pragma unroll
        for (int cc = 0; cc < 32; cc++) {
            float a0 = a_t[nl][cc];
            float a1 = a_t[nl + 64][cc];
#pragma unroll
            for (int j = 0; j < 32; j++) {
                float wv = w_t[cog * 32 + j][cc];
                acc0[j] += a0 * wv;
                acc1[j] += a1 * wv;
            }
        }
    }
#pragma unroll
    for (int j = 0; j < 32; j++) {
        int co = cog * 32 + j;
        float bv = bias[co];
        out[((size_t)b * 128 + co) * N_ + n0 + nl]      = acc0[j] + bv;
        out[((size_t)b * 128 + co) * N_ + n0 + nl + 64] = acc1[j] + bv;
    }
}

// =====================================================================
extern "C" void kernel_launch(void* const* d_in, const int* in_sizes, int n_in,
                              void* d_out, int out_size)
{
    const float* x      = (const float*)d_in[0];
    const float* wq     = (const float*)d_in[1];
    const float* gq     = (const float*)d_in[2];
    const float* bq     = (const float*)d_in[3];
    const float* wk     = (const float*)d_in[4];
    const float* gk     = (const float*)d_in[5];
    const float* bk     = (const float*)d_in[6];
    const float* wv     = (const float*)d_in[7];
    const float* gv     = (const float*)d_in[8];
    const float* bv     = (const float*)d_in[9];
    const float* table  = (const float*)d_in[10];
    const int*   relidx = (const int*)  d_in[11];
    const float* out_w  = (const float*)d_in[12];
    const float* out_b  = (const float*)d_in[13];
    float* out = (float*)d_out;

    // NOTE: launch index 3 (0-based) is the one ncu profiles — put conv there.
    prep_x_kernel<<<2048, 256>>>(x);                      // 0
    prep_w_kernel<<<1728, 256>>>(wq, wk, wv);             // 1
    bias_kernel<<<1024, 256>>>(table, relidx);            // 2 (independent)
    conv_mma_kernel<<<dim3(8, 16, 3), 256>>>();           // 3  <- profiled
    gn_reduce1_kernel<<<1536, 256>>>();                   // 4
    gn_reduce2_kernel<<<48, 32>>>();                      // 5
    norm_gelu_kernel<<<dim3(16, 4, 48), 256>>>(gq, bq, gk, bk, gv, bv); // 6
    attn_kernel<<<dim3(16, 64), 256>>>();                 // 7
    outconv_kernel<<<dim3(8, 16), 256>>>(out_w, out_b, out); // 8
}

// round 5
// speedup vs baseline: 3.4042x; 3.1715x over previous
#include <cuda_runtime.h>
#include <cuda_bf16.h>
#include <math.h>

#define B_   16
#define C_   128
#define N_   1024
#define H_   4
#define D_   32
#define CN   (C_*N_)

typedef unsigned short ushort_t;

// ---------------- scratch (device globals; no allocations) ----------------
__device__ float g_conv[3][B_*CN];        // conv outputs, [p][b][c][n]
__device__ float g_mean[48];
__device__ float g_rstd[48];
__device__ float g_partf[1536][2];
__device__ float g_bias4[H_*N_*N_];       // [h][n][m]
__device__ float g_attn[B_*N_*C_];        // [b][n][c]

// padded input, transposed: [b][sp_pad(34*40)][ci(128)], hi/lo bf16 bits
__device__ __align__(16) ushort_t g_xpad_hi[B_*34*40*C_];
__device__ __align__(16) ushort_t g_xpad_lo[B_*34*40*C_];
// weights: [p][((ky*3+kx)*128+co)*128+ci]
__device__ __align__(16) __nv_bfloat16 g_w_hi[3][9*128*128];
__device__ __align__(16) __nv_bfloat16 g_w_lo[3][9*128*128];

// attention operands (bf16 bits, hi/lo split)
__device__ __align__(16) ushort_t g_q_hi[64*N_*D_];   // [bh][n][d]
__device__ __align__(16) ushort_t g_q_lo[64*N_*D_];
__device__ __align__(16) ushort_t g_k_hi[64*N_*D_];   // [bh][n][d]
__device__ __align__(16) ushort_t g_k_lo[64*N_*D_];
__device__ __align__(16) ushort_t g_v_hi[64*D_*N_];   // [bh][d][n]  (transposed)
__device__ __align__(16) ushort_t g_v_lo[64*D_*N_];

// =====================================================================
// helpers
// =====================================================================
__device__ __forceinline__ void mma_bf16(float* d, const unsigned* A,
                                         unsigned b0, unsigned b1)
{
    asm volatile(
        "mma.sync.aligned.m16n8k16.row.col.f32.bf16.bf16.f32 "
        "{%0,%1,%2,%3},{%4,%5,%6,%7},{%8,%9},{%0,%1,%2,%3};"
        : "+f"(d[0]), "+f"(d[1]), "+f"(d[2]), "+f"(d[3])
        : "r"(A[0]), "r"(A[1]), "r"(A[2]), "r"(A[3]), "r"(b0), "r"(b1));
}

__device__ __forceinline__ void ldmatrix_x4(unsigned* r, const ushort_t* p)
{
    unsigned addr = (unsigned)__cvta_generic_to_shared((void*)p);
    asm volatile("ldmatrix.sync.aligned.m8n8.x4.shared.b16 {%0,%1,%2,%3}, [%4];"
        : "=r"(r[0]), "=r"(r[1]), "=r"(r[2]), "=r"(r[3]) : "r"(addr));
}

// pack two floats -> bf16x2 (upper = hi_elem, lower = lo_elem)
__device__ __forceinline__ unsigned packbf(float hi_elem, float lo_elem)
{
    unsigned d;
    asm("cvt.rn.bf16x2.f32 %0, %1, %2;" : "=r"(d) : "f"(hi_elem), "f"(lo_elem));
    return d;
}
__device__ __forceinline__ float upperf(unsigned u){ return __uint_as_float(u & 0xffff0000u); }
__device__ __forceinline__ float lowerf(unsigned u){ return __uint_as_float(u << 16); }

// =====================================================================
// Prep: split x into padded transposed bf16 hi/lo  [b][sp(34*40)][ci]
// =====================================================================
__global__ __launch_bounds__(256) void prep_x_kernel(const float* __restrict__ x)
{
    const int total = B_*1360*128;
    for (int e = blockIdx.x*256 + threadIdx.x; e < total; e += gridDim.x*256) {
        int ci = e & 127;
        int t  = e >> 7;
        int sp = t % 1360;
        int b  = t / 1360;
        int yy = sp / 40, xx = sp % 40;
        int y = yy - 1, c = xx - 1;
        float v = 0.f;
        if ((unsigned)y < 32u && (unsigned)c < 32u)
            v = x[((size_t)b*128 + ci)*1024 + y*32 + c];
        __nv_bfloat16 hb = __float2bfloat16(v);
        float lov = v - __bfloat162float(hb);
        __nv_bfloat16 lb = __float2bfloat16(lov);
        g_xpad_hi[e] = *(ushort_t*)&hb;
        g_xpad_lo[e] = *(ushort_t*)&lb;
    }
}

// =====================================================================
// Prep: split + transpose weights
// =====================================================================
__global__ __launch_bounds__(256) void prep_w_kernel(
    const float* __restrict__ wq, const float* __restrict__ wk,
    const float* __restrict__ wv)
{
    int e = blockIdx.x*256 + threadIdx.x;
    if (e >= 3*128*128*9) return;
    int kx = e % 3; int t = e / 3;
    int ky = t % 3; t /= 3;
    int ci = t % 128; t /= 128;
    int co = t % 128;
    int p  = t / 128;
    const float* w = (p == 0) ? wq : (p == 1) ? wk : wv;
    float v = w[((co*128 + ci)*3 + ky)*3 + kx];
    __nv_bfloat16 h = __float2bfloat16(v);
    float lo = v - __bfloat162float(h);
    int dst = ((ky*3 + kx)*128 + co)*128 + ci;
    g_w_hi[p][dst] = h;
    g_w_lo[p][dst] = __float2bfloat16(lo);
}

// =====================================================================
// conv3x3 as bf16x3 tensor-core GEMM, v3: full ldmatrix feeding.
// =====================================================================
__global__ __launch_bounds__(256) void conv_mma_kernel()
{
    __shared__ __align__(16) ushort_t a_sm[128*104];      // 26624 B
    __shared__ __align__(16) ushort_t b_sm[2*136*24];     // 13056 B

    const int sp = blockIdx.x, b = blockIdx.y, p = blockIdx.z;
    const int tid = threadIdx.x, lane = tid & 31, wid = tid >> 5;
    const int wm = wid & 1, wn = wid >> 1;
    const int r0 = sp * 4;
    const int n0 = sp * 128;

    const __nv_bfloat16* whi = g_w_hi[p];
    const __nv_bfloat16* wlo = g_w_lo[p];
    const ushort_t* xh = g_xpad_hi + (size_t)b * (1360*128);
    const ushort_t* xl = g_xpad_lo + (size_t)b * (1360*128);

    float acc[4][4][4];
#pragma unroll
    for (int mi = 0; mi < 4; mi++)
#pragma unroll
        for (int ni = 0; ni < 4; ni++)
#pragma unroll
            for (int j = 0; j < 4; j++) acc[mi][ni][j] = 0.f;

    const int m_idx = lane >> 3;
    const int row_in = lane & 7;
    int aoff[4];
#pragma unroll
    for (int mi = 0; mi < 4; mi++)
        aoff[mi] = (wm*64 + mi*16 + (lane & 15))*104 + (lane >> 4)*8;
    int boff[2];
#pragma unroll
    for (int tp = 0; tp < 2; tp++) {
        int tile = tp*2 + (m_idx >> 1);
        int n = wn*32 + tile*8 + row_in;
        int rr = n >> 5, cc = n & 31;
        boff[tp] = (rr*34 + cc)*24 + (m_idx & 1)*8;
    }

    for (int ky = 0; ky < 3; ky++) {
        for (int ci0 = 0; ci0 < 128; ci0 += 16) {
            __syncthreads();
            // stage A: 1536 uint4
            for (int u = tid; u < 1536; u += 256) {
                int half = u & 1;
                int co   = (u >> 1) & 127;
                int sk   = u >> 8;
                int split = (sk >= 3), kx = split ? sk - 3 : sk;
                const __nv_bfloat16* src = (split ? wlo : whi)
                    + ((ky*3 + kx)*128 + co)*128 + ci0 + half*8;
                uint4 v = *reinterpret_cast<const uint4*>(src);
                *reinterpret_cast<uint4*>(&a_sm[co*104 + sk*16 + half*8]) = v;
            }
            // stage B: 544 uint4
            for (int u = tid; u < 544; u += 256) {
                int half = u & 1;
                int idx  = u >> 1;
                int pc = idx % 34;
                int t  = idx / 34;
                int r  = t & 3;
                int split = t >> 2;
                const ushort_t* src = (split ? xl : xh)
                    + ((size_t)(r0 + r + ky)*40 + pc)*128 + ci0 + half*8;
                uint4 v = *reinterpret_cast<const uint4*>(src);
                *reinterpret_cast<uint4*>(
                    &b_sm[(split*136 + r*34 + pc)*24 + half*8]) = v;
            }
            __syncthreads();

#pragma unroll
            for (int kx = 0; kx < 3; kx++) {
                unsigned bf[4][2], Af[4][4];
                {
                    unsigned t4[4];
                    ldmatrix_x4(t4, &b_sm[boff[0] + kx*24]);
                    bf[0][0]=t4[0]; bf[0][1]=t4[1]; bf[1][0]=t4[2]; bf[1][1]=t4[3];
                    ldmatrix_x4(t4, &b_sm[boff[1] + kx*24]);
                    bf[2][0]=t4[0]; bf[2][1]=t4[1]; bf[3][0]=t4[2]; bf[3][1]=t4[3];
                }
#pragma unroll
                for (int mi = 0; mi < 4; mi++)
                    ldmatrix_x4(Af[mi], &a_sm[aoff[mi] + kx*16]);
#pragma unroll
                for (int ni = 0; ni < 4; ni++)
#pragma unroll
                    for (int mi = 0; mi < 4; mi++)
                        mma_bf16(acc[mi][ni], Af[mi], bf[ni][0], bf[ni][1]);
                unsigned bl[4][2];
                {
                    unsigned t4[4];
                    ldmatrix_x4(t4, &b_sm[136*24 + boff[0] + kx*24]);
                    bl[0][0]=t4[0]; bl[0][1]=t4[1]; bl[1][0]=t4[2]; bl[1][1]=t4[3];
                    ldmatrix_x4(t4, &b_sm[136*24 + boff[1] + kx*24]);
                    bl[2][0]=t4[0]; bl[2][1]=t4[1]; bl[3][0]=t4[2]; bl[3][1]=t4[3];
                }
#pragma unroll
                for (int ni = 0; ni < 4; ni++)
#pragma unroll
                    for (int mi = 0; mi < 4; mi++)
                        mma_bf16(acc[mi][ni], Af[mi], bl[ni][0], bl[ni][1]);
#pragma unroll
                for (int mi = 0; mi < 4; mi++)
                    ldmatrix_x4(Af[mi], &a_sm[aoff[mi] + (3 + kx)*16]);
#pragma unroll
                for (int ni = 0; ni < 4; ni++)
#pragma unroll
                    for (int mi = 0; mi < 4; mi++)
                        mma_bf16(acc[mi][ni], Af[mi], bf[ni][0], bf[ni][1]);
            }
        }
    }

    float* outb = &g_conv[p][(size_t)b * CN];
#pragma unroll
    for (int mi = 0; mi < 4; mi++) {
        int row = wm*64 + mi*16 + (lane >> 2);
#pragma unroll
        for (int ni = 0; ni < 4; ni++) {
            int col = n0 + wn*32 + ni*8 + (lane & 3)*2;
            float2 v0; v0.x = acc[mi][ni][0]; v0.y = acc[mi][ni][1];
            float2 v1; v1.x = acc[mi][ni][2]; v1.y = acc[mi][ni][3];
            *reinterpret_cast<float2*>(&outb[(size_t)row*1024 + col])     = v0;
            *reinterpret_cast<float2*>(&outb[(size_t)(row+8)*1024 + col]) = v1;
        }
    }
}

// =====================================================================
// Deterministic two-stage mean/var per (proj, batch), fp32
// =====================================================================
__global__ __launch_bounds__(256) void gn_reduce1_kernel()
{
    const int blk = blockIdx.x;
    const int pb = blk >> 5, seg = blk & 31;
    const float* src = &g_conv[0][0] + (size_t)pb*CN + seg*4096;
    const int tid = threadIdx.x;
    float s = 0.f, s2 = 0.f;
    for (int i = tid; i < 4096; i += 256) {
        float v = src[i];
        s += v; s2 = fmaf(v, v, s2);
    }
    __shared__ float a[256], a2[256];
    a[tid] = s; a2[tid] = s2;
    __syncthreads();
    for (int st = 128; st > 0; st >>= 1) {
        if (tid < st) { a[tid] += a[tid + st]; a2[tid] += a2[tid + st]; }
        __syncthreads();
    }
    if (tid == 0) { g_partf[blk][0] = a[0]; g_partf[blk][1] = a2[0]; }
}

__global__ void gn_reduce2_kernel()
{
    const int pb = blockIdx.x;
    const int l = threadIdx.x;
    float s  = g_partf[pb*32 + l][0];
    float s2 = g_partf[pb*32 + l][1];
    for (int off = 16; off > 0; off >>= 1) {
        s  += __shfl_down_sync(0xffffffffu, s, off);
        s2 += __shfl_down_sync(0xffffffffu, s2, off);
    }
    if (l == 0) {
        float mean = s / (float)CN;
        float var  = s2 / (float)CN - mean * mean;
        g_mean[pb] = mean;
        g_rstd[pb] = rsqrtf(var + 1e-6f);
    }
}

// =====================================================================
// GroupNorm apply + exact GELU -> bf16 hi/lo attention operands
// =====================================================================
__global__ __launch_bounds__(256) void norm_gelu_kernel(
    const float* __restrict__ gq, const float* __restrict__ bq,
    const float* __restrict__ gk, const float* __restrict__ bk,
    const float* __restrict__ gv, const float* __restrict__ bv)
{
    const int pb = blockIdx.z;
    const int p = pb >> 4, b = pb & 15;
    const int h = blockIdx.y;
    const int n0 = blockIdx.x * 64;
    const int tid = threadIdx.x;
    const int bhid = b*4 + h;

    const float* gamma = (p == 0) ? gq : (p == 1) ? gk : gv;
    const float* beta  = (p == 0) ? bq : (p == 1) ? bk : bv;
    const float mean = g_mean[pb];
    const float rstd = g_rstd[pb];

    __shared__ float s[32][65];
    const float* src = g_conv[p] + ((size_t)b * 128 + h * 32) * N_;

    if (p == 2) {
        for (int e = tid; e < 2048; e += 256) {
            int d = e >> 6, nn = e & 63;
            float v = src[(size_t)d * N_ + n0 + nn];
            int c = h * 32 + d;
            v = (v - mean) * rstd * gamma[c] + beta[c];
            v = 0.5f * v * (1.0f + erff(v * 0.70710678118654752f));
            __nv_bfloat16 hb = __float2bfloat16(v);
            float lov = v - __bfloat162float(hb);
            __nv_bfloat16 lb = __float2bfloat16(lov);
            size_t idx = ((size_t)bhid*32 + d)*1024 + n0 + nn;
            g_v_hi[idx] = *(ushort_t*)&hb;
            g_v_lo[idx] = *(ushort_t*)&lb;
        }
    } else {
        for (int e = tid; e < 2048; e += 256) {
            int d = e >> 6, nn = e & 63;
            float v = src[(size_t)d * N_ + n0 + nn];
            int c = h * 32 + d;
            v = (v - mean) * rstd * gamma[c] + beta[c];
            v = 0.5f * v * (1.0f + erff(v * 0.70710678118654752f));
            s[d][nn] = v;
        }
        __syncthreads();
        ushort_t* dhi = (p == 0) ? g_q_hi : g_k_hi;
        ushort_t* dlo = (p == 0) ? g_q_lo : g_k_lo;
        for (int e = tid; e < 2048; e += 256) {
            int nn = e >> 5, d = e & 31;
            float v = s[d][nn];
            __nv_bfloat16 hb = __float2bfloat16(v);
            float lov = v - __bfloat162float(hb);
            __nv_bfloat16 lb = __float2bfloat16(lov);
            size_t idx = ((size_t)bhid*1024 + n0 + nn)*32 + d;
            dhi[idx] = *(ushort_t*)&hb;
            dlo[idx] = *(ushort_t*)&lb;
        }
    }
}

// =====================================================================
// Materialize bias[h][n][m]
// =====================================================================
__global__ __launch_bounds__(256) void bias_kernel(
    const float* __restrict__ table, const int* __restrict__ rel_index)
{
    const int n = blockIdx.x;
    for (int m = threadIdx.x; m < N_; m += 256) {
        int idx = rel_index[n * N_ + m];
        float4 t = *reinterpret_cast<const float4*>(table + idx * 4);
        g_bias4[(0 * N_ + n) * N_ + m] = t.x;
        g_bias4[(1 * N_ + n) * N_ + m] = t.y;
        g_bias4[(2 * N_ + n) * N_ + m] = t.z;
        g_bias4[(3 * N_ + n) * N_ + m] = t.w;
    }
}

// =====================================================================
// Attention via tensor cores (flash-style, fragment softmax)
// grid (8 qt, 64 bh), block 256 = 8 warps, warp owns 16 q-rows.
// =====================================================================
__global__ __launch_bounds__(256) void attn_mma_kernel()
{
    __shared__ __align__(16) ushort_t q_sm[2][128][40];   // 20480 B
    __shared__ __align__(16) ushort_t k_sm[2][64][40];    // 10240 B
    __shared__ __align__(16) ushort_t v_sm[2][32][72];    //  9216 B

    const int tid = threadIdx.x, lane = tid & 31, w = tid >> 5;
    const int qt = blockIdx.x, bh = blockIdx.y;
    const int b = bh >> 2, h = bh & 3;

    // load Q tile (128 rows x 32 d, hi+lo): 1024 uint4
    for (int u = tid; u < 1024; u += 256) {
        int quarter = u & 3, row = (u >> 2) & 127, split = u >> 9;
        const ushort_t* src = (split ? g_q_lo : g_q_hi)
            + ((size_t)bh*1024 + qt*128 + row)*32 + quarter*8;
        *reinterpret_cast<uint4*>(&q_sm[split][row][quarter*8]) =
            *reinterpret_cast<const uint4*>(src);
    }
    __syncthreads();

    unsigned qh[2][4], ql[2][4];
#pragma unroll
    for (int kit = 0; kit < 2; kit++) {
        ldmatrix_x4(qh[kit], &q_sm[0][w*16 + (lane & 15)][kit*16 + (lane >> 4)*8]);
        ldmatrix_x4(ql[kit], &q_sm[1][w*16 + (lane & 15)][kit*16 + (lane >> 4)*8]);
    }

    const int m_idx = lane >> 3;
    const int row_in = lane & 7;
    int koff[4], voff[2];
#pragma unroll
    for (int tp = 0; tp < 4; tp++)
        koff[tp] = ((tp*2 + (m_idx >> 1))*8 + row_in)*40 + (m_idx & 1)*8;
#pragma unroll
    for (int tp = 0; tp < 2; tp++)
        voff[tp] = ((tp*2 + (m_idx >> 1))*8 + row_in)*72 + (m_idx & 1)*8;

    float O[4][4];
#pragma unroll
    for (int nd = 0; nd < 4; nd++)
#pragma unroll
        for (int j = 0; j < 4; j++) O[nd][j] = 0.f;
    float mrun0 = -INFINITY, mrun1 = -INFINITY, lrun0 = 0.f, lrun1 = 0.f;

    const int qrow0 = qt*128 + w*16 + (lane >> 2);
    const float* biasbase = g_bias4 + ((size_t)h*1024 + qrow0)*1024 + 2*(lane & 3);

    for (int kc = 0; kc < 16; kc++) {
        const int m0 = kc * 64;
        __syncthreads();
        // K chunk: 512 uint4 (2/thread)
        for (int u = tid; u < 512; u += 256) {
            int quarter = u & 3, row = (u >> 2) & 63, split = u >> 8;
            const ushort_t* src = (split ? g_k_lo : g_k_hi)
                + ((size_t)bh*1024 + m0 + row)*32 + quarter*8;
            *reinterpret_cast<uint4*>(&k_sm[split][row][quarter*8]) =
                *reinterpret_cast<const uint4*>(src);
        }
        // V chunk: 512 uint4 (2/thread)
        for (int u = tid; u < 512; u += 256) {
            int seg = u & 7, d = (u >> 3) & 31, split = u >> 8;
            const ushort_t* src = (split ? g_v_lo : g_v_hi)
                + ((size_t)bh*32 + d)*1024 + m0 + seg*8;
            *reinterpret_cast<uint4*>(&v_sm[split][d][seg*8]) =
                *reinterpret_cast<const uint4*>(src);
        }
        __syncthreads();

        // ---- S = Q K^T (3-term hi/lo) ----
        float c[8][4];
#pragma unroll
        for (int ni = 0; ni < 8; ni++)
#pragma unroll
            for (int j = 0; j < 4; j++) c[ni][j] = 0.f;

#pragma unroll
        for (int kit = 0; kit < 2; kit++) {
            unsigned kb[8][2];
#pragma unroll
            for (int tp = 0; tp < 4; tp++) {
                unsigned t4[4];
                ldmatrix_x4(t4, &k_sm[0][0][0] + koff[tp] + kit*16);
                kb[tp*2][0]=t4[0]; kb[tp*2][1]=t4[1];
                kb[tp*2+1][0]=t4[2]; kb[tp*2+1][1]=t4[3];
            }
#pragma unroll
            for (int ni = 0; ni < 8; ni++) {
                mma_bf16(c[ni], qh[kit], kb[ni][0], kb[ni][1]);
                mma_bf16(c[ni], ql[kit], kb[ni][0], kb[ni][1]);
            }
#pragma unroll
            for (int tp = 0; tp < 4; tp++) {
                unsigned t4[4];
                ldmatrix_x4(t4, &k_sm[1][0][0] + koff[tp] + kit*16);
                kb[tp*2][0]=t4[0]; kb[tp*2][1]=t4[1];
                kb[tp*2+1][0]=t4[2]; kb[tp*2+1][1]=t4[3];
            }
#pragma unroll
            for (int ni = 0; ni < 8; ni++)
                mma_bf16(c[ni], qh[kit], kb[ni][0], kb[ni][1]);
        }

        // ---- bias + online softmax (fragment layout) ----
        const float* b0p = biasbase + m0;
        const float* b1p = b0p + 8*1024;
        float rm0 = -INFINITY, rm1 = -INFINITY;
#pragma unroll
        for (int ni = 0; ni < 8; ni++) {
            float2 t0 = *reinterpret_cast<const float2*>(b0p + ni*8);
            float2 t1 = *reinterpret_cast<const float2*>(b1p + ni*8);
            c[ni][0] += t0.x; c[ni][1] += t0.y;
            c[ni][2] += t1.x; c[ni][3] += t1.y;
            rm0 = fmaxf(rm0, fmaxf(c[ni][0], c[ni][1]));
            rm1 = fmaxf(rm1, fmaxf(c[ni][2], c[ni][3]));
        }
        rm0 = fmaxf(rm0, __shfl_xor_sync(0xffffffffu, rm0, 1));
        rm0 = fmaxf(rm0, __shfl_xor_sync(0xffffffffu, rm0, 2));
        rm1 = fmaxf(rm1, __shfl_xor_sync(0xffffffffu, rm1, 1));
        rm1 = fmaxf(rm1, __shfl_xor_sync(0xffffffffu, rm1, 2));
        float mnew0 = fmaxf(mrun0, rm0), mnew1 = fmaxf(mrun1, rm1);
        float corr0 = __expf(mrun0 - mnew0), corr1 = __expf(mrun1 - mnew1);
        mrun0 = mnew0; mrun1 = mnew1;
        float rs0 = 0.f, rs1 = 0.f;
#pragma unroll
        for (int ni = 0; ni < 8; ni++) {
            c[ni][0] = __expf(c[ni][0] - mnew0);
            c[ni][1] = __expf(c[ni][1] - mnew0);
            c[ni][2] = __expf(c[ni][2] - mnew1);
            c[ni][3] = __expf(c[ni][3] - mnew1);
            rs0 += c[ni][0] + c[ni][1];
            rs1 += c[ni][2] + c[ni][3];
        }
        rs0 += __shfl_xor_sync(0xffffffffu, rs0, 1);
        rs0 += __shfl_xor_sync(0xffffffffu, rs0, 2);
        rs1 += __shfl_xor_sync(0xffffffffu, rs1, 1);
        rs1 += __shfl_xor_sync(0xffffffffu, rs1, 2);
        lrun0 = lrun0 * corr0 + rs0;
        lrun1 = lrun1 * corr1 + rs1;
#pragma unroll
        for (int nd = 0; nd < 4; nd++) {
            O[nd][0] *= corr0; O[nd][1] *= corr0;
            O[nd][2] *= corr1; O[nd][3] *= corr1;
        }

        // ---- PV (3-term: Ph*Vh + Pl*Vh + Ph*Vl) ----
#pragma unroll
        for (int t = 0; t < 4; t++) {
            int j0 = 2*t, j1 = 2*t + 1;
            unsigned ph[4], pl[4];
            ph[0] = packbf(c[j0][1], c[j0][0]);
            ph[1] = packbf(c[j0][3], c[j0][2]);
            ph[2] = packbf(c[j1][1], c[j1][0]);
            ph[3] = packbf(c[j1][3], c[j1][2]);
            pl[0] = packbf(c[j0][1] - upperf(ph[0]), c[j0][0] - lowerf(ph[0]));
            pl[1] = packbf(c[j0][3] - upperf(ph[1]), c[j0][2] - lowerf(ph[1]));
            pl[2] = packbf(c[j1][1] - upperf(ph[2]), c[j1][0] - lowerf(ph[2]));
            pl[3] = packbf(c[j1][3] - upperf(ph[3]), c[j1][2] - lowerf(ph[3]));

            unsigned vb[4][2];
#pragma unroll
            for (int tp = 0; tp < 2; tp++) {
                unsigned t4[4];
                ldmatrix_x4(t4, &v_sm[0][0][0] + voff[tp] + t*16);
                vb[tp*2][0]=t4[0]; vb[tp*2][1]=t4[1];
                vb[tp*2+1][0]=t4[2]; vb[tp*2+1][1]=t4[3];
            }
#pragma unroll
            for (int nd = 0; nd < 4; nd++) {
                mma_bf16(O[nd], ph, vb[nd][0], vb[nd][1]);
                mma_bf16(O[nd], pl, vb[nd][0], vb[nd][1]);
            }
#pragma unroll
            for (int tp = 0; tp < 2; tp++) {
                unsigned t4[4];
                ldmatrix_x4(t4, &v_sm[1][0][0] + voff[tp] + t*16);
                vb[tp*2][0]=t4[0]; vb[tp*2][1]=t4[1];
                vb[tp*2+1][0]=t4[2]; vb[tp*2+1][1]=t4[3];
            }
#pragma unroll
            for (int nd = 0; nd < 4; nd++)
                mma_bf16(O[nd], ph, vb[nd][0], vb[nd][1]);
        }
    }

    // epilogue
    float il0 = 1.f / lrun0, il1 = 1.f / lrun1;
    float* o0 = g_attn + ((size_t)b*1024 + qrow0)*128 + h*32 + 2*(lane & 3);
    float* o1 = o0 + 8*128;
#pragma unroll
    for (int nd = 0; nd < 4; nd++) {
        float2 v0; v0.x = O[nd][0]*il0; v0.y = O[nd][1]*il0;
        float2 v1; v1.x = O[nd][2]*il1; v1.y = O[nd][3]*il1;
        *reinterpret_cast<float2*>(o0 + nd*8) = v0;
        *reinterpret_cast<float2*>(o1 + nd*8) = v1;
    }
}

// =====================================================================
// 1x1 conv (GEMM) + bias
// =====================================================================
__global__ __launch_bounds__(256) void outconv_kernel(
    const float* __restrict__ w, const float* __restrict__ bias,
    float* __restrict__ out)
{
    __shared__ float a_t[128][33];
    __shared__ float w_t[128][32];

    const int b  = blockIdx.y;
    const int n0 = blockIdx.x * 128;
    const int tid = threadIdx.x;
    const int nl  = tid & 63;
    const int cog = tid >> 6;

    float acc0[32], acc1[32];
#pragma unroll
    for (int j = 0; j < 32; j++) { acc0[j] = 0.f; acc1[j] = 0.f; }

    for (int c0 = 0; c0 < 128; c0 += 32) {
        __syncthreads();
        for (int e = tid; e < 4096; e += 256) {
            int nn = e >> 5, cc = e & 31;
            a_t[nn][cc] = g_attn[((size_t)b * N_ + n0 + nn) * C_ + c0 + cc];
        }
        for (int e = tid; e < 4096; e += 256) {
            int co = e >> 5, cc = e & 31;
            w_t[co][cc] = w[co * 128 + c0 + cc];
        }
        __syncthreads();
#pragma unroll
        for (int cc = 0; cc < 32; cc++) {
            float a0 = a_t[nl][cc];
            float a1 = a_t[nl + 64][cc];
#pragma unroll
            for (int j = 0; j < 32; j++) {
                float wv = w_t[cog * 32 + j][cc];
                acc0[j] += a0 * wv;
                acc1[j] += a1 * wv;
            }
        }
    }
#pragma unroll
    for (int j = 0; j < 32; j++) {
        int co = cog * 32 + j;
        float bv = bias[co];
        out[((size_t)b * 128 + co) * N_ + n0 + nl]      = acc0[j] + bv;
        out[((size_t)b * 128 + co) * N_ + n0 + nl + 64] = acc1[j] + bv;
    }
}

// =====================================================================
extern "C" void kernel_launch(void* const* d_in, const int* in_sizes, int n_in,
                              void* d_out, int out_size)
{
    const float* x      = (const float*)d_in[0];
    const float* wq     = (const float*)d_in[1];
    const float* gq     = (const float*)d_in[2];
    const float* bq     = (const float*)d_in[3];
    const float* wk     = (const float*)d_in[4];
    const float* gk     = (const float*)d_in[5];
    const float* bk     = (const float*)d_in[6];
    const float* wv     = (const float*)d_in[7];
    const float* gv     = (const float*)d_in[8];
    const float* bv     = (const float*)d_in[9];
    const float* table  = (const float*)d_in[10];
    const int*   relidx = (const int*)  d_in[11];
    const float* out_w  = (const float*)d_in[12];
    const float* out_b  = (const float*)d_in[13];
    float* out = (float*)d_out;

    prep_x_kernel<<<2048, 256>>>(x);                      // 0
    prep_w_kernel<<<1728, 256>>>(wq, wk, wv);             // 1
    bias_kernel<<<1024, 256>>>(table, relidx);            // 2
    conv_mma_kernel<<<dim3(8, 16, 3), 256>>>();           // 3  <- profiled
    gn_reduce1_kernel<<<1536, 256>>>();                   // 4
    gn_reduce2_kernel<<<48, 32>>>();                      // 5
    norm_gelu_kernel<<<dim3(16, 4, 48), 256>>>(gq, bq, gk, bk, gv, bv); // 6
    attn_mma_kernel<<<dim3(8, 64), 256>>>();              // 7
    outconv_kernel<<<dim3(8, 16), 256>>>(out_w, out_b, out); // 8
}

// round 6
// speedup vs baseline: 4.5522x; 1.3372x over previous
#include <cuda_runtime.h>
#include <cuda_bf16.h>
#include <math.h>

#define B_   16
#define C_   128
#define N_   1024
#define H_   4
#define D_   32
#define CN   (C_*N_)

typedef unsigned short ushort_t;

// ---------------- scratch (device globals; no allocations) ----------------
__device__ float g_conv[3][B_*CN];        // conv outputs, [p][b][c][n]
__device__ float g_mean[48];
__device__ float g_rstd[48];
__device__ float g_partf[1536][2];
__device__ float g_bias4[H_*N_*N_];       // [h][n][m]
__device__ float g_attn[B_*N_*C_];        // [b][n][c]

// padded input, transposed: [b][sp_pad(34*40)][ci(128)], hi/lo bf16 bits
__device__ __align__(16) ushort_t g_xpad_hi[B_*34*40*C_];
__device__ __align__(16) ushort_t g_xpad_lo[B_*34*40*C_];
// weights: [p][((ky*3+kx)*128+co)*128+ci]
__device__ __align__(16) __nv_bfloat16 g_w_hi[3][9*128*128];
__device__ __align__(16) __nv_bfloat16 g_w_lo[3][9*128*128];

// attention operands (bf16 bits, hi/lo split)
__device__ __align__(16) ushort_t g_q_hi[64*N_*D_];   // [bh][n][d]
__device__ __align__(16) ushort_t g_q_lo[64*N_*D_];
__device__ __align__(16) ushort_t g_k_hi[64*N_*D_];   // [bh][n][d]
__device__ __align__(16) ushort_t g_k_lo[64*N_*D_];
__device__ __align__(16) ushort_t g_v_hi[64*D_*N_];   // [bh][d][n]  (transposed)
__device__ __align__(16) ushort_t g_v_lo[64*D_*N_];

// =====================================================================
// helpers
// =====================================================================
__device__ __forceinline__ void mma_bf16(float* d, const unsigned* A,
                                         unsigned b0, unsigned b1)
{
    asm volatile(
        "mma.sync.aligned.m16n8k16.row.col.f32.bf16.bf16.f32 "
        "{%0,%1,%2,%3},{%4,%5,%6,%7},{%8,%9},{%0,%1,%2,%3};"
        : "+f"(d[0]), "+f"(d[1]), "+f"(d[2]), "+f"(d[3])
        : "r"(A[0]), "r"(A[1]), "r"(A[2]), "r"(A[3]), "r"(b0), "r"(b1));
}

__device__ __forceinline__ void ldmatrix_x4(unsigned* r, const ushort_t* p)
{
    unsigned addr = (unsigned)__cvta_generic_to_shared((void*)p);
    asm volatile("ldmatrix.sync.aligned.m8n8.x4.shared.b16 {%0,%1,%2,%3}, [%4];"
        : "=r"(r[0]), "=r"(r[1]), "=r"(r[2]), "=r"(r[3]) : "r"(addr));
}

__device__ __forceinline__ void cp_async16(void* smem, const void* gmem)
{
    unsigned s = (unsigned)__cvta_generic_to_shared(smem);
    asm volatile("cp.async.cg.shared.global [%0], [%1], 16;" :: "r"(s), "l"(gmem));
}
__device__ __forceinline__ void cp_async_commit(){ asm volatile("cp.async.commit_group;"); }
__device__ __forceinline__ void cp_async_wait0(){ asm volatile("cp.async.wait_group 0;" ::: "memory"); }

// pack two floats -> bf16x2 (upper = hi_elem, lower = lo_elem)
__device__ __forceinline__ unsigned packbf(float hi_elem, float lo_elem)
{
    unsigned d;
    asm("cvt.rn.bf16x2.f32 %0, %1, %2;" : "=r"(d) : "f"(hi_elem), "f"(lo_elem));
    return d;
}
__device__ __forceinline__ float upperf(unsigned u){ return __uint_as_float(u & 0xffff0000u); }
__device__ __forceinline__ float lowerf(unsigned u){ return __uint_as_float(u << 16); }

// =====================================================================
// Prep: split x into padded transposed bf16 hi/lo  [b][sp(34*40)][ci]
// =====================================================================
__global__ __launch_bounds__(256) void prep_x_kernel(const float* __restrict__ x)
{
    const int total = B_*1360*128;
    for (int e = blockIdx.x*256 + threadIdx.x; e < total; e += gridDim.x*256) {
        int ci = e & 127;
        int t  = e >> 7;
        int sp = t % 1360;
        int b  = t / 1360;
        int yy = sp / 40, xx = sp % 40;
        int y = yy - 1, c = xx - 1;
        float v = 0.f;
        if ((unsigned)y < 32u && (unsigned)c < 32u)
            v = x[((size_t)b*128 + ci)*1024 + y*32 + c];
        __nv_bfloat16 hb = __float2bfloat16(v);
        float lov = v - __bfloat162float(hb);
        __nv_bfloat16 lb = __float2bfloat16(lov);
        g_xpad_hi[e] = *(ushort_t*)&hb;
        g_xpad_lo[e] = *(ushort_t*)&lb;
    }
}

// =====================================================================
// Prep: split + transpose weights
// =====================================================================
__global__ __launch_bounds__(256) void prep_w_kernel(
    const float* __restrict__ wq, const float* __restrict__ wk,
    const float* __restrict__ wv)
{
    int e = blockIdx.x*256 + threadIdx.x;
    if (e >= 3*128*128*9) return;
    int kx = e % 3; int t = e / 3;
    int ky = t % 3; t /= 3;
    int ci = t % 128; t /= 128;
    int co = t % 128;
    int p  = t / 128;
    const float* w = (p == 0) ? wq : (p == 1) ? wk : wv;
    float v = w[((co*128 + ci)*3 + ky)*3 + kx];
    __nv_bfloat16 h = __float2bfloat16(v);
    float lo = v - __bfloat162float(h);
    int dst = ((ky*3 + kx)*128 + co)*128 + ci;
    g_w_hi[p][dst] = h;
    g_w_lo[p][dst] = __float2bfloat16(lo);
}

// =====================================================================
// conv3x3 as bf16x3 tensor-core GEMM, v4: cp.async staging + 2 CTA/SM
// =====================================================================
__global__ __launch_bounds__(256, 2) void conv_mma_kernel()
{
    __shared__ __align__(16) ushort_t a_sm[128*104];      // 26624 B
    __shared__ __align__(16) ushort_t b_sm[2*136*24];     // 13056 B

    const int sp = blockIdx.x, b = blockIdx.y, p = blockIdx.z;
    const int tid = threadIdx.x, lane = tid & 31, wid = tid >> 5;
    const int wm = wid & 1, wn = wid >> 1;
    const int r0 = sp * 4;
    const int n0 = sp * 128;

    const __nv_bfloat16* whi = g_w_hi[p];
    const __nv_bfloat16* wlo = g_w_lo[p];
    const ushort_t* xh = g_xpad_hi + (size_t)b * (1360*128);
    const ushort_t* xl = g_xpad_lo + (size_t)b * (1360*128);

    float acc[4][4][4];
#pragma unroll
    for (int mi = 0; mi < 4; mi++)
#pragma unroll
        for (int ni = 0; ni < 4; ni++)
#pragma unroll
            for (int j = 0; j < 4; j++) acc[mi][ni][j] = 0.f;

    const int m_idx = lane >> 3;
    const int row_in = lane & 7;
    int aoff[4];
#pragma unroll
    for (int mi = 0; mi < 4; mi++)
        aoff[mi] = (wm*64 + mi*16 + (lane & 15))*104 + (lane >> 4)*8;
    int boff[2];
#pragma unroll
    for (int tp = 0; tp < 2; tp++) {
        int tile = tp*2 + (m_idx >> 1);
        int n = wn*32 + tile*8 + row_in;
        int rr = n >> 5, cc = n & 31;
        boff[tp] = (rr*34 + cc)*24 + (m_idx & 1)*8;
    }

    for (int ky = 0; ky < 3; ky++) {
        for (int ci0 = 0; ci0 < 128; ci0 += 16) {
            __syncthreads();
            // stage A: 1536 x 16B via cp.async
            for (int u = tid; u < 1536; u += 256) {
                int half = u & 1;
                int co   = (u >> 1) & 127;
                int sk   = u >> 8;
                int split = (sk >= 3), kx = split ? sk - 3 : sk;
                const __nv_bfloat16* src = (split ? wlo : whi)
                    + ((ky*3 + kx)*128 + co)*128 + ci0 + half*8;
                cp_async16(&a_sm[co*104 + sk*16 + half*8], src);
            }
            // stage B: 544 x 16B via cp.async
            for (int u = tid; u < 544; u += 256) {
                int half = u & 1;
                int idx  = u >> 1;
                int pc = idx % 34;
                int t  = idx / 34;
                int r  = t & 3;
                int split = t >> 2;
                const ushort_t* src = (split ? xl : xh)
                    + ((size_t)(r0 + r + ky)*40 + pc)*128 + ci0 + half*8;
                cp_async16(&b_sm[(split*136 + r*34 + pc)*24 + half*8], src);
            }
            cp_async_commit();
            cp_async_wait0();
            __syncthreads();

#pragma unroll
            for (int kx = 0; kx < 3; kx++) {
                unsigned bf[4][2], Af[4][4];
                {
                    unsigned t4[4];
                    ldmatrix_x4(t4, &b_sm[boff[0] + kx*24]);
                    bf[0][0]=t4[0]; bf[0][1]=t4[1]; bf[1][0]=t4[2]; bf[1][1]=t4[3];
                    ldmatrix_x4(t4, &b_sm[boff[1] + kx*24]);
                    bf[2][0]=t4[0]; bf[2][1]=t4[1]; bf[3][0]=t4[2]; bf[3][1]=t4[3];
                }
#pragma unroll
                for (int mi = 0; mi < 4; mi++)
                    ldmatrix_x4(Af[mi], &a_sm[aoff[mi] + kx*16]);
#pragma unroll
                for (int ni = 0; ni < 4; ni++)
#pragma unroll
                    for (int mi = 0; mi < 4; mi++)
                        mma_bf16(acc[mi][ni], Af[mi], bf[ni][0], bf[ni][1]);
                unsigned bl[4][2];
                {
                    unsigned t4[4];
                    ldmatrix_x4(t4, &b_sm[136*24 + boff[0] + kx*24]);
                    bl[0][0]=t4[0]; bl[0][1]=t4[1]; bl[1][0]=t4[2]; bl[1][1]=t4[3];
                    ldmatrix_x4(t4, &b_sm[136*24 + boff[1] + kx*24]);
                    bl[2][0]=t4[0]; bl[2][1]=t4[1]; bl[3][0]=t4[2]; bl[3][1]=t4[3];
                }
#pragma unroll
                for (int ni = 0; ni < 4; ni++)
#pragma unroll
                    for (int mi = 0; mi < 4; mi++)
                        mma_bf16(acc[mi][ni], Af[mi], bl[ni][0], bl[ni][1]);
#pragma unroll
                for (int mi = 0; mi < 4; mi++)
                    ldmatrix_x4(Af[mi], &a_sm[aoff[mi] + (3 + kx)*16]);
#pragma unroll
                for (int ni = 0; ni < 4; ni++)
#pragma unroll
                    for (int mi = 0; mi < 4; mi++)
                        mma_bf16(acc[mi][ni], Af[mi], bf[ni][0], bf[ni][1]);
            }
        }
    }

    float* outb = &g_conv[p][(size_t)b * CN];
#pragma unroll
    for (int mi = 0; mi < 4; mi++) {
        int row = wm*64 + mi*16 + (lane >> 2);
#pragma unroll
        for (int ni = 0; ni < 4; ni++) {
            int col = n0 + wn*32 + ni*8 + (lane & 3)*2;
            float2 v0; v0.x = acc[mi][ni][0]; v0.y = acc[mi][ni][1];
            float2 v1; v1.x = acc[mi][ni][2]; v1.y = acc[mi][ni][3];
            *reinterpret_cast<float2*>(&outb[(size_t)row*1024 + col])     = v0;
            *reinterpret_cast<float2*>(&outb[(size_t)(row+8)*1024 + col]) = v1;
        }
    }
}

// =====================================================================
// Deterministic two-stage mean/var per (proj, batch), fp32
// =====================================================================
__global__ __launch_bounds__(256) void gn_reduce1_kernel()
{
    const int blk = blockIdx.x;
    const int pb = blk >> 5, seg = blk & 31;
    const float* src = &g_conv[0][0] + (size_t)pb*CN + seg*4096;
    const int tid = threadIdx.x;
    float s = 0.f, s2 = 0.f;
    for (int i = tid; i < 4096; i += 256) {
        float v = src[i];
        s += v; s2 = fmaf(v, v, s2);
    }
    __shared__ float a[256], a2[256];
    a[tid] = s; a2[tid] = s2;
    __syncthreads();
    for (int st = 128; st > 0; st >>= 1) {
        if (tid < st) { a[tid] += a[tid + st]; a2[tid] += a2[tid + st]; }
        __syncthreads();
    }
    if (tid == 0) { g_partf[blk][0] = a[0]; g_partf[blk][1] = a2[0]; }
}

__global__ void gn_reduce2_kernel()
{
    const int pb = blockIdx.x;
    const int l = threadIdx.x;
    float s  = g_partf[pb*32 + l][0];
    float s2 = g_partf[pb*32 + l][1];
    for (int off = 16; off > 0; off >>= 1) {
        s  += __shfl_down_sync(0xffffffffu, s, off);
        s2 += __shfl_down_sync(0xffffffffu, s2, off);
    }
    if (l == 0) {
        float mean = s / (float)CN;
        float var  = s2 / (float)CN - mean * mean;
        g_mean[pb] = mean;
        g_rstd[pb] = rsqrtf(var + 1e-6f);
    }
}

// =====================================================================
// GroupNorm apply + exact GELU -> bf16 hi/lo attention operands
// =====================================================================
__global__ __launch_bounds__(256) void norm_gelu_kernel(
    const float* __restrict__ gq, const float* __restrict__ bq,
    const float* __restrict__ gk, const float* __restrict__ bk,
    const float* __restrict__ gv, const float* __restrict__ bv)
{
    const int pb = blockIdx.z;
    const int p = pb >> 4, b = pb & 15;
    const int h = blockIdx.y;
    const int n0 = blockIdx.x * 64;
    const int tid = threadIdx.x;
    const int bhid = b*4 + h;

    const float* gamma = (p == 0) ? gq : (p == 1) ? gk : gv;
    const float* beta  = (p == 0) ? bq : (p == 1) ? bk : bv;
    const float mean = g_mean[pb];
    const float rstd = g_rstd[pb];

    __shared__ float s[32][65];
    const float* src = g_conv[p] + ((size_t)b * 128 + h * 32) * N_;

    if (p == 2) {
        for (int e = tid; e < 2048; e += 256) {
            int d = e >> 6, nn = e & 63;
            float v = src[(size_t)d * N_ + n0 + nn];
            int c = h * 32 + d;
            v = (v - mean) * rstd * gamma[c] + beta[c];
            v = 0.5f * v * (1.0f + erff(v * 0.70710678118654752f));
            __nv_bfloat16 hb = __float2bfloat16(v);
            float lov = v - __bfloat162float(hb);
            __nv_bfloat16 lb = __float2bfloat16(lov);
            size_t idx = ((size_t)bhid*32 + d)*1024 + n0 + nn;
            g_v_hi[idx] = *(ushort_t*)&hb;
            g_v_lo[idx] = *(ushort_t*)&lb;
        }
    } else {
        for (int e = tid; e < 2048; e += 256) {
            int d = e >> 6, nn = e & 63;
            float v = src[(size_t)d * N_ + n0 + nn];
            int c = h * 32 + d;
            v = (v - mean) * rstd * gamma[c] + beta[c];
            v = 0.5f * v * (1.0f + erff(v * 0.70710678118654752f));
            s[d][nn] = v;
        }
        __syncthreads();
        ushort_t* dhi = (p == 0) ? g_q_hi : g_k_hi;
        ushort_t* dlo = (p == 0) ? g_q_lo : g_k_lo;
        for (int e = tid; e < 2048; e += 256) {
            int nn = e >> 5, d = e & 31;
            float v = s[d][nn];
            __nv_bfloat16 hb = __float2bfloat16(v);
            float lov = v - __bfloat162float(hb);
            __nv_bfloat16 lb = __float2bfloat16(lov);
            size_t idx = ((size_t)bhid*1024 + n0 + nn)*32 + d;
            dhi[idx] = *(ushort_t*)&hb;
            dlo[idx] = *(ushort_t*)&lb;
        }
    }
}

// =====================================================================
// Materialize bias[h][n][m]
// =====================================================================
__global__ __launch_bounds__(256) void bias_kernel(
    const float* __restrict__ table, const int* __restrict__ rel_index)
{
    const int n = blockIdx.x;
    for (int m = threadIdx.x; m < N_; m += 256) {
        int idx = rel_index[n * N_ + m];
        float4 t = *reinterpret_cast<const float4*>(table + idx * 4);
        g_bias4[(0 * N_ + n) * N_ + m] = t.x;
        g_bias4[(1 * N_ + n) * N_ + m] = t.y;
        g_bias4[(2 * N_ + n) * N_ + m] = t.z;
        g_bias4[(3 * N_ + n) * N_ + m] = t.w;
    }
}

// =====================================================================
// Attention via tensor cores (flash-style, fragment softmax)
// =====================================================================
__global__ __launch_bounds__(256, 2) void attn_mma_kernel()
{
    __shared__ __align__(16) ushort_t q_sm[2][128][40];   // 20480 B
    __shared__ __align__(16) ushort_t k_sm[2][64][40];    // 10240 B
    __shared__ __align__(16) ushort_t v_sm[2][32][72];    //  9216 B

    const int tid = threadIdx.x, lane = tid & 31, w = tid >> 5;
    const int qt = blockIdx.x, bh = blockIdx.y;
    const int b = bh >> 2, h = bh & 3;

    // load Q tile (128 rows x 32 d, hi+lo): 1024 uint4
    for (int u = tid; u < 1024; u += 256) {
        int quarter = u & 3, row = (u >> 2) & 127, split = u >> 9;
        const ushort_t* src = (split ? g_q_lo : g_q_hi)
            + ((size_t)bh*1024 + qt*128 + row)*32 + quarter*8;
        *reinterpret_cast<uint4*>(&q_sm[split][row][quarter*8]) =
            *reinterpret_cast<const uint4*>(src);
    }
    __syncthreads();

    unsigned qh[2][4], ql[2][4];
#pragma unroll
    for (int kit = 0; kit < 2; kit++) {
        ldmatrix_x4(qh[kit], &q_sm[0][w*16 + (lane & 15)][kit*16 + (lane >> 4)*8]);
        ldmatrix_x4(ql[kit], &q_sm[1][w*16 + (lane & 15)][kit*16 + (lane >> 4)*8]);
    }

    const int m_idx = lane >> 3;
    const int row_in = lane & 7;
    int koff[4], voff[2];
#pragma unroll
    for (int tp = 0; tp < 4; tp++)
        koff[tp] = ((tp*2 + (m_idx >> 1))*8 + row_in)*40 + (m_idx & 1)*8;
#pragma unroll
    for (int tp = 0; tp < 2; tp++)
        voff[tp] = ((tp*2 + (m_idx >> 1))*8 + row_in)*72 + (m_idx & 1)*8;

    float O[4][4];
#pragma unroll
    for (int nd = 0; nd < 4; nd++)
#pragma unroll
        for (int j = 0; j < 4; j++) O[nd][j] = 0.f;
    float mrun0 = -INFINITY, mrun1 = -INFINITY, lrun0 = 0.f, lrun1 = 0.f;

    const int qrow0 = qt*128 + w*16 + (lane >> 2);
    const float* biasbase = g_bias4 + ((size_t)h*1024 + qrow0)*1024 + 2*(lane & 3);

    for (int kc = 0; kc < 16; kc++) {
        const int m0 = kc * 64;
        __syncthreads();
        // K chunk: 512 uint4 (2/thread)
        for (int u = tid; u < 512; u += 256) {
            int quarter = u & 3, row = (u >> 2) & 63, split = u >> 8;
            const ushort_t* src = (split ? g_k_lo : g_k_hi)
                + ((size_t)bh*1024 + m0 + row)*32 + quarter*8;
            *reinterpret_cast<uint4*>(&k_sm[split][row][quarter*8]) =
                *reinterpret_cast<const uint4*>(src);
        }
        // V chunk: 512 uint4 (2/thread)
        for (int u = tid; u < 512; u += 256) {
            int seg = u & 7, d = (u >> 3) & 31, split = u >> 8;
            const ushort_t* src = (split ? g_v_lo : g_v_hi)
                + ((size_t)bh*32 + d)*1024 + m0 + seg*8;
            *reinterpret_cast<uint4*>(&v_sm[split][d][seg*8]) =
                *reinterpret_cast<const uint4*>(src);
        }
        __syncthreads();

        // ---- S = Q K^T (3-term hi/lo) ----
        float c[8][4];
#pragma unroll
        for (int ni = 0; ni < 8; ni++)
#pragma unroll
            for (int j = 0; j < 4; j++) c[ni][j] = 0.f;

#pragma unroll
        for (int kit = 0; kit < 2; kit++) {
            unsigned kb[8][2];
#pragma unroll
            for (int tp = 0; tp < 4; tp++) {
                unsigned t4[4];
                ldmatrix_x4(t4, &k_sm[0][0][0] + koff[tp] + kit*16);
                kb[tp*2][0]=t4[0]; kb[tp*2][1]=t4[1];
                kb[tp*2+1][0]=t4[2]; kb[tp*2+1][1]=t4[3];
            }
#pragma unroll
            for (int ni = 0; ni < 8; ni++) {
                mma_bf16(c[ni], qh[kit], kb[ni][0], kb[ni][1]);
                mma_bf16(c[ni], ql[kit], kb[ni][0], kb[ni][1]);
            }
#pragma unroll
            for (int tp = 0; tp < 4; tp++) {
                unsigned t4[4];
                ldmatrix_x4(t4, &k_sm[1][0][0] + koff[tp] + kit*16);
                kb[tp*2][0]=t4[0]; kb[tp*2][1]=t4[1];
                kb[tp*2+1][0]=t4[2]; kb[tp*2+1][1]=t4[3];
            }
#pragma unroll
            for (int ni = 0; ni < 8; ni++)
                mma_bf16(c[ni], qh[kit], kb[ni][0], kb[ni][1]);
        }

        // ---- bias + online softmax (fragment layout) ----
        const float* b0p = biasbase + m0;
        const float* b1p = b0p + 8*1024;
        float rm0 = -INFINITY, rm1 = -INFINITY;
#pragma unroll
        for (int ni = 0; ni < 8; ni++) {
            float2 t0 = *reinterpret_cast<const float2*>(b0p + ni*8);
            float2 t1 = *reinterpret_cast<const float2*>(b1p + ni*8);
            c[ni][0] += t0.x; c[ni][1] += t0.y;
            c[ni][2] += t1.x; c[ni][3] += t1.y;
            rm0 = fmaxf(rm0, fmaxf(c[ni][0], c[ni][1]));
            rm1 = fmaxf(rm1, fmaxf(c[ni][2], c[ni][3]));
        }
        rm0 = fmaxf(rm0, __shfl_xor_sync(0xffffffffu, rm0, 1));
        rm0 = fmaxf(rm0, __shfl_xor_sync(0xffffffffu, rm0, 2));
        rm1 = fmaxf(rm1, __shfl_xor_sync(0xffffffffu, rm1, 1));
        rm1 = fmaxf(rm1, __shfl_xor_sync(0xffffffffu, rm1, 2));
        float mnew0 = fmaxf(mrun0, rm0), mnew1 = fmaxf(mrun1, rm1);
        float corr0 = __expf(mrun0 - mnew0), corr1 = __expf(mrun1 - mnew1);
        mrun0 = mnew0; mrun1 = mnew1;
        float rs0 = 0.f, rs1 = 0.f;
#pragma unroll
        for (int ni = 0; ni < 8; ni++) {
            c[ni][0] = __expf(c[ni][0] - mnew0);
            c[ni][1] = __expf(c[ni][1] - mnew0);
            c[ni][2] = __expf(c[ni][2] - mnew1);
            c[ni][3] = __expf(c[ni][3] - mnew1);
            rs0 += c[ni][0] + c[ni][1];
            rs1 += c[ni][2] + c[ni][3];
        }
        rs0 += __shfl_xor_sync(0xffffffffu, rs0, 1);
        rs0 += __shfl_xor_sync(0xffffffffu, rs0, 2);
        rs1 += __shfl_xor_sync(0xffffffffu, rs1, 1);
        rs1 += __shfl_xor_sync(0xffffffffu, rs1, 2);
        lrun0 = lrun0 * corr0 + rs0;
        lrun1 = lrun1 * corr1 + rs1;
#pragma unroll
        for (int nd = 0; nd < 4; nd++) {
            O[nd][0] *= corr0; O[nd][1] *= corr0;
            O[nd][2] *= corr1; O[nd][3] *= corr1;
        }

        // ---- PV (3-term: Ph*Vh + Pl*Vh + Ph*Vl) ----
#pragma unroll
        for (int t = 0; t < 4; t++) {
            int j0 = 2*t, j1 = 2*t + 1;
            unsigned ph[4], pl[4];
            ph[0] = packbf(c[j0][1], c[j0][0]);
            ph[1] = packbf(c[j0][3], c[j0][2]);
            ph[2] = packbf(c[j1][1], c[j1][0]);
            ph[3] = packbf(c[j1][3], c[j1][2]);
            pl[0] = packbf(c[j0][1] - upperf(ph[0]), c[j0][0] - lowerf(ph[0]));
            pl[1] = packbf(c[j0][3] - upperf(ph[1]), c[j0][2] - lowerf(ph[1]));
            pl[2] = packbf(c[j1][1] - upperf(ph[2]), c[j1][0] - lowerf(ph[2]));
            pl[3] = packbf(c[j1][3] - upperf(ph[3]), c[j1][2] - lowerf(ph[3]));

            unsigned vb[4][2];
#pragma unroll
            for (int tp = 0; tp < 2; tp++) {
                unsigned t4[4];
                ldmatrix_x4(t4, &v_sm[0][0][0] + voff[tp] + t*16);
                vb[tp*2][0]=t4[0]; vb[tp*2][1]=t4[1];
                vb[tp*2+1][0]=t4[2]; vb[tp*2+1][1]=t4[3];
            }
#pragma unroll
            for (int nd = 0; nd < 4; nd++) {
                mma_bf16(O[nd], ph, vb[nd][0], vb[nd][1]);
                mma_bf16(O[nd], pl, vb[nd][0], vb[nd][1]);
            }
#pragma unroll
            for (int tp = 0; tp < 2; tp++) {
                unsigned t4[4];
                ldmatrix_x4(t4, &v_sm[1][0][0] + voff[tp] + t*16);
                vb[tp*2][0]=t4[0]; vb[tp*2][1]=t4[1];
                vb[tp*2+1][0]=t4[2]; vb[tp*2+1][1]=t4[3];
            }
#pragma unroll
            for (int nd = 0; nd < 4; nd++)
                mma_bf16(O[nd], ph, vb[nd][0], vb[nd][1]);
        }
    }

    // epilogue
    float il0 = 1.f / lrun0, il1 = 1.f / lrun1;
    float* o0 = g_attn + ((size_t)b*1024 + qrow0)*128 + h*32 + 2*(lane & 3);
    float* o1 = o0 + 8*128;
#pragma unroll
    for (int nd = 0; nd < 4; nd++) {
        float2 v0; v0.x = O[nd][0]*il0; v0.y = O[nd][1]*il0;
        float2 v1; v1.x = O[nd][2]*il1; v1.y = O[nd][3]*il1;
        *reinterpret_cast<float2*>(o0 + nd*8) = v0;
        *reinterpret_cast<float2*>(o1 + nd*8) = v1;
    }
}

// =====================================================================
// 1x1 conv (GEMM) + bias
// =====================================================================
__global__ __launch_bounds__(256) void outconv_kernel(
    const float* __restrict__ w, const float* __restrict__ bias,
    float* __restrict__ out)
{
    __shared__ float a_t[128][33];
    __shared__ float w_t[128][32];

    const int b  = blockIdx.y;
    const int n0 = blockIdx.x * 128;
    const int tid = threadIdx.x;
    const int nl  = tid & 63;
    const int cog = tid >> 6;

    float acc0[32], acc1[32];
#pragma unroll
    for (int j = 0; j < 32; j++) { acc0[j] = 0.f; acc1[j] = 0.f; }

    for (int c0 = 0; c0 < 128; c0 += 32) {
        __syncthreads();
        for (int e = tid; e < 4096; e += 256) {
            int nn = e >> 5, cc = e & 31;
            a_t[nn][cc] = g_attn[((size_t)b * N_ + n0 + nn) * C_ + c0 + cc];
        }
        for (int e = tid; e < 4096; e += 256) {
            int co = e >> 5, cc = e & 31;
            w_t[co][cc] = w[co * 128 + c0 + cc];
        }
        __syncthreads();
#pragma unroll
        for (int cc = 0; cc < 32; cc++) {
            float a0 = a_t[nl][cc];
            float a1 = a_t[nl + 64][cc];
#pragma unroll
            for (int j = 0; j < 32; j++) {
                float wv = w_t[cog * 32 + j][cc];
                acc0[j] += a0 * wv;
                acc1[j] += a1 * wv;
            }
        }
    }
#pragma unroll
    for (int j = 0; j < 32; j++) {
        int co = cog * 32 + j;
        float bv = bias[co];
        out[((size_t)b * 128 + co) * N_ + n0 + nl]      = acc0[j] + bv;
        out[((size_t)b * 128 + co) * N_ + n0 + nl + 64] = acc1[j] + bv;
    }
}

// =====================================================================
extern "C" void kernel_launch(void* const* d_in, const int* in_sizes, int n_in,
                              void* d_out, int out_size)
{
    const float* x      = (const float*)d_in[0];
    const float* wq     = (const float*)d_in[1];
    const float* gq     = (const float*)d_in[2];
    const float* bq     = (const float*)d_in[3];
    const float* wk     = (const float*)d_in[4];
    const float* gk     = (const float*)d_in[5];
    const float* bk     = (const float*)d_in[6];
    const float* wv     = (const float*)d_in[7];
    const float* gv     = (const float*)d_in[8];
    const float* bv     = (const float*)d_in[9];
    const float* table  = (const float*)d_in[10];
    const int*   relidx = (const int*)  d_in[11];
    const float* out_w  = (const float*)d_in[12];
    const float* out_b  = (const float*)d_in[13];
    float* out = (float*)d_out;

    prep_x_kernel<<<2048, 256>>>(x);                      // 0
    prep_w_kernel<<<1728, 256>>>(wq, wk, wv);             // 1
    bias_kernel<<<1024, 256>>>(table, relidx);            // 2
    conv_mma_kernel<<<dim3(8, 16, 3), 256>>>();           // 3  <- profiled
    gn_reduce1_kernel<<<1536, 256>>>();                   // 4
    gn_reduce2_kernel<<<48, 32>>>();                      // 5
    norm_gelu_kernel<<<dim3(16, 4, 48), 256>>>(gq, bq, gk, bk, gv, bv); // 6
    attn_mma_kernel<<<dim3(8, 64), 256>>>();              // 7
    outconv_kernel<<<dim3(8, 16), 256>>>(out_w, out_b, out); // 8
}

// round 7
// speedup vs baseline: 4.9007x; 1.0766x over previous
#include <cuda_runtime.h>
#include <cuda_bf16.h>
#include <math.h>

#define B_   16
#define C_   128
#define N_   1024
#define H_   4
#define D_   32
#define CN   (C_*N_)

typedef unsigned short ushort_t;

// ---------------- scratch (device globals; no allocations) ----------------
__device__ float g_conv[3][B_*CN];        // conv outputs, [p][b][c][n]
__device__ float g_mean[48];
__device__ float g_rstd[48];
__device__ float g_part2[384][2];         // conv-block partial sums (48 pb x 8 sp)
__device__ float g_bias4[H_*N_*N_];       // [h][n][m]
__device__ float g_attn[B_*N_*C_];        // [b][n][c]

// padded input, transposed: [b][sp_pad(34*40)][ci(128)], hi/lo bf16 bits
__device__ __align__(16) ushort_t g_xpad_hi[B_*34*40*C_];
__device__ __align__(16) ushort_t g_xpad_lo[B_*34*40*C_];
// weights: [p][((ky*3+kx)*128+co)*128+ci]
__device__ __align__(16) __nv_bfloat16 g_w_hi[3][9*128*128];
__device__ __align__(16) __nv_bfloat16 g_w_lo[3][9*128*128];

// attention operands (bf16 bits, hi/lo split)
__device__ __align__(16) ushort_t g_q_hi[64*N_*D_];   // [bh][n][d]
__device__ __align__(16) ushort_t g_q_lo[64*N_*D_];
__device__ __align__(16) ushort_t g_k_hi[64*N_*D_];   // [bh][n][d]
__device__ __align__(16) ushort_t g_k_lo[64*N_*D_];
__device__ __align__(16) ushort_t g_v_hi[64*D_*N_];   // [bh][d][n]  (transposed)
__device__ __align__(16) ushort_t g_v_lo[64*D_*N_];

// =====================================================================
// helpers
// =====================================================================
__device__ __forceinline__ void mma_bf16(float* d, const unsigned* A,
                                         unsigned b0, unsigned b1)
{
    asm volatile(
        "mma.sync.aligned.m16n8k16.row.col.f32.bf16.bf16.f32 "
        "{%0,%1,%2,%3},{%4,%5,%6,%7},{%8,%9},{%0,%1,%2,%3};"
        : "+f"(d[0]), "+f"(d[1]), "+f"(d[2]), "+f"(d[3])
        : "r"(A[0]), "r"(A[1]), "r"(A[2]), "r"(A[3]), "r"(b0), "r"(b1));
}

__device__ __forceinline__ void ldmatrix_x4(unsigned* r, const ushort_t* p)
{
    unsigned addr = (unsigned)__cvta_generic_to_shared((void*)p);
    asm volatile("ldmatrix.sync.aligned.m8n8.x4.shared.b16 {%0,%1,%2,%3}, [%4];"
        : "=r"(r[0]), "=r"(r[1]), "=r"(r[2]), "=r"(r[3]) : "r"(addr));
}

__device__ __forceinline__ void cp_async16(void* smem, const void* gmem)
{
    unsigned s = (unsigned)__cvta_generic_to_shared(smem);
    asm volatile("cp.async.cg.shared.global [%0], [%1], 16;" :: "r"(s), "l"(gmem));
}
__device__ __forceinline__ void cp_async_commit(){ asm volatile("cp.async.commit_group;"); }
__device__ __forceinline__ void cp_async_wait0(){ asm volatile("cp.async.wait_group 0;" ::: "memory"); }
__device__ __forceinline__ void cp_async_wait1(){ asm volatile("cp.async.wait_group 1;" ::: "memory"); }

// pack two floats -> bf16x2 (upper = hi_elem, lower = lo_elem)
__device__ __forceinline__ unsigned packbf(float hi_elem, float lo_elem)
{
    unsigned d;
    asm("cvt.rn.bf16x2.f32 %0, %1, %2;" : "=r"(d) : "f"(hi_elem), "f"(lo_elem));
    return d;
}
__device__ __forceinline__ float upperf(unsigned u){ return __uint_as_float(u & 0xffff0000u); }
__device__ __forceinline__ float lowerf(unsigned u){ return __uint_as_float(u << 16); }

// =====================================================================
// Prep: split x into padded transposed bf16 hi/lo  [b][sp(34*40)][ci]
// =====================================================================
__global__ __launch_bounds__(256) void prep_x_kernel(const float* __restrict__ x)
{
    const int total = B_*1360*128;
    for (int e = blockIdx.x*256 + threadIdx.x; e < total; e += gridDim.x*256) {
        int ci = e & 127;
        int t  = e >> 7;
        int sp = t % 1360;
        int b  = t / 1360;
        int yy = sp / 40, xx = sp % 40;
        int y = yy - 1, c = xx - 1;
        float v = 0.f;
        if ((unsigned)y < 32u && (unsigned)c < 32u)
            v = x[((size_t)b*128 + ci)*1024 + y*32 + c];
        __nv_bfloat16 hb = __float2bfloat16(v);
        float lov = v - __bfloat162float(hb);
        __nv_bfloat16 lb = __float2bfloat16(lov);
        g_xpad_hi[e] = *(ushort_t*)&hb;
        g_xpad_lo[e] = *(ushort_t*)&lb;
    }
}

// =====================================================================
// Prep: split + transpose weights
// =====================================================================
__global__ __launch_bounds__(256) void prep_w_kernel(
    const float* __restrict__ wq, const float* __restrict__ wk,
    const float* __restrict__ wv)
{
    int e = blockIdx.x*256 + threadIdx.x;
    if (e >= 3*128*128*9) return;
    int kx = e % 3; int t = e / 3;
    int ky = t % 3; t /= 3;
    int ci = t % 128; t /= 128;
    int co = t % 128;
    int p  = t / 128;
    const float* w = (p == 0) ? wq : (p == 1) ? wk : wv;
    float v = w[((co*128 + ci)*3 + ky)*3 + kx];
    __nv_bfloat16 h = __float2bfloat16(v);
    float lo = v - __bfloat162float(h);
    int dst = ((ky*3 + kx)*128 + co)*128 + ci;
    g_w_hi[p][dst] = h;
    g_w_lo[p][dst] = __float2bfloat16(lo);
}

// =====================================================================
// conv3x3 as bf16x3 tensor-core GEMM, v5: 2-stage cp.async pipeline
// + fused GroupNorm partial reduction in epilogue.
// =====================================================================
__global__ __launch_bounds__(256, 2) void conv_mma_kernel()
{
    __shared__ __align__(16) ushort_t a_sm[2][128*104];   // 53248 B
    __shared__ __align__(16) ushort_t b_sm[2][2*136*24];  // 26112 B

    const int sp = blockIdx.x, b = blockIdx.y, p = blockIdx.z;
    const int tid = threadIdx.x, lane = tid & 31, wid = tid >> 5;
    const int wm = wid & 1, wn = wid >> 1;
    const int r0 = sp * 4;
    const int n0 = sp * 128;

    const __nv_bfloat16* whi = g_w_hi[p];
    const __nv_bfloat16* wlo = g_w_lo[p];
    const ushort_t* xh = g_xpad_hi + (size_t)b * (1360*128);
    const ushort_t* xl = g_xpad_lo + (size_t)b * (1360*128);

    float acc[4][4][4];
#pragma unroll
    for (int mi = 0; mi < 4; mi++)
#pragma unroll
        for (int ni = 0; ni < 4; ni++)
#pragma unroll
            for (int j = 0; j < 4; j++) acc[mi][ni][j] = 0.f;

    const int m_idx = lane >> 3;
    const int row_in = lane & 7;
    int aoff[4];
#pragma unroll
    for (int mi = 0; mi < 4; mi++)
        aoff[mi] = (wm*64 + mi*16 + (lane & 15))*104 + (lane >> 4)*8;
    int boff[2];
#pragma unroll
    for (int tp = 0; tp < 2; tp++) {
        int tile = tp*2 + (m_idx >> 1);
        int n = wn*32 + tile*8 + row_in;
        int rr = n >> 5, cc = n & 31;
        boff[tp] = (rr*34 + cc)*24 + (m_idx & 1)*8;
    }

    // stage loader: s in [0,24) -> (ky = s/8, ci0 = (s%8)*16)
    auto stage = [&](int s, int bufi) {
        int ky = s >> 3, ci0 = (s & 7) << 4;
        for (int u = tid; u < 1536; u += 256) {
            int half = u & 1;
            int co   = (u >> 1) & 127;
            int sk   = u >> 8;
            int split = (sk >= 3), kx = split ? sk - 3 : sk;
            const __nv_bfloat16* src = (split ? wlo : whi)
                + ((ky*3 + kx)*128 + co)*128 + ci0 + half*8;
            cp_async16(&a_sm[bufi][co*104 + sk*16 + half*8], src);
        }
        for (int u = tid; u < 544; u += 256) {
            int half = u & 1;
            int idx  = u >> 1;
            int pc = idx % 34;
            int t  = idx / 34;
            int r  = t & 3;
            int split = t >> 2;
            const ushort_t* src = (split ? xl : xh)
                + ((size_t)(r0 + r + ky)*40 + pc)*128 + ci0 + half*8;
            cp_async16(&b_sm[bufi][(split*136 + r*34 + pc)*24 + half*8], src);
        }
        cp_async_commit();
    };

    stage(0, 0);
    for (int s = 0; s < 24; s++) {
        const int buf = s & 1;
        if (s + 1 < 24) { stage(s + 1, buf ^ 1); cp_async_wait1(); }
        else            { cp_async_wait0(); }
        __syncthreads();

        const ushort_t* ab = a_sm[buf];
        const ushort_t* bb = b_sm[buf];
#pragma unroll
        for (int kx = 0; kx < 3; kx++) {
            unsigned bf[4][2], Af[4][4];
            {
                unsigned t4[4];
                ldmatrix_x4(t4, bb + boff[0] + kx*24);
                bf[0][0]=t4[0]; bf[0][1]=t4[1]; bf[1][0]=t4[2]; bf[1][1]=t4[3];
                ldmatrix_x4(t4, bb + boff[1] + kx*24);
                bf[2][0]=t4[0]; bf[2][1]=t4[1]; bf[3][0]=t4[2]; bf[3][1]=t4[3];
            }
#pragma unroll
            for (int mi = 0; mi < 4; mi++)
                ldmatrix_x4(Af[mi], ab + aoff[mi] + kx*16);
#pragma unroll
            for (int ni = 0; ni < 4; ni++)
#pragma unroll
                for (int mi = 0; mi < 4; mi++)
                    mma_bf16(acc[mi][ni], Af[mi], bf[ni][0], bf[ni][1]);
            unsigned bl[4][2];
            {
                unsigned t4[4];
                ldmatrix_x4(t4, bb + 136*24 + boff[0] + kx*24);
                bl[0][0]=t4[0]; bl[0][1]=t4[1]; bl[1][0]=t4[2]; bl[1][1]=t4[3];
                ldmatrix_x4(t4, bb + 136*24 + boff[1] + kx*24);
                bl[2][0]=t4[0]; bl[2][1]=t4[1]; bl[3][0]=t4[2]; bl[3][1]=t4[3];
            }
#pragma unroll
            for (int ni = 0; ni < 4; ni++)
#pragma unroll
                for (int mi = 0; mi < 4; mi++)
                    mma_bf16(acc[mi][ni], Af[mi], bl[ni][0], bl[ni][1]);
#pragma unroll
            for (int mi = 0; mi < 4; mi++)
                ldmatrix_x4(Af[mi], ab + aoff[mi] + (3 + kx)*16);
#pragma unroll
            for (int ni = 0; ni < 4; ni++)
#pragma unroll
                for (int mi = 0; mi < 4; mi++)
                    mma_bf16(acc[mi][ni], Af[mi], bf[ni][0], bf[ni][1]);
        }
        __syncthreads();
    }

    // epilogue: store + fused GN partial reduction
    float s1 = 0.f, s2 = 0.f;
    float* outb = &g_conv[p][(size_t)b * CN];
#pragma unroll
    for (int mi = 0; mi < 4; mi++) {
        int row = wm*64 + mi*16 + (lane >> 2);
#pragma unroll
        for (int ni = 0; ni < 4; ni++) {
            int col = n0 + wn*32 + ni*8 + (lane & 3)*2;
            float2 v0; v0.x = acc[mi][ni][0]; v0.y = acc[mi][ni][1];
            float2 v1; v1.x = acc[mi][ni][2]; v1.y = acc[mi][ni][3];
            *reinterpret_cast<float2*>(&outb[(size_t)row*1024 + col])     = v0;
            *reinterpret_cast<float2*>(&outb[(size_t)(row+8)*1024 + col]) = v1;
#pragma unroll
            for (int j = 0; j < 4; j++) {
                float v = acc[mi][ni][j];
                s1 += v; s2 = fmaf(v, v, s2);
            }
        }
    }
    float* red = reinterpret_cast<float*>(b_sm);
    red[tid] = s1; red[256 + tid] = s2;
    __syncthreads();
    for (int st = 128; st > 0; st >>= 1) {
        if (tid < st) { red[tid] += red[tid + st]; red[256 + tid] += red[256 + tid + st]; }
        __syncthreads();
    }
    if (tid == 0) {
        int slot = (p*16 + b)*8 + sp;
        g_part2[slot][0] = red[0];
        g_part2[slot][1] = red[256];
    }
}

// =====================================================================
// GN finalize: combine 8 partials per (proj,batch)
// =====================================================================
__global__ void gn_reduce2_kernel()
{
    const int pb = blockIdx.x;            // 48
    const int l = threadIdx.x;            // 32
    float s  = (l < 8) ? g_part2[pb*8 + l][0] : 0.f;
    float s2 = (l < 8) ? g_part2[pb*8 + l][1] : 0.f;
    for (int off = 4; off > 0; off >>= 1) {
        s  += __shfl_down_sync(0xffffffffu, s, off);
        s2 += __shfl_down_sync(0xffffffffu, s2, off);
    }
    if (l == 0) {
        float mean = s / (float)CN;
        float var  = s2 / (float)CN - mean * mean;
        g_mean[pb] = mean;
        g_rstd[pb] = rsqrtf(var + 1e-6f);
    }
}

// =====================================================================
// GroupNorm apply + exact GELU -> bf16 hi/lo attention operands
// =====================================================================
__global__ __launch_bounds__(256) void norm_gelu_kernel(
    const float* __restrict__ gq, const float* __restrict__ bq,
    const float* __restrict__ gk, const float* __restrict__ bk,
    const float* __restrict__ gv, const float* __restrict__ bv)
{
    const int pb = blockIdx.z;
    const int p = pb >> 4, b = pb & 15;
    const int h = blockIdx.y;
    const int n0 = blockIdx.x * 64;
    const int tid = threadIdx.x;
    const int bhid = b*4 + h;

    const float* gamma = (p == 0) ? gq : (p == 1) ? gk : gv;
    const float* beta  = (p == 0) ? bq : (p == 1) ? bk : bv;
    const float mean = g_mean[pb];
    const float rstd = g_rstd[pb];

    __shared__ float s[32][65];
    const float* src = g_conv[p] + ((size_t)b * 128 + h * 32) * N_;

    if (p == 2) {
        for (int e = tid; e < 2048; e += 256) {
            int d = e >> 6, nn = e & 63;
            float v = src[(size_t)d * N_ + n0 + nn];
            int c = h * 32 + d;
            v = (v - mean) * rstd * gamma[c] + beta[c];
            v = 0.5f * v * (1.0f + erff(v * 0.70710678118654752f));
            __nv_bfloat16 hb = __float2bfloat16(v);
            float lov = v - __bfloat162float(hb);
            __nv_bfloat16 lb = __float2bfloat16(lov);
            size_t idx = ((size_t)bhid*32 + d)*1024 + n0 + nn;
            g_v_hi[idx] = *(ushort_t*)&hb;
            g_v_lo[idx] = *(ushort_t*)&lb;
        }
    } else {
        for (int e = tid; e < 2048; e += 256) {
            int d = e >> 6, nn = e & 63;
            float v = src[(size_t)d * N_ + n0 + nn];
            int c = h * 32 + d;
            v = (v - mean) * rstd * gamma[c] + beta[c];
            v = 0.5f * v * (1.0f + erff(v * 0.70710678118654752f));
            s[d][nn] = v;
        }
        __syncthreads();
        ushort_t* dhi = (p == 0) ? g_q_hi : g_k_hi;
        ushort_t* dlo = (p == 0) ? g_q_lo : g_k_lo;
        for (int e = tid; e < 2048; e += 256) {
            int nn = e >> 5, d = e & 31;
            float v = s[d][nn];
            __nv_bfloat16 hb = __float2bfloat16(v);
            float lov = v - __bfloat162float(hb);
            __nv_bfloat16 lb = __float2bfloat16(lov);
            size_t idx = ((size_t)bhid*1024 + n0 + nn)*32 + d;
            dhi[idx] = *(ushort_t*)&hb;
            dlo[idx] = *(ushort_t*)&lb;
        }
    }
}

// =====================================================================
// Materialize bias[h][n][m]
// =====================================================================
__global__ __launch_bounds__(256) void bias_kernel(
    const float* __restrict__ table, const int* __restrict__ rel_index)
{
    const int n = blockIdx.x;
    for (int m = threadIdx.x; m < N_; m += 256) {
        int idx = rel_index[n * N_ + m];
        float4 t = *reinterpret_cast<const float4*>(table + idx * 4);
        g_bias4[(0 * N_ + n) * N_ + m] = t.x;
        g_bias4[(1 * N_ + n) * N_ + m] = t.y;
        g_bias4[(2 * N_ + n) * N_ + m] = t.z;
        g_bias4[(3 * N_ + n) * N_ + m] = t.w;
    }
}

// =====================================================================
// Attention via tensor cores (flash-style, fragment softmax)
// v2: 2-stage cp.async K/V pipeline.
// =====================================================================
__global__ __launch_bounds__(256, 2) void attn_mma_kernel()
{
    __shared__ __align__(16) ushort_t q_sm[2][128][40];      // 20480 B
    __shared__ __align__(16) ushort_t k_sm[2][2][64][40];    // 20480 B
    __shared__ __align__(16) ushort_t v_sm[2][2][32][72];    // 18432 B

    const int tid = threadIdx.x, lane = tid & 31, w = tid >> 5;
    const int qt = blockIdx.x, bh = blockIdx.y;
    const int b = bh >> 2, h = bh & 3;

    auto stage_kv = [&](int kc, int bufi) {
        const int m0 = kc * 64;
        for (int u = tid; u < 512; u += 256) {
            int quarter = u & 3, row = (u >> 2) & 63, split = u >> 8;
            const ushort_t* src = (split ? g_k_lo : g_k_hi)
                + ((size_t)bh*1024 + m0 + row)*32 + quarter*8;
            cp_async16(&k_sm[bufi][split][row][quarter*8], src);
        }
        for (int u = tid; u < 512; u += 256) {
            int seg = u & 7, d = (u >> 3) & 31, split = u >> 8;
            const ushort_t* src = (split ? g_v_lo : g_v_hi)
                + ((size_t)bh*32 + d)*1024 + m0 + seg*8;
            cp_async16(&v_sm[bufi][split][d][seg*8], src);
        }
        cp_async_commit();
    };

    // load Q tile (128 rows x 32 d, hi+lo): 1024 uint4
    for (int u = tid; u < 1024; u += 256) {
        int quarter = u & 3, row = (u >> 2) & 127, split = u >> 9;
        const ushort_t* src = (split ? g_q_lo : g_q_hi)
            + ((size_t)bh*1024 + qt*128 + row)*32 + quarter*8;
        *reinterpret_cast<uint4*>(&q_sm[split][row][quarter*8]) =
            *reinterpret_cast<const uint4*>(src);
    }
    stage_kv(0, 0);
    __syncthreads();

    unsigned qh[2][4], ql[2][4];
#pragma unroll
    for (int kit = 0; kit < 2; kit++) {
        ldmatrix_x4(qh[kit], &q_sm[0][w*16 + (lane & 15)][kit*16 + (lane >> 4)*8]);
        ldmatrix_x4(ql[kit], &q_sm[1][w*16 + (lane & 15)][kit*16 + (lane >> 4)*8]);
    }

    const int m_idx = lane >> 3;
    const int row_in = lane & 7;
    int koff[4], voff[2];
#pragma unroll
    for (int tp = 0; tp < 4; tp++)
        koff[tp] = ((tp*2 + (m_idx >> 1))*8 + row_in)*40 + (m_idx & 1)*8;
#pragma unroll
    for (int tp = 0; tp < 2; tp++)
        voff[tp] = ((tp*2 + (m_idx >> 1))*8 + row_in)*72 + (m_idx & 1)*8;

    float O[4][4];
#pragma unroll
    for (int nd = 0; nd < 4; nd++)
#pragma unroll
        for (int j = 0; j < 4; j++) O[nd][j] = 0.f;
    float mrun0 = -INFINITY, mrun1 = -INFINITY, lrun0 = 0.f, lrun1 = 0.f;

    const int qrow0 = qt*128 + w*16 + (lane >> 2);
    const float* biasbase = g_bias4 + ((size_t)h*1024 + qrow0)*1024 + 2*(lane & 3);

    for (int kc = 0; kc < 16; kc++) {
        const int m0 = kc * 64;
        const int buf = kc & 1;
        if (kc + 1 < 16) { stage_kv(kc + 1, buf ^ 1); cp_async_wait1(); }
        else             { cp_async_wait0(); }
        __syncthreads();

        const ushort_t* kb0 = &k_sm[buf][0][0][0];
        const ushort_t* kb1 = kb0 + 64*40;
        const ushort_t* vb0 = &v_sm[buf][0][0][0];
        const ushort_t* vb1 = vb0 + 32*72;

        // ---- S = Q K^T (3-term hi/lo) ----
        float c[8][4];
#pragma unroll
        for (int ni = 0; ni < 8; ni++)
#pragma unroll
            for (int j = 0; j < 4; j++) c[ni][j] = 0.f;

#pragma unroll
        for (int kit = 0; kit < 2; kit++) {
            unsigned kb[8][2];
#pragma unroll
            for (int tp = 0; tp < 4; tp++) {
                unsigned t4[4];
                ldmatrix_x4(t4, kb0 + koff[tp] + kit*16);
                kb[tp*2][0]=t4[0]; kb[tp*2][1]=t4[1];
                kb[tp*2+1][0]=t4[2]; kb[tp*2+1][1]=t4[3];
            }
#pragma unroll
            for (int ni = 0; ni < 8; ni++) {
                mma_bf16(c[ni], qh[kit], kb[ni][0], kb[ni][1]);
                mma_bf16(c[ni], ql[kit], kb[ni][0], kb[ni][1]);
            }
#pragma unroll
            for (int tp = 0; tp < 4; tp++) {
                unsigned t4[4];
                ldmatrix_x4(t4, kb1 + koff[tp] + kit*16);
                kb[tp*2][0]=t4[0]; kb[tp*2][1]=t4[1];
                kb[tp*2+1][0]=t4[2]; kb[tp*2+1][1]=t4[3];
            }
#pragma unroll
            for (int ni = 0; ni < 8; ni++)
                mma_bf16(c[ni], qh[kit], kb[ni][0], kb[ni][1]);
        }

        // ---- bias + online softmax (fragment layout) ----
        const float* b0p = biasbase + m0;
        const float* b1p = b0p + 8*1024;
        float rm0 = -INFINITY, rm1 = -INFINITY;
#pragma unroll
        for (int ni = 0; ni < 8; ni++) {
            float2 t0 = *reinterpret_cast<const float2*>(b0p + ni*8);
            float2 t1 = *reinterpret_cast<const float2*>(b1p + ni*8);
            c[ni][0] += t0.x; c[ni][1] += t0.y;
            c[ni][2] += t1.x; c[ni][3] += t1.y;
            rm0 = fmaxf(rm0, fmaxf(c[ni][0], c[ni][1]));
            rm1 = fmaxf(rm1, fmaxf(c[ni][2], c[ni][3]));
        }
        rm0 = fmaxf(rm0, __shfl_xor_sync(0xffffffffu, rm0, 1));
        rm0 = fmaxf(rm0, __shfl_xor_sync(0xffffffffu, rm0, 2));
        rm1 = fmaxf(rm1, __shfl_xor_sync(0xffffffffu, rm1, 1));
        rm1 = fmaxf(rm1, __shfl_xor_sync(0xffffffffu, rm1, 2));
        float mnew0 = fmaxf(mrun0, rm0), mnew1 = fmaxf(mrun1, rm1);
        float corr0 = __expf(mrun0 - mnew0), corr1 = __expf(mrun1 - mnew1);
        mrun0 = mnew0; mrun1 = mnew1;
        float rs0 = 0.f, rs1 = 0.f;
#pragma unroll
        for (int ni = 0; ni < 8; ni++) {
            c[ni][0] = __expf(c[ni][0] - mnew0);
            c[ni][1] = __expf(c[ni][1] - mnew0);
            c[ni][2] = __expf(c[ni][2] - mnew1);
            c[ni][3] = __expf(c[ni][3] - mnew1);
            rs0 += c[ni][0] + c[ni][1];
            rs1 += c[ni][2] + c[ni][3];
        }
        rs0 += __shfl_xor_sync(0xffffffffu, rs0, 1);
        rs0 += __shfl_xor_sync(0xffffffffu, rs0, 2);
        rs1 += __shfl_xor_sync(0xffffffffu, rs1, 1);
        rs1 += __shfl_xor_sync(0xffffffffu, rs1, 2);
        lrun0 = lrun0 * corr0 + rs0;
        lrun1 = lrun1 * corr1 + rs1;
#pragma unroll
        for (int nd = 0; nd < 4; nd++) {
            O[nd][0] *= corr0; O[nd][1] *= corr0;
            O[nd][2] *= corr1; O[nd][3] *= corr1;
        }

        // ---- PV (3-term: Ph*Vh + Pl*Vh + Ph*Vl) ----
#pragma unroll
        for (int t = 0; t < 4; t++) {
            int j0 = 2*t, j1 = 2*t + 1;
            unsigned ph[4], pl[4];
            ph[0] = packbf(c[j0][1], c[j0][0]);
            ph[1] = packbf(c[j0][3], c[j0][2]);
            ph[2] = packbf(c[j1][1], c[j1][0]);
            ph[3] = packbf(c[j1][3], c[j1][2]);
            pl[0] = packbf(c[j0][1] - upperf(ph[0]), c[j0][0] - lowerf(ph[0]));
            pl[1] = packbf(c[j0][3] - upperf(ph[1]), c[j0][2] - lowerf(ph[1]));
            pl[2] = packbf(c[j1][1] - upperf(ph[2]), c[j1][0] - lowerf(ph[2]));
            pl[3] = packbf(c[j1][3] - upperf(ph[3]), c[j1][2] - lowerf(ph[3]));

            unsigned vb[4][2];
#pragma unroll
            for (int tp = 0; tp < 2; tp++) {
                unsigned t4[4];
                ldmatrix_x4(t4, vb0 + voff[tp] + t*16);
                vb[tp*2][0]=t4[0]; vb[tp*2][1]=t4[1];
                vb[tp*2+1][0]=t4[2]; vb[tp*2+1][1]=t4[3];
            }
#pragma unroll
            for (int nd = 0; nd < 4; nd++) {
                mma_bf16(O[nd], ph, vb[nd][0], vb[nd][1]);
                mma_bf16(O[nd], pl, vb[nd][0], vb[nd][1]);
            }
#pragma unroll
            for (int tp = 0; tp < 2; tp++) {
                unsigned t4[4];
                ldmatrix_x4(t4, vb1 + voff[tp] + t*16);
                vb[tp*2][0]=t4[0]; vb[tp*2][1]=t4[1];
                vb[tp*2+1][0]=t4[2]; vb[tp*2+1][1]=t4[3];
            }
#pragma unroll
            for (int nd = 0; nd < 4; nd++)
                mma_bf16(O[nd], ph, vb[nd][0], vb[nd][1]);
        }
        __syncthreads();
    }

    // epilogue
    float il0 = 1.f / lrun0, il1 = 1.f / lrun1;
    float* o0 = g_attn + ((size_t)b*1024 + qrow0)*128 + h*32 + 2*(lane & 3);
    float* o1 = o0 + 8*128;
#pragma unroll
    for (int nd = 0; nd < 4; nd++) {
        float2 v0; v0.x = O[nd][0]*il0; v0.y = O[nd][1]*il0;
        float2 v1; v1.x = O[nd][2]*il1; v1.y = O[nd][3]*il1;
        *reinterpret_cast<float2*>(o0 + nd*8) = v0;
        *reinterpret_cast<float2*>(o1 + nd*8) = v1;
    }
}

// =====================================================================
// 1x1 conv (GEMM) + bias
// =====================================================================
__global__ __launch_bounds__(256, 2) void outconv_kernel(
    const float* __restrict__ w, const float* __restrict__ bias,
    float* __restrict__ out)
{
    __shared__ float a_t[128][33];
    __shared__ float w_t[128][32];

    const int b  = blockIdx.y;
    const int n0 = blockIdx.x * 128;
    const int tid = threadIdx.x;
    const int nl  = tid & 63;
    const int cog = tid >> 6;

    float acc0[32], acc1[32];
#pragma unroll
    for (int j = 0; j < 32; j++) { acc0[j] = 0.f; acc1[j] = 0.f; }

    for (int c0 = 0; c0 < 128; c0 += 32) {
        __syncthreads();
        for (int e = tid; e < 4096; e += 256) {
            int nn = e >> 5, cc = e & 31;
            a_t[nn][cc] = g_attn[((size_t)b * N_ + n0 + nn) * C_ + c0 + cc];
        }
        for (int e = tid; e < 4096; e += 256) {
            int co = e >> 5, cc = e & 31;
            w_t[co][cc] = w[co * 128 + c0 + cc];
        }
        __syncthreads();
#pragma unroll
        for (int cc = 0; cc < 32; cc++) {
            float a0 = a_t[nl][cc];
            float a1 = a_t[nl + 64][cc];
#pragma unroll
            for (int j = 0; j < 32; j++) {
                float wv = w_t[cog * 32 + j][cc];
                acc0[j] += a0 * wv;
                acc1[j] += a1 * wv;
            }
        }
    }
#pragma unroll
    for (int j = 0; j < 32; j++) {
        int co = cog * 32 + j;
        float bv = bias[co];
        out[((size_t)b * 128 + co) * N_ + n0 + nl]      = acc0[j] + bv;
        out[((size_t)b * 128 + co) * N_ + n0 + nl + 64] = acc1[j] + bv;
    }
}

// =====================================================================
extern "C" void kernel_launch(void* const* d_in, const int* in_sizes, int n_in,
                              void* d_out, int out_size)
{
    const float* x      = (const float*)d_in[0];
    const float* wq     = (const float*)d_in[1];
    const float* gq     = (const float*)d_in[2];
    const float* bq     = (const float*)d_in[3];
    const float* wk     = (const float*)d_in[4];
    const float* gk     = (const float*)d_in[5];
    const float* bk     = (const float*)d_in[6];
    const float* wv     = (const float*)d_in[7];
    const float* gv     = (const float*)d_in[8];
    const float* bv     = (const float*)d_in[9];
    const float* table  = (const float*)d_in[10];
    const int*   relidx = (const int*)  d_in[11];
    const float* out_w  = (const float*)d_in[12];
    const float* out_b  = (const float*)d_in[13];
    float* out = (float*)d_out;

    prep_x_kernel<<<2048, 256>>>(x);                      // 0
    prep_w_kernel<<<1728, 256>>>(wq, wk, wv);             // 1
    bias_kernel<<<1024, 256>>>(table, relidx);            // 2
    conv_mma_kernel<<<dim3(8, 16, 3), 256>>>();           // 3  <- profiled
    gn_reduce2_kernel<<<48, 32>>>();                      // 4
    norm_gelu_kernel<<<dim3(16, 4, 48), 256>>>(gq, bq, gk, bk, gv, bv); // 5
    attn_mma_kernel<<<dim3(8, 64), 256>>>();              // 6
    outconv_kernel<<<dim3(8, 16), 256>>>(out_w, out_b, out); // 7
}

// round 8
// speedup vs baseline: 5.3450x; 1.0907x over previous
#include <cuda_runtime.h>
#include <cuda_bf16.h>
#include <math.h>

#define B_   16
#define C_   128
#define N_   1024
#define H_   4
#define D_   32
#define CN   (C_*N_)

typedef unsigned short ushort_t;

// ---------------- scratch (device globals; no allocations) ----------------
__device__ float g_conv[3][B_*CN];        // conv outputs, [p][b][c][n]
__device__ float g_mean[48];
__device__ float g_rstd[48];
__device__ float g_part2[384][2];         // conv-block partial sums
__device__ float g_bias4[H_*N_*N_];       // [h][n][m]

// padded input, transposed: [b][sp_pad(34*40)][ci(128)], hi/lo bf16 bits
__device__ __align__(16) ushort_t g_xpad_hi[B_*34*40*C_];
__device__ __align__(16) ushort_t g_xpad_lo[B_*34*40*C_];
// weights: [p][((ky*3+kx)*128+co)*128+ci]
__device__ __align__(16) __nv_bfloat16 g_w_hi[3][9*128*128];
__device__ __align__(16) __nv_bfloat16 g_w_lo[3][9*128*128];
// out_w split: [co][ci]
__device__ __align__(16) ushort_t g_w2_hi[128*128];
__device__ __align__(16) ushort_t g_w2_lo[128*128];

// attention operands (bf16 bits, hi/lo split)
__device__ __align__(16) ushort_t g_q_hi[64*N_*D_];   // [bh][n][d]
__device__ __align__(16) ushort_t g_q_lo[64*N_*D_];
__device__ __align__(16) ushort_t g_k_hi[64*N_*D_];   // [bh][n][d]
__device__ __align__(16) ushort_t g_k_lo[64*N_*D_];
__device__ __align__(16) ushort_t g_v_hi[64*D_*N_];   // [bh][d][n]  (transposed)
__device__ __align__(16) ushort_t g_v_lo[64*D_*N_];
// attention output, bf16 hi/lo: [b][n][c]
__device__ __align__(16) ushort_t g_ao_hi[B_*N_*C_];
__device__ __align__(16) ushort_t g_ao_lo[B_*N_*C_];

// =====================================================================
// helpers
// =====================================================================
__device__ __forceinline__ void mma_bf16(float* d, const unsigned* A,
                                         unsigned b0, unsigned b1)
{
    asm volatile(
        "mma.sync.aligned.m16n8k16.row.col.f32.bf16.bf16.f32 "
        "{%0,%1,%2,%3},{%4,%5,%6,%7},{%8,%9},{%0,%1,%2,%3};"
        : "+f"(d[0]), "+f"(d[1]), "+f"(d[2]), "+f"(d[3])
        : "r"(A[0]), "r"(A[1]), "r"(A[2]), "r"(A[3]), "r"(b0), "r"(b1));
}

__device__ __forceinline__ void ldmatrix_x4(unsigned* r, const ushort_t* p)
{
    unsigned addr = (unsigned)__cvta_generic_to_shared((void*)p);
    asm volatile("ldmatrix.sync.aligned.m8n8.x4.shared.b16 {%0,%1,%2,%3}, [%4];"
        : "=r"(r[0]), "=r"(r[1]), "=r"(r[2]), "=r"(r[3]) : "r"(addr));
}

__device__ __forceinline__ void cp_async16(void* smem, const void* gmem)
{
    unsigned s = (unsigned)__cvta_generic_to_shared(smem);
    asm volatile("cp.async.cg.shared.global [%0], [%1], 16;" :: "r"(s), "l"(gmem));
}
__device__ __forceinline__ void cp_async_commit(){ asm volatile("cp.async.commit_group;"); }
__device__ __forceinline__ void cp_async_wait0(){ asm volatile("cp.async.wait_group 0;" ::: "memory"); }
__device__ __forceinline__ void cp_async_wait1(){ asm volatile("cp.async.wait_group 1;" ::: "memory"); }

__device__ __forceinline__ unsigned packbf(float hi_elem, float lo_elem)
{
    unsigned d;
    asm("cvt.rn.bf16x2.f32 %0, %1, %2;" : "=r"(d) : "f"(hi_elem), "f"(lo_elem));
    return d;
}
__device__ __forceinline__ float upperf(unsigned u){ return __uint_as_float(u & 0xffff0000u); }
__device__ __forceinline__ float lowerf(unsigned u){ return __uint_as_float(u << 16); }

// =====================================================================
// Prep: split x into padded transposed bf16 hi/lo  [b][sp(34*40)][ci]
// =====================================================================
__global__ __launch_bounds__(256) void prep_x_kernel(const float* __restrict__ x)
{
    const int total = B_*1360*128;
    for (int e = blockIdx.x*256 + threadIdx.x; e < total; e += gridDim.x*256) {
        int ci = e & 127;
        int t  = e >> 7;
        int sp = t % 1360;
        int b  = t / 1360;
        int yy = sp / 40, xx = sp % 40;
        int y = yy - 1, c = xx - 1;
        float v = 0.f;
        if ((unsigned)y < 32u && (unsigned)c < 32u)
            v = x[((size_t)b*128 + ci)*1024 + y*32 + c];
        __nv_bfloat16 hb = __float2bfloat16(v);
        float lov = v - __bfloat162float(hb);
        __nv_bfloat16 lb = __float2bfloat16(lov);
        g_xpad_hi[e] = *(ushort_t*)&hb;
        g_xpad_lo[e] = *(ushort_t*)&lb;
    }
}

// =====================================================================
// Prep: split + transpose conv weights, plus out_w split
// =====================================================================
__global__ __launch_bounds__(256) void prep_w_kernel(
    const float* __restrict__ wq, const float* __restrict__ wk,
    const float* __restrict__ wv, const float* __restrict__ w2)
{
    int e = blockIdx.x*256 + threadIdx.x;
    const int conv_total = 3*128*128*9;
    if (e < conv_total) {
        int kx = e % 3; int t = e / 3;
        int ky = t % 3; t /= 3;
        int ci = t % 128; t /= 128;
        int co = t % 128;
        int p  = t / 128;
        const float* w = (p == 0) ? wq : (p == 1) ? wk : wv;
        float v = w[((co*128 + ci)*3 + ky)*3 + kx];
        __nv_bfloat16 h = __float2bfloat16(v);
        float lo = v - __bfloat162float(h);
        int dst = ((ky*3 + kx)*128 + co)*128 + ci;
        g_w_hi[p][dst] = h;
        g_w_lo[p][dst] = __float2bfloat16(lo);
    } else if (e < conv_total + 16384) {
        int i = e - conv_total;            // co*128+ci
        float v = w2[i];
        __nv_bfloat16 h = __float2bfloat16(v);
        float lo = v - __bfloat162float(h);
        __nv_bfloat16 lb = __float2bfloat16(lo);
        g_w2_hi[i] = *(ushort_t*)&h;
        g_w2_lo[i] = *(ushort_t*)&lb;
    }
}

// =====================================================================
// conv3x3 as bf16x3 tensor-core GEMM, v6: 2-stage pipeline +
// strength-reduced staging indices + fused GN partials.
// =====================================================================
__global__ __launch_bounds__(256, 2) void conv_mma_kernel()
{
    __shared__ __align__(16) ushort_t a_sm[2][128*104];   // 53248 B
    __shared__ __align__(16) ushort_t b_sm[2][2*136*24];  // 26112 B

    const int sp = blockIdx.x, b = blockIdx.y, p = blockIdx.z;
    const int tid = threadIdx.x, lane = tid & 31, wid = tid >> 5;
    const int wm = wid & 1, wn = wid >> 1;
    const int r0 = sp * 4;
    const int n0 = sp * 128;

    const __nv_bfloat16* whi = g_w_hi[p];
    const __nv_bfloat16* wlo = g_w_lo[p];
    const ushort_t* xh = g_xpad_hi + (size_t)b * (1360*128);
    const ushort_t* xl = g_xpad_lo + (size_t)b * (1360*128);

    float acc[4][4][4];
#pragma unroll
    for (int mi = 0; mi < 4; mi++)
#pragma unroll
        for (int ni = 0; ni < 4; ni++)
#pragma unroll
            for (int j = 0; j < 4; j++) acc[mi][ni][j] = 0.f;

    const int m_idx = lane >> 3;
    const int row_in = lane & 7;
    int aoff[4];
#pragma unroll
    for (int mi = 0; mi < 4; mi++)
        aoff[mi] = (wm*64 + mi*16 + (lane & 15))*104 + (lane >> 4)*8;
    int boff[2];
#pragma unroll
    for (int tp = 0; tp < 2; tp++) {
        int tile = tp*2 + (m_idx >> 1);
        int n = wn*32 + tile*8 + row_in;
        int rr = n >> 5, cc = n & 31;
        boff[tp] = (rr*34 + cc)*24 + (m_idx & 1)*8;
    }

    // precomputed B-staging indices (3 iterations of the 544-item loop)
    int bsrc[3], bdst[3];
    unsigned bflag[3];     // bit0 = valid, bit1 = split
#pragma unroll
    for (int it = 0; it < 3; it++) {
        int u = tid + it*256;
        int valid = (u < 544);
        int uu = valid ? u : 0;
        int half = uu & 1;
        int idx  = uu >> 1;
        int pc = idx % 34;
        int t  = idx / 34;
        int r  = t & 3;
        int split = t >> 2;
        bsrc[it] = ((r0 + r)*40 + pc)*128 + half*8;
        bdst[it] = (split*136 + r*34 + pc)*24 + half*8;
        bflag[it] = valid | (split << 1);
    }

    auto stage = [&](int s, int bufi) {
        int ky = s >> 3, ci0 = (s & 7) << 4;
        for (int u = tid; u < 1536; u += 256) {
            int half = u & 1;
            int co   = (u >> 1) & 127;
            int sk   = u >> 8;
            int split = (sk >= 3), kx = split ? sk - 3 : sk;
            const __nv_bfloat16* src = (split ? wlo : whi)
                + ((ky*3 + kx)*128 + co)*128 + ci0 + half*8;
            cp_async16(&a_sm[bufi][co*104 + sk*16 + half*8], src);
        }
        int badd = ky*5120 + ci0;
#pragma unroll
        for (int it = 0; it < 3; it++) {
            if (bflag[it] & 1) {
                const ushort_t* base = (bflag[it] & 2) ? xl : xh;
                cp_async16(&b_sm[bufi][bdst[it]], base + bsrc[it] + badd);
            }
        }
        cp_async_commit();
    };

    stage(0, 0);
    for (int s = 0; s < 24; s++) {
        const int buf = s & 1;
        if (s + 1 < 24) { stage(s + 1, buf ^ 1); cp_async_wait1(); }
        else            { cp_async_wait0(); }
        __syncthreads();

        const ushort_t* ab = a_sm[buf];
        const ushort_t* bb = b_sm[buf];
#pragma unroll
        for (int kx = 0; kx < 3; kx++) {
            unsigned bf[4][2], Af[4][4];
            {
                unsigned t4[4];
                ldmatrix_x4(t4, bb + boff[0] + kx*24);
                bf[0][0]=t4[0]; bf[0][1]=t4[1]; bf[1][0]=t4[2]; bf[1][1]=t4[3];
                ldmatrix_x4(t4, bb + boff[1] + kx*24);
                bf[2][0]=t4[0]; bf[2][1]=t4[1]; bf[3][0]=t4[2]; bf[3][1]=t4[3];
            }
#pragma unroll
            for (int mi = 0; mi < 4; mi++)
                ldmatrix_x4(Af[mi], ab + aoff[mi] + kx*16);
#pragma unroll
            for (int ni = 0; ni < 4; ni++)
#pragma unroll
                for (int mi = 0; mi < 4; mi++)
                    mma_bf16(acc[mi][ni], Af[mi], bf[ni][0], bf[ni][1]);
            unsigned bl[4][2];
            {
                unsigned t4[4];
                ldmatrix_x4(t4, bb + 136*24 + boff[0] + kx*24);
                bl[0][0]=t4[0]; bl[0][1]=t4[1]; bl[1][0]=t4[2]; bl[1][1]=t4[3];
                ldmatrix_x4(t4, bb + 136*24 + boff[1] + kx*24);
                bl[2][0]=t4[0]; bl[2][1]=t4[1]; bl[3][0]=t4[2]; bl[3][1]=t4[3];
            }
#pragma unroll
            for (int ni = 0; ni < 4; ni++)
#pragma unroll
                for (int mi = 0; mi < 4; mi++)
                    mma_bf16(acc[mi][ni], Af[mi], bl[ni][0], bl[ni][1]);
#pragma unroll
            for (int mi = 0; mi < 4; mi++)
                ldmatrix_x4(Af[mi], ab + aoff[mi] + (3 + kx)*16);
#pragma unroll
            for (int ni = 0; ni < 4; ni++)
#pragma unroll
                for (int mi = 0; mi < 4; mi++)
                    mma_bf16(acc[mi][ni], Af[mi], bf[ni][0], bf[ni][1]);
        }
        __syncthreads();
    }

    // epilogue: store + fused GN partial reduction
    float s1 = 0.f, s2 = 0.f;
    float* outb = &g_conv[p][(size_t)b * CN];
#pragma unroll
    for (int mi = 0; mi < 4; mi++) {
        int row = wm*64 + mi*16 + (lane >> 2);
#pragma unroll
        for (int ni = 0; ni < 4; ni++) {
            int col = n0 + wn*32 + ni*8 + (lane & 3)*2;
            float2 v0; v0.x = acc[mi][ni][0]; v0.y = acc[mi][ni][1];
            float2 v1; v1.x = acc[mi][ni][2]; v1.y = acc[mi][ni][3];
            *reinterpret_cast<float2*>(&outb[(size_t)row*1024 + col])     = v0;
            *reinterpret_cast<float2*>(&outb[(size_t)(row+8)*1024 + col]) = v1;
#pragma unroll
            for (int j = 0; j < 4; j++) {
                float v = acc[mi][ni][j];
                s1 += v; s2 = fmaf(v, v, s2);
            }
        }
    }
    float* red = reinterpret_cast<float*>(b_sm);
    red[tid] = s1; red[256 + tid] = s2;
    __syncthreads();
    for (int st = 128; st > 0; st >>= 1) {
        if (tid < st) { red[tid] += red[tid + st]; red[256 + tid] += red[256 + tid + st]; }
        __syncthreads();
    }
    if (tid == 0) {
        int slot = (p*16 + b)*8 + sp;
        g_part2[slot][0] = red[0];
        g_part2[slot][1] = red[256];
    }
}

// =====================================================================
// GN finalize
// =====================================================================
__global__ void gn_reduce2_kernel()
{
    const int pb = blockIdx.x;
    const int l = threadIdx.x;
    float s  = (l < 8) ? g_part2[pb*8 + l][0] : 0.f;
    float s2 = (l < 8) ? g_part2[pb*8 + l][1] : 0.f;
    for (int off = 4; off > 0; off >>= 1) {
        s  += __shfl_down_sync(0xffffffffu, s, off);
        s2 += __shfl_down_sync(0xffffffffu, s2, off);
    }
    if (l == 0) {
        float mean = s / (float)CN;
        float var  = s2 / (float)CN - mean * mean;
        g_mean[pb] = mean;
        g_rstd[pb] = rsqrtf(var + 1e-6f);
    }
}

// =====================================================================
// GroupNorm apply + exact GELU -> bf16 hi/lo attention operands
// =====================================================================
__global__ __launch_bounds__(256) void norm_gelu_kernel(
    const float* __restrict__ gq, const float* __restrict__ bq,
    const float* __restrict__ gk, const float* __restrict__ bk,
    const float* __restrict__ gv, const float* __restrict__ bv)
{
    const int pb = blockIdx.z;
    const int p = pb >> 4, b = pb & 15;
    const int h = blockIdx.y;
    const int n0 = blockIdx.x * 64;
    const int tid = threadIdx.x;
    const int bhid = b*4 + h;

    const float* gamma = (p == 0) ? gq : (p == 1) ? gk : gv;
    const float* beta  = (p == 0) ? bq : (p == 1) ? bk : bv;
    const float mean = g_mean[pb];
    const float rstd = g_rstd[pb];

    __shared__ float s[32][65];
    const float* src = g_conv[p] + ((size_t)b * 128 + h * 32) * N_;

    if (p == 2) {
        for (int e = tid; e < 2048; e += 256) {
            int d = e >> 6, nn = e & 63;
            float v = src[(size_t)d * N_ + n0 + nn];
            int c = h * 32 + d;
            v = (v - mean) * rstd * gamma[c] + beta[c];
            v = 0.5f * v * (1.0f + erff(v * 0.70710678118654752f));
            __nv_bfloat16 hb = __float2bfloat16(v);
            float lov = v - __bfloat162float(hb);
            __nv_bfloat16 lb = __float2bfloat16(lov);
            size_t idx = ((size_t)bhid*32 + d)*1024 + n0 + nn;
            g_v_hi[idx] = *(ushort_t*)&hb;
            g_v_lo[idx] = *(ushort_t*)&lb;
        }
    } else {
        for (int e = tid; e < 2048; e += 256) {
            int d = e >> 6, nn = e & 63;
            float v = src[(size_t)d * N_ + n0 + nn];
            int c = h * 32 + d;
            v = (v - mean) * rstd * gamma[c] + beta[c];
            v = 0.5f * v * (1.0f + erff(v * 0.70710678118654752f));
            s[d][nn] = v;
        }
        __syncthreads();
        ushort_t* dhi = (p == 0) ? g_q_hi : g_k_hi;
        ushort_t* dlo = (p == 0) ? g_q_lo : g_k_lo;
        for (int e = tid; e < 2048; e += 256) {
            int nn = e >> 5, d = e & 31;
            float v = s[d][nn];
            __nv_bfloat16 hb = __float2bfloat16(v);
            float lov = v - __bfloat162float(hb);
            __nv_bfloat16 lb = __float2bfloat16(lov);
            size_t idx = ((size_t)bhid*1024 + n0 + nn)*32 + d;
            dhi[idx] = *(ushort_t*)&hb;
            dlo[idx] = *(ushort_t*)&lb;
        }
    }
}

// =====================================================================
// Materialize bias[h][n][m]
// =====================================================================
__global__ __launch_bounds__(256) void bias_kernel(
    const float* __restrict__ table, const int* __restrict__ rel_index)
{
    const int n = blockIdx.x;
    for (int m = threadIdx.x; m < N_; m += 256) {
        int idx = rel_index[n * N_ + m];
        float4 t = *reinterpret_cast<const float4*>(table + idx * 4);
        g_bias4[(0 * N_ + n) * N_ + m] = t.x;
        g_bias4[(1 * N_ + n) * N_ + m] = t.y;
        g_bias4[(2 * N_ + n) * N_ + m] = t.z;
        g_bias4[(3 * N_ + n) * N_ + m] = t.w;
    }
}

// =====================================================================
// Attention via tensor cores (flash-style, fragment softmax)
// v3: bf16 hi/lo output for mma outconv.
// =====================================================================
__global__ __launch_bounds__(256, 2) void attn_mma_kernel()
{
    __shared__ __align__(16) ushort_t q_sm[2][128][40];      // 20480 B
    __shared__ __align__(16) ushort_t k_sm[2][2][64][40];    // 20480 B
    __shared__ __align__(16) ushort_t v_sm[2][2][32][72];    // 18432 B

    const int tid = threadIdx.x, lane = tid & 31, w = tid >> 5;
    const int qt = blockIdx.x, bh = blockIdx.y;
    const int b = bh >> 2, h = bh & 3;

    auto stage_kv = [&](int kc, int bufi) {
        const int m0 = kc * 64;
        for (int u = tid; u < 512; u += 256) {
            int quarter = u & 3, row = (u >> 2) & 63, split = u >> 8;
            const ushort_t* src = (split ? g_k_lo : g_k_hi)
                + ((size_t)bh*1024 + m0 + row)*32 + quarter*8;
            cp_async16(&k_sm[bufi][split][row][quarter*8], src);
        }
        for (int u = tid; u < 512; u += 256) {
            int seg = u & 7, d = (u >> 3) & 31, split = u >> 8;
            const ushort_t* src = (split ? g_v_lo : g_v_hi)
                + ((size_t)bh*32 + d)*1024 + m0 + seg*8;
            cp_async16(&v_sm[bufi][split][d][seg*8], src);
        }
        cp_async_commit();
    };

    for (int u = tid; u < 1024; u += 256) {
        int quarter = u & 3, row = (u >> 2) & 127, split = u >> 9;
        const ushort_t* src = (split ? g_q_lo : g_q_hi)
            + ((size_t)bh*1024 + qt*128 + row)*32 + quarter*8;
        *reinterpret_cast<uint4*>(&q_sm[split][row][quarter*8]) =
            *reinterpret_cast<const uint4*>(src);
    }
    stage_kv(0, 0);
    __syncthreads();

    unsigned qh[2][4], ql[2][4];
#pragma unroll
    for (int kit = 0; kit < 2; kit++) {
        ldmatrix_x4(qh[kit], &q_sm[0][w*16 + (lane & 15)][kit*16 + (lane >> 4)*8]);
        ldmatrix_x4(ql[kit], &q_sm[1][w*16 + (lane & 15)][kit*16 + (lane >> 4)*8]);
    }

    const int m_idx = lane >> 3;
    const int row_in = lane & 7;
    int koff[4], voff[2];
#pragma unroll
    for (int tp = 0; tp < 4; tp++)
        koff[tp] = ((tp*2 + (m_idx >> 1))*8 + row_in)*40 + (m_idx & 1)*8;
#pragma unroll
    for (int tp = 0; tp < 2; tp++)
        voff[tp] = ((tp*2 + (m_idx >> 1))*8 + row_in)*72 + (m_idx & 1)*8;

    float O[4][4];
#pragma unroll
    for (int nd = 0; nd < 4; nd++)
#pragma unroll
        for (int j = 0; j < 4; j++) O[nd][j] = 0.f;
    float mrun0 = -INFINITY, mrun1 = -INFINITY, lrun0 = 0.f, lrun1 = 0.f;

    const int qrow0 = qt*128 + w*16 + (lane >> 2);
    const float* biasbase = g_bias4 + ((size_t)h*1024 + qrow0)*1024 + 2*(lane & 3);

    for (int kc = 0; kc < 16; kc++) {
        const int m0 = kc * 64;
        const int buf = kc & 1;
        if (kc + 1 < 16) { stage_kv(kc + 1, buf ^ 1); cp_async_wait1(); }
        else             { cp_async_wait0(); }
        __syncthreads();

        const ushort_t* kb0 = &k_sm[buf][0][0][0];
        const ushort_t* kb1 = kb0 + 64*40;
        const ushort_t* vb0 = &v_sm[buf][0][0][0];
        const ushort_t* vb1 = vb0 + 32*72;

        float c[8][4];
#pragma unroll
        for (int ni = 0; ni < 8; ni++)
#pragma unroll
            for (int j = 0; j < 4; j++) c[ni][j] = 0.f;

#pragma unroll
        for (int kit = 0; kit < 2; kit++) {
            unsigned kb[8][2];
#pragma unroll
            for (int tp = 0; tp < 4; tp++) {
                unsigned t4[4];
                ldmatrix_x4(t4, kb0 + koff[tp] + kit*16);
                kb[tp*2][0]=t4[0]; kb[tp*2][1]=t4[1];
                kb[tp*2+1][0]=t4[2]; kb[tp*2+1][1]=t4[3];
            }
#pragma unroll
            for (int ni = 0; ni < 8; ni++) {
                mma_bf16(c[ni], qh[kit], kb[ni][0], kb[ni][1]);
                mma_bf16(c[ni], ql[kit], kb[ni][0], kb[ni][1]);
            }
#pragma unroll
            for (int tp = 0; tp < 4; tp++) {
                unsigned t4[4];
                ldmatrix_x4(t4, kb1 + koff[tp] + kit*16);
                kb[tp*2][0]=t4[0]; kb[tp*2][1]=t4[1];
                kb[tp*2+1][0]=t4[2]; kb[tp*2+1][1]=t4[3];
            }
#pragma unroll
            for (int ni = 0; ni < 8; ni++)
                mma_bf16(c[ni], qh[kit], kb[ni][0], kb[ni][1]);
        }

        const float* b0p = biasbase + m0;
        const float* b1p = b0p + 8*1024;
        float rm0 = -INFINITY, rm1 = -INFINITY;
#pragma unroll
        for (int ni = 0; ni < 8; ni++) {
            float2 t0 = *reinterpret_cast<const float2*>(b0p + ni*8);
            float2 t1 = *reinterpret_cast<const float2*>(b1p + ni*8);
            c[ni][0] += t0.x; c[ni][1] += t0.y;
            c[ni][2] += t1.x; c[ni][3] += t1.y;
            rm0 = fmaxf(rm0, fmaxf(c[ni][0], c[ni][1]));
            rm1 = fmaxf(rm1, fmaxf(c[ni][2], c[ni][3]));
        }
        rm0 = fmaxf(rm0, __shfl_xor_sync(0xffffffffu, rm0, 1));
        rm0 = fmaxf(rm0, __shfl_xor_sync(0xffffffffu, rm0, 2));
        rm1 = fmaxf(rm1, __shfl_xor_sync(0xffffffffu, rm1, 1));
        rm1 = fmaxf(rm1, __shfl_xor_sync(0xffffffffu, rm1, 2));
        float mnew0 = fmaxf(mrun0, rm0), mnew1 = fmaxf(mrun1, rm1);
        float corr0 = __expf(mrun0 - mnew0), corr1 = __expf(mrun1 - mnew1);
        mrun0 = mnew0; mrun1 = mnew1;
        float rs0 = 0.f, rs1 = 0.f;
#pragma unroll
        for (int ni = 0; ni < 8; ni++) {
            c[ni][0] = __expf(c[ni][0] - mnew0);
            c[ni][1] = __expf(c[ni][1] - mnew0);
            c[ni][2] = __expf(c[ni][2] - mnew1);
            c[ni][3] = __expf(c[ni][3] - mnew1);
            rs0 += c[ni][0] + c[ni][1];
            rs1 += c[ni][2] + c[ni][3];
        }
        rs0 += __shfl_xor_sync(0xffffffffu, rs0, 1);
        rs0 += __shfl_xor_sync(0xffffffffu, rs0, 2);
        rs1 += __shfl_xor_sync(0xffffffffu, rs1, 1);
        rs1 += __shfl_xor_sync(0xffffffffu, rs1, 2);
        lrun0 = lrun0 * corr0 + rs0;
        lrun1 = lrun1 * corr1 + rs1;
#pragma unroll
        for (int nd = 0; nd < 4; nd++) {
            O[nd][0] *= corr0; O[nd][1] *= corr0;
            O[nd][2] *= corr1; O[nd][3] *= corr1;
        }

#pragma unroll
        for (int t = 0; t < 4; t++) {
            int j0 = 2*t, j1 = 2*t + 1;
            unsigned ph[4], pl[4];
            ph[0] = packbf(c[j0][1], c[j0][0]);
            ph[1] = packbf(c[j0][3], c[j0][2]);
            ph[2] = packbf(c[j1][1], c[j1][0]);
            ph[3] = packbf(c[j1][3], c[j1][2]);
            pl[0] = packbf(c[j0][1] - upperf(ph[0]), c[j0][0] - lowerf(ph[0]));
            pl[1] = packbf(c[j0][3] - upperf(ph[1]), c[j0][2] - lowerf(ph[1]));
            pl[2] = packbf(c[j1][1] - upperf(ph[2]), c[j1][0] - lowerf(ph[2]));
            pl[3] = packbf(c[j1][3] - upperf(ph[3]), c[j1][2] - lowerf(ph[3]));

            unsigned vb[4][2];
#pragma unroll
            for (int tp = 0; tp < 2; tp++) {
                unsigned t4[4];
                ldmatrix_x4(t4, vb0 + voff[tp] + t*16);
                vb[tp*2][0]=t4[0]; vb[tp*2][1]=t4[1];
                vb[tp*2+1][0]=t4[2]; vb[tp*2+1][1]=t4[3];
            }
#pragma unroll
            for (int nd = 0; nd < 4; nd++) {
                mma_bf16(O[nd], ph, vb[nd][0], vb[nd][1]);
                mma_bf16(O[nd], pl, vb[nd][0], vb[nd][1]);
            }
#pragma unroll
            for (int tp = 0; tp < 2; tp++) {
                unsigned t4[4];
                ldmatrix_x4(t4, vb1 + voff[tp] + t*16);
                vb[tp*2][0]=t4[0]; vb[tp*2][1]=t4[1];
                vb[tp*2+1][0]=t4[2]; vb[tp*2+1][1]=t4[3];
            }
#pragma unroll
            for (int nd = 0; nd < 4; nd++)
                mma_bf16(O[nd], ph, vb[nd][0], vb[nd][1]);
        }
        __syncthreads();
    }

    // epilogue: bf16 hi/lo split output [b][n][c]
    float il0 = 1.f / lrun0, il1 = 1.f / lrun1;
    const size_t base0 = ((size_t)b*1024 + qrow0)*128 + h*32 + 2*(lane & 3);
    const size_t base1 = base0 + 8*128;
#pragma unroll
    for (int nd = 0; nd < 4; nd++) {
        float a0 = O[nd][0]*il0, a1 = O[nd][1]*il0;
        float b0 = O[nd][2]*il1, b1 = O[nd][3]*il1;
        unsigned h0 = packbf(a1, a0);
        unsigned l0 = packbf(a1 - upperf(h0), a0 - lowerf(h0));
        unsigned h1 = packbf(b1, b0);
        unsigned l1 = packbf(b1 - upperf(h1), b0 - lowerf(h1));
        *reinterpret_cast<unsigned*>(&g_ao_hi[base0 + nd*8]) = h0;
        *reinterpret_cast<unsigned*>(&g_ao_lo[base0 + nd*8]) = l0;
        *reinterpret_cast<unsigned*>(&g_ao_hi[base1 + nd*8]) = h1;
        *reinterpret_cast<unsigned*>(&g_ao_lo[base1 + nd*8]) = l1;
    }
}

// =====================================================================
// 1x1 conv via tensor cores (bf16x3), + bias.
// grid (8 n-tiles, 16 b), 256 thr, warp tile 64co x 32n.
// =====================================================================
__global__ __launch_bounds__(256, 2) void outconv_mma_kernel(
    const float* __restrict__ bias, float* __restrict__ out)
{
    __shared__ __align__(16) ushort_t a_sm[2][128*40];    // 20480 B
    __shared__ __align__(16) ushort_t b_sm[2][128*40];    // 20480 B

    const int bx = blockIdx.x, b = blockIdx.y;
    const int n0 = bx * 128;
    const int tid = threadIdx.x, lane = tid & 31, wid = tid >> 5;
    const int wm = wid & 1, wn = wid >> 1;
    const int m_idx = lane >> 3;
    const int row_in = lane & 7;

    float acc[4][4][4];
#pragma unroll
    for (int mi = 0; mi < 4; mi++)
#pragma unroll
        for (int ni = 0; ni < 4; ni++)
#pragma unroll
            for (int j = 0; j < 4; j++) acc[mi][ni][j] = 0.f;

    int aoff[4];
#pragma unroll
    for (int mi = 0; mi < 4; mi++)
        aoff[mi] = (wm*64 + mi*16 + (lane & 15))*40 + (lane >> 4)*8;
    int boff[2];
#pragma unroll
    for (int tp = 0; tp < 2; tp++) {
        int tile = tp*2 + (m_idx >> 1);
        int n = wn*32 + tile*8 + row_in;
        boff[tp] = n*40 + (m_idx & 1)*8;
    }

    auto stage = [&](int ck, int bufi) {
        int c0 = ck * 16;
        // A: W2 128co x 16ci, both splits: 512 cp.async
        for (int u = tid; u < 512; u += 256) {
            int half = u & 1, co = (u >> 1) & 127, split = u >> 8;
            const ushort_t* src = (split ? g_w2_lo : g_w2_hi) + co*128 + c0 + half*8;
            cp_async16(&a_sm[bufi][co*40 + split*16 + half*8], src);
        }
        // B: attn 128n x 16c, both splits: 512 cp.async
        for (int u = tid; u < 512; u += 256) {
            int half = u & 1, n = (u >> 1) & 127, split = u >> 8;
            const ushort_t* src = (split ? g_ao_lo : g_ao_hi)
                + ((size_t)b*1024 + n0 + n)*128 + c0 + half*8;
            cp_async16(&b_sm[bufi][n*40 + split*16 + half*8], src);
        }
        cp_async_commit();
    };

    stage(0, 0);
    for (int ck = 0; ck < 8; ck++) {
        const int buf = ck & 1;
        if (ck + 1 < 8) { stage(ck + 1, buf ^ 1); cp_async_wait1(); }
        else            { cp_async_wait0(); }
        __syncthreads();

        const ushort_t* ab = a_sm[buf];
        const ushort_t* bb = b_sm[buf];

        unsigned Ah[4][4], bf[4][2], bl[4][2];
#pragma unroll
        for (int mi = 0; mi < 4; mi++)
            ldmatrix_x4(Ah[mi], ab + aoff[mi]);
        {
            unsigned t4[4];
            ldmatrix_x4(t4, bb + boff[0]);
            bf[0][0]=t4[0]; bf[0][1]=t4[1]; bf[1][0]=t4[2]; bf[1][1]=t4[3];
            ldmatrix_x4(t4, bb + boff[1]);
            bf[2][0]=t4[0]; bf[2][1]=t4[1]; bf[3][0]=t4[2]; bf[3][1]=t4[3];
            ldmatrix_x4(t4, bb + boff[0] + 16);
            bl[0][0]=t4[0]; bl[0][1]=t4[1]; bl[1][0]=t4[2]; bl[1][1]=t4[3];
            ldmatrix_x4(t4, bb + boff[1] + 16);
            bl[2][0]=t4[0]; bl[2][1]=t4[1]; bl[3][0]=t4[2]; bl[3][1]=t4[3];
        }
#pragma unroll
        for (int ni = 0; ni < 4; ni++)
#pragma unroll
            for (int mi = 0; mi < 4; mi++) {
                mma_bf16(acc[mi][ni], Ah[mi], bf[ni][0], bf[ni][1]);
                mma_bf16(acc[mi][ni], Ah[mi], bl[ni][0], bl[ni][1]);
            }
#pragma unroll
        for (int mi = 0; mi < 4; mi++)
            ldmatrix_x4(Ah[mi], ab + aoff[mi] + 16);    // A lo split
#pragma unroll
        for (int ni = 0; ni < 4; ni++)
#pragma unroll
            for (int mi = 0; mi < 4; mi++)
                mma_bf16(acc[mi][ni], Ah[mi], bf[ni][0], bf[ni][1]);
        __syncthreads();
    }

    // epilogue: out[b][co][n] + bias
#pragma unroll
    for (int mi = 0; mi < 4; mi++) {
        int row = wm*64 + mi*16 + (lane >> 2);
        float bv0 = bias[row], bv1 = bias[row + 8];
#pragma unroll
        for (int ni = 0; ni < 4; ni++) {
            int col = n0 + wn*32 + ni*8 + (lane & 3)*2;
            float2 v0; v0.x = acc[mi][ni][0] + bv0; v0.y = acc[mi][ni][1] + bv0;
            float2 v1; v1.x = acc[mi][ni][2] + bv1; v1.y = acc[mi][ni][3] + bv1;
            *reinterpret_cast<float2*>(&out[((size_t)b*128 + row)*1024 + col])     = v0;
            *reinterpret_cast<float2*>(&out[((size_t)b*128 + row + 8)*1024 + col]) = v1;
        }
    }
}

// =====================================================================
extern "C" void kernel_launch(void* const* d_in, const int* in_sizes, int n_in,
                              void* d_out, int out_size)
{
    const float* x      = (const float*)d_in[0];
    const float* wq     = (const float*)d_in[1];
    const float* gq     = (const float*)d_in[2];
    const float* bq     = (const float*)d_in[3];
    const float* wk     = (const float*)d_in[4];
    const float* gk     = (const float*)d_in[5];
    const float* bk     = (const float*)d_in[6];
    const float* wv     = (const float*)d_in[7];
    const float* gv     = (const float*)d_in[8];
    const float* bv     = (const float*)d_in[9];
    const float* table  = (const float*)d_in[10];
    const int*   relidx = (const int*)  d_in[11];
    const float* out_w  = (const float*)d_in[12];
    const float* out_b  = (const float*)d_in[13];
    float* out = (float*)d_out;

    prep_x_kernel<<<2048, 256>>>(x);                      // 0
    prep_w_kernel<<<1792, 256>>>(wq, wk, wv, out_w);      // 1
    bias_kernel<<<1024, 256>>>(table, relidx);            // 2
    conv_mma_kernel<<<dim3(8, 16, 3), 256>>>();           // 3  <- profiled
    gn_reduce2_kernel<<<48, 32>>>();                      // 4
    norm_gelu_kernel<<<dim3(16, 4, 48), 256>>>(gq, bq, gk, bk, gv, bv); // 5
    attn_mma_kernel<<<dim3(8, 64), 256>>>();              // 6
    outconv_mma_kernel<<<dim3(8, 16), 256>>>(out_b, out); // 7
}

// round 9
// speedup vs baseline: 5.3628x; 1.0033x over previous
#include <cuda_runtime.h>
#include <cuda_bf16.h>
#include <math.h>

#define B_   16
#define C_   128
#define N_   1024
#define H_   4
#define D_   32
#define CN   (C_*N_)

typedef unsigned short ushort_t;

// ---------------- scratch (device globals; no allocations) ----------------
__device__ float g_conv[3][B_*CN];        // conv outputs, [p][b][c][n]
__device__ float g_part2[384][2];         // conv-block partial sums
__device__ ushort_t g_bias4[H_*N_*N_];    // [h][n][m]  (bf16 bits)

// padded input, transposed: [b][sp_pad(34*40)][ci(128)], hi/lo bf16 bits
__device__ __align__(16) ushort_t g_xpad_hi[B_*34*40*C_];
__device__ __align__(16) ushort_t g_xpad_lo[B_*34*40*C_];
// weights: [p][((ky*3+kx)*128+co)*128+ci]
__device__ __align__(16) __nv_bfloat16 g_w_hi[3][9*128*128];
__device__ __align__(16) __nv_bfloat16 g_w_lo[3][9*128*128];
// out_w split: [co][ci]
__device__ __align__(16) ushort_t g_w2_hi[128*128];
__device__ __align__(16) ushort_t g_w2_lo[128*128];

// attention operands (bf16 bits, hi/lo split)
__device__ __align__(16) ushort_t g_q_hi[64*N_*D_];   // [bh][n][d]
__device__ __align__(16) ushort_t g_q_lo[64*N_*D_];
__device__ __align__(16) ushort_t g_k_hi[64*N_*D_];   // [bh][n][d]
__device__ __align__(16) ushort_t g_k_lo[64*N_*D_];
__device__ __align__(16) ushort_t g_v_hi[64*D_*N_];   // [bh][d][n]  (transposed)
__device__ __align__(16) ushort_t g_v_lo[64*D_*N_];
// attention output, bf16 hi/lo: [b][n][c]
__device__ __align__(16) ushort_t g_ao_hi[B_*N_*C_];
__device__ __align__(16) ushort_t g_ao_lo[B_*N_*C_];

// =====================================================================
// helpers
// =====================================================================
__device__ __forceinline__ void mma_bf16(float* d, const unsigned* A,
                                         unsigned b0, unsigned b1)
{
    asm volatile(
        "mma.sync.aligned.m16n8k16.row.col.f32.bf16.bf16.f32 "
        "{%0,%1,%2,%3},{%4,%5,%6,%7},{%8,%9},{%0,%1,%2,%3};"
        : "+f"(d[0]), "+f"(d[1]), "+f"(d[2]), "+f"(d[3])
        : "r"(A[0]), "r"(A[1]), "r"(A[2]), "r"(A[3]), "r"(b0), "r"(b1));
}

__device__ __forceinline__ void ldmatrix_x4(unsigned* r, const ushort_t* p)
{
    unsigned addr = (unsigned)__cvta_generic_to_shared((void*)p);
    asm volatile("ldmatrix.sync.aligned.m8n8.x4.shared.b16 {%0,%1,%2,%3}, [%4];"
        : "=r"(r[0]), "=r"(r[1]), "=r"(r[2]), "=r"(r[3]) : "r"(addr));
}

__device__ __forceinline__ void cp_async16(void* smem, const void* gmem)
{
    unsigned s = (unsigned)__cvta_generic_to_shared(smem);
    asm volatile("cp.async.cg.shared.global [%0], [%1], 16;" :: "r"(s), "l"(gmem));
}
__device__ __forceinline__ void cp_async_commit(){ asm volatile("cp.async.commit_group;"); }
__device__ __forceinline__ void cp_async_wait0(){ asm volatile("cp.async.wait_group 0;" ::: "memory"); }
__device__ __forceinline__ void cp_async_wait1(){ asm volatile("cp.async.wait_group 1;" ::: "memory"); }

__device__ __forceinline__ unsigned packbf(float hi_elem, float lo_elem)
{
    unsigned d;
    asm("cvt.rn.bf16x2.f32 %0, %1, %2;" : "=r"(d) : "f"(hi_elem), "f"(lo_elem));
    return d;
}
__device__ __forceinline__ float upperf(unsigned u){ return __uint_as_float(u & 0xffff0000u); }
__device__ __forceinline__ float lowerf(unsigned u){ return __uint_as_float(u << 16); }

// =====================================================================
// prep_all: x split (blocks [0,2048)), conv w split ([2048,3776)),
// out_w split ([3776,3840)), bias gather -> bf16 ([3840,4864))
// =====================================================================
__global__ __launch_bounds__(256) void prep_all_kernel(
    const float* __restrict__ x,
    const float* __restrict__ wq, const float* __restrict__ wk,
    const float* __restrict__ wv, const float* __restrict__ w2,
    const float* __restrict__ table, const int* __restrict__ rel_index)
{
    const int blk = blockIdx.x;
    const int tid = threadIdx.x;

    if (blk < 2048) {
        const int total = B_*1360*128;
        for (int e = blk*256 + tid; e < total; e += 2048*256) {
            int ci = e & 127;
            int t  = e >> 7;
            int sp = t % 1360;
            int b  = t / 1360;
            int yy = sp / 40, xx = sp % 40;
            int y = yy - 1, c = xx - 1;
            float v = 0.f;
            if ((unsigned)y < 32u && (unsigned)c < 32u)
                v = x[((size_t)b*128 + ci)*1024 + y*32 + c];
            __nv_bfloat16 hb = __float2bfloat16(v);
            float lov = v - __bfloat162float(hb);
            __nv_bfloat16 lb = __float2bfloat16(lov);
            g_xpad_hi[e] = *(ushort_t*)&hb;
            g_xpad_lo[e] = *(ushort_t*)&lb;
        }
    } else if (blk < 3776) {
        int e = (blk - 2048)*256 + tid;
        if (e < 3*128*128*9) {
            int kx = e % 3; int t = e / 3;
            int ky = t % 3; t /= 3;
            int ci = t % 128; t /= 128;
            int co = t % 128;
            int p  = t / 128;
            const float* w = (p == 0) ? wq : (p == 1) ? wk : wv;
            float v = w[((co*128 + ci)*3 + ky)*3 + kx];
            __nv_bfloat16 h = __float2bfloat16(v);
            float lo = v - __bfloat162float(h);
            int dst = ((ky*3 + kx)*128 + co)*128 + ci;
            g_w_hi[p][dst] = h;
            g_w_lo[p][dst] = __float2bfloat16(lo);
        }
    } else if (blk < 3840) {
        int i = (blk - 3776)*256 + tid;
        if (i < 16384) {
            float v = w2[i];
            __nv_bfloat16 h = __float2bfloat16(v);
            float lo = v - __bfloat162float(h);
            __nv_bfloat16 lb = __float2bfloat16(lo);
            g_w2_hi[i] = *(ushort_t*)&h;
            g_w2_lo[i] = *(ushort_t*)&lb;
        }
    } else {
        const int n = blk - 3840;
        for (int m = tid; m < N_; m += 256) {
            int idx = rel_index[n * N_ + m];
            float4 t = *reinterpret_cast<const float4*>(table + idx * 4);
            __nv_bfloat16 b0 = __float2bfloat16(t.x);
            __nv_bfloat16 b1 = __float2bfloat16(t.y);
            __nv_bfloat16 b2 = __float2bfloat16(t.z);
            __nv_bfloat16 b3 = __float2bfloat16(t.w);
            g_bias4[(0 * N_ + n) * N_ + m] = *(ushort_t*)&b0;
            g_bias4[(1 * N_ + n) * N_ + m] = *(ushort_t*)&b1;
            g_bias4[(2 * N_ + n) * N_ + m] = *(ushort_t*)&b2;
            g_bias4[(3 * N_ + n) * N_ + m] = *(ushort_t*)&b3;
        }
    }
}

// =====================================================================
// conv3x3 as bf16x3 tensor-core GEMM (2-stage cp.async pipeline,
// strength-reduced staging, fused GN partials)
// =====================================================================
__global__ __launch_bounds__(256, 2) void conv_mma_kernel()
{
    __shared__ __align__(16) ushort_t a_sm[2][128*104];   // 53248 B
    __shared__ __align__(16) ushort_t b_sm[2][2*136*24];  // 26112 B

    const int sp = blockIdx.x, b = blockIdx.y, p = blockIdx.z;
    const int tid = threadIdx.x, lane = tid & 31, wid = tid >> 5;
    const int wm = wid & 1, wn = wid >> 1;
    const int r0 = sp * 4;
    const int n0 = sp * 128;

    const __nv_bfloat16* whi = g_w_hi[p];
    const __nv_bfloat16* wlo = g_w_lo[p];
    const ushort_t* xh = g_xpad_hi + (size_t)b * (1360*128);
    const ushort_t* xl = g_xpad_lo + (size_t)b * (1360*128);

    float acc[4][4][4];
#pragma unroll
    for (int mi = 0; mi < 4; mi++)
#pragma unroll
        for (int ni = 0; ni < 4; ni++)
#pragma unroll
            for (int j = 0; j < 4; j++) acc[mi][ni][j] = 0.f;

    const int m_idx = lane >> 3;
    const int row_in = lane & 7;
    int aoff[4];
#pragma unroll
    for (int mi = 0; mi < 4; mi++)
        aoff[mi] = (wm*64 + mi*16 + (lane & 15))*104 + (lane >> 4)*8;
    int boff[2];
#pragma unroll
    for (int tp = 0; tp < 2; tp++) {
        int tile = tp*2 + (m_idx >> 1);
        int n = wn*32 + tile*8 + row_in;
        int rr = n >> 5, cc = n & 31;
        boff[tp] = (rr*34 + cc)*24 + (m_idx & 1)*8;
    }

    int bsrc[3], bdst[3];
    unsigned bflag[3];
#pragma unroll
    for (int it = 0; it < 3; it++) {
        int u = tid + it*256;
        int valid = (u < 544);
        int uu = valid ? u : 0;
        int half = uu & 1;
        int idx  = uu >> 1;
        int pc = idx % 34;
        int t  = idx / 34;
        int r  = t & 3;
        int split = t >> 2;
        bsrc[it] = ((r0 + r)*40 + pc)*128 + half*8;
        bdst[it] = (split*136 + r*34 + pc)*24 + half*8;
        bflag[it] = valid | (split << 1);
    }

    auto stage = [&](int s, int bufi) {
        int ky = s >> 3, ci0 = (s & 7) << 4;
        for (int u = tid; u < 1536; u += 256) {
            int half = u & 1;
            int co   = (u >> 1) & 127;
            int sk   = u >> 8;
            int split = (sk >= 3), kx = split ? sk - 3 : sk;
            const __nv_bfloat16* src = (split ? wlo : whi)
                + ((ky*3 + kx)*128 + co)*128 + ci0 + half*8;
            cp_async16(&a_sm[bufi][co*104 + sk*16 + half*8], src);
        }
        int badd = ky*5120 + ci0;
#pragma unroll
        for (int it = 0; it < 3; it++) {
            if (bflag[it] & 1) {
                const ushort_t* base = (bflag[it] & 2) ? xl : xh;
                cp_async16(&b_sm[bufi][bdst[it]], base + bsrc[it] + badd);
            }
        }
        cp_async_commit();
    };

    stage(0, 0);
    for (int s = 0; s < 24; s++) {
        const int buf = s & 1;
        if (s + 1 < 24) { stage(s + 1, buf ^ 1); cp_async_wait1(); }
        else            { cp_async_wait0(); }
        __syncthreads();

        const ushort_t* ab = a_sm[buf];
        const ushort_t* bb = b_sm[buf];
#pragma unroll
        for (int kx = 0; kx < 3; kx++) {
            unsigned bf[4][2], Af[4][4];
            {
                unsigned t4[4];
                ldmatrix_x4(t4, bb + boff[0] + kx*24);
                bf[0][0]=t4[0]; bf[0][1]=t4[1]; bf[1][0]=t4[2]; bf[1][1]=t4[3];
                ldmatrix_x4(t4, bb + boff[1] + kx*24);
                bf[2][0]=t4[0]; bf[2][1]=t4[1]; bf[3][0]=t4[2]; bf[3][1]=t4[3];
            }
#pragma unroll
            for (int mi = 0; mi < 4; mi++)
                ldmatrix_x4(Af[mi], ab + aoff[mi] + kx*16);
#pragma unroll
            for (int ni = 0; ni < 4; ni++)
#pragma unroll
                for (int mi = 0; mi < 4; mi++)
                    mma_bf16(acc[mi][ni], Af[mi], bf[ni][0], bf[ni][1]);
            unsigned bl[4][2];
            {
                unsigned t4[4];
                ldmatrix_x4(t4, bb + 136*24 + boff[0] + kx*24);
                bl[0][0]=t4[0]; bl[0][1]=t4[1]; bl[1][0]=t4[2]; bl[1][1]=t4[3];
                ldmatrix_x4(t4, bb + 136*24 + boff[1] + kx*24);
                bl[2][0]=t4[0]; bl[2][1]=t4[1]; bl[3][0]=t4[2]; bl[3][1]=t4[3];
            }
#pragma unroll
            for (int ni = 0; ni < 4; ni++)
#pragma unroll
                for (int mi = 0; mi < 4; mi++)
                    mma_bf16(acc[mi][ni], Af[mi], bl[ni][0], bl[ni][1]);
#pragma unroll
            for (int mi = 0; mi < 4; mi++)
                ldmatrix_x4(Af[mi], ab + aoff[mi] + (3 + kx)*16);
#pragma unroll
            for (int ni = 0; ni < 4; ni++)
#pragma unroll
                for (int mi = 0; mi < 4; mi++)
                    mma_bf16(acc[mi][ni], Af[mi], bf[ni][0], bf[ni][1]);
        }
        __syncthreads();
    }

    // epilogue: store + fused GN partial reduction
    float s1 = 0.f, s2 = 0.f;
    float* outb = &g_conv[p][(size_t)b * CN];
#pragma unroll
    for (int mi = 0; mi < 4; mi++) {
        int row = wm*64 + mi*16 + (lane >> 2);
#pragma unroll
        for (int ni = 0; ni < 4; ni++) {
            int col = n0 + wn*32 + ni*8 + (lane & 3)*2;
            float2 v0; v0.x = acc[mi][ni][0]; v0.y = acc[mi][ni][1];
            float2 v1; v1.x = acc[mi][ni][2]; v1.y = acc[mi][ni][3];
            *reinterpret_cast<float2*>(&outb[(size_t)row*1024 + col])     = v0;
            *reinterpret_cast<float2*>(&outb[(size_t)(row+8)*1024 + col]) = v1;
#pragma unroll
            for (int j = 0; j < 4; j++) {
                float v = acc[mi][ni][j];
                s1 += v; s2 = fmaf(v, v, s2);
            }
        }
    }
    float* red = reinterpret_cast<float*>(b_sm);
    red[tid] = s1; red[256 + tid] = s2;
    __syncthreads();
    for (int st = 128; st > 0; st >>= 1) {
        if (tid < st) { red[tid] += red[tid + st]; red[256 + tid] += red[256 + tid + st]; }
        __syncthreads();
    }
    if (tid == 0) {
        int slot = (p*16 + b)*8 + sp;
        g_part2[slot][0] = red[0];
        g_part2[slot][1] = red[256];
    }
}

// =====================================================================
// GroupNorm apply (inline finalize) + exact GELU -> bf16 hi/lo operands
// =====================================================================
__global__ __launch_bounds__(256) void norm_gelu_kernel(
    const float* __restrict__ gq, const float* __restrict__ bq,
    const float* __restrict__ gk, const float* __restrict__ bk,
    const float* __restrict__ gv, const float* __restrict__ bv)
{
    const int pb = blockIdx.z;
    const int p = pb >> 4, b = pb & 15;
    const int h = blockIdx.y;
    const int n0 = blockIdx.x * 64;
    const int tid = threadIdx.x;
    const int bhid = b*4 + h;

    const float* gamma = (p == 0) ? gq : (p == 1) ? gk : gv;
    const float* beta  = (p == 0) ? bq : (p == 1) ? bk : bv;

    // inline GN finalize (deterministic fixed-order sum of 8 partials)
    float sa = 0.f, sb = 0.f;
#pragma unroll
    for (int i = 0; i < 8; i++) {
        sa += g_part2[pb*8 + i][0];
        sb += g_part2[pb*8 + i][1];
    }
    const float mean = sa / (float)CN;
    const float rstd = rsqrtf(sb / (float)CN - mean*mean + 1e-6f);

    __shared__ float s[32][65];
    const float* src = g_conv[p] + ((size_t)b * 128 + h * 32) * N_;

    if (p == 2) {
        for (int e = tid; e < 2048; e += 256) {
            int d = e >> 6, nn = e & 63;
            float v = src[(size_t)d * N_ + n0 + nn];
            int c = h * 32 + d;
            v = (v - mean) * rstd * gamma[c] + beta[c];
            v = 0.5f * v * (1.0f + erff(v * 0.70710678118654752f));
            __nv_bfloat16 hb = __float2bfloat16(v);
            float lov = v - __bfloat162float(hb);
            __nv_bfloat16 lb = __float2bfloat16(lov);
            size_t idx = ((size_t)bhid*32 + d)*1024 + n0 + nn;
            g_v_hi[idx] = *(ushort_t*)&hb;
            g_v_lo[idx] = *(ushort_t*)&lb;
        }
    } else {
        for (int e = tid; e < 2048; e += 256) {
            int d = e >> 6, nn = e & 63;
            float v = src[(size_t)d * N_ + n0 + nn];
            int c = h * 32 + d;
            v = (v - mean) * rstd * gamma[c] + beta[c];
            v = 0.5f * v * (1.0f + erff(v * 0.70710678118654752f));
            s[d][nn] = v;
        }
        __syncthreads();
        ushort_t* dhi = (p == 0) ? g_q_hi : g_k_hi;
        ushort_t* dlo = (p == 0) ? g_q_lo : g_k_lo;
        for (int e = tid; e < 2048; e += 256) {
            int nn = e >> 5, d = e & 31;
            float v = s[d][nn];
            __nv_bfloat16 hb = __float2bfloat16(v);
            float lov = v - __bfloat162float(hb);
            __nv_bfloat16 lb = __float2bfloat16(lov);
            size_t idx = ((size_t)bhid*1024 + n0 + nn)*32 + d;
            dhi[idx] = *(ushort_t*)&hb;
            dlo[idx] = *(ushort_t*)&lb;
        }
    }
}

// =====================================================================
// Attention via tensor cores (flash-style, fragment softmax),
// bf16 bias reads, bf16 hi/lo output.
// =====================================================================
__global__ __launch_bounds__(256, 2) void attn_mma_kernel()
{
    __shared__ __align__(16) ushort_t q_sm[2][128][40];      // 20480 B
    __shared__ __align__(16) ushort_t k_sm[2][2][64][40];    // 20480 B
    __shared__ __align__(16) ushort_t v_sm[2][2][32][72];    // 18432 B

    const int tid = threadIdx.x, lane = tid & 31, w = tid >> 5;
    const int qt = blockIdx.x, bh = blockIdx.y;
    const int b = bh >> 2, h = bh & 3;

    auto stage_kv = [&](int kc, int bufi) {
        const int m0 = kc * 64;
        for (int u = tid; u < 512; u += 256) {
            int quarter = u & 3, row = (u >> 2) & 63, split = u >> 8;
            const ushort_t* src = (split ? g_k_lo : g_k_hi)
                + ((size_t)bh*1024 + m0 + row)*32 + quarter*8;
            cp_async16(&k_sm[bufi][split][row][quarter*8], src);
        }
        for (int u = tid; u < 512; u += 256) {
            int seg = u & 7, d = (u >> 3) & 31, split = u >> 8;
            const ushort_t* src = (split ? g_v_lo : g_v_hi)
                + ((size_t)bh*32 + d)*1024 + m0 + seg*8;
            cp_async16(&v_sm[bufi][split][d][seg*8], src);
        }
        cp_async_commit();
    };

    for (int u = tid; u < 1024; u += 256) {
        int quarter = u & 3, row = (u >> 2) & 127, split = u >> 9;
        const ushort_t* src = (split ? g_q_lo : g_q_hi)
            + ((size_t)bh*1024 + qt*128 + row)*32 + quarter*8;
        *reinterpret_cast<uint4*>(&q_sm[split][row][quarter*8]) =
            *reinterpret_cast<const uint4*>(src);
    }
    stage_kv(0, 0);
    __syncthreads();

    unsigned qh[2][4], ql[2][4];
#pragma unroll
    for (int kit = 0; kit < 2; kit++) {
        ldmatrix_x4(qh[kit], &q_sm[0][w*16 + (lane & 15)][kit*16 + (lane >> 4)*8]);
        ldmatrix_x4(ql[kit], &q_sm[1][w*16 + (lane & 15)][kit*16 + (lane >> 4)*8]);
    }

    const int m_idx = lane >> 3;
    const int row_in = lane & 7;
    int koff[4], voff[2];
#pragma unroll
    for (int tp = 0; tp < 4; tp++)
        koff[tp] = ((tp*2 + (m_idx >> 1))*8 + row_in)*40 + (m_idx & 1)*8;
#pragma unroll
    for (int tp = 0; tp < 2; tp++)
        voff[tp] = ((tp*2 + (m_idx >> 1))*8 + row_in)*72 + (m_idx & 1)*8;

    float O[4][4];
#pragma unroll
    for (int nd = 0; nd < 4; nd++)
#pragma unroll
        for (int j = 0; j < 4; j++) O[nd][j] = 0.f;
    float mrun0 = -INFINITY, mrun1 = -INFINITY, lrun0 = 0.f, lrun1 = 0.f;

    const int qrow0 = qt*128 + w*16 + (lane >> 2);
    const ushort_t* biasbase = g_bias4 + ((size_t)h*1024 + qrow0)*1024 + 2*(lane & 3);

    for (int kc = 0; kc < 16; kc++) {
        const int m0 = kc * 64;
        const int buf = kc & 1;
        if (kc + 1 < 16) { stage_kv(kc + 1, buf ^ 1); cp_async_wait1(); }
        else             { cp_async_wait0(); }
        __syncthreads();

        const ushort_t* kb0 = &k_sm[buf][0][0][0];
        const ushort_t* kb1 = kb0 + 64*40;
        const ushort_t* vb0 = &v_sm[buf][0][0][0];
        const ushort_t* vb1 = vb0 + 32*72;

        float c[8][4];
#pragma unroll
        for (int ni = 0; ni < 8; ni++)
#pragma unroll
            for (int j = 0; j < 4; j++) c[ni][j] = 0.f;

#pragma unroll
        for (int kit = 0; kit < 2; kit++) {
            unsigned kb[8][2];
#pragma unroll
            for (int tp = 0; tp < 4; tp++) {
                unsigned t4[4];
                ldmatrix_x4(t4, kb0 + koff[tp] + kit*16);
                kb[tp*2][0]=t4[0]; kb[tp*2][1]=t4[1];
                kb[tp*2+1][0]=t4[2]; kb[tp*2+1][1]=t4[3];
            }
#pragma unroll
            for (int ni = 0; ni < 8; ni++) {
                mma_bf16(c[ni], qh[kit], kb[ni][0], kb[ni][1]);
                mma_bf16(c[ni], ql[kit], kb[ni][0], kb[ni][1]);
            }
#pragma unroll
            for (int tp = 0; tp < 4; tp++) {
                unsigned t4[4];
                ldmatrix_x4(t4, kb1 + koff[tp] + kit*16);
                kb[tp*2][0]=t4[0]; kb[tp*2][1]=t4[1];
                kb[tp*2+1][0]=t4[2]; kb[tp*2+1][1]=t4[3];
            }
#pragma unroll
            for (int ni = 0; ni < 8; ni++)
                mma_bf16(c[ni], qh[kit], kb[ni][0], kb[ni][1]);
        }

        // bias (bf16) + online softmax
        const ushort_t* b0p = biasbase + m0;
        const ushort_t* b1p = b0p + 8*1024;
        float rm0 = -INFINITY, rm1 = -INFINITY;
#pragma unroll
        for (int ni = 0; ni < 8; ni++) {
            unsigned u0 = *reinterpret_cast<const unsigned*>(b0p + ni*8);
            unsigned u1 = *reinterpret_cast<const unsigned*>(b1p + ni*8);
            c[ni][0] += lowerf(u0); c[ni][1] += upperf(u0);
            c[ni][2] += lowerf(u1); c[ni][3] += upperf(u1);
            rm0 = fmaxf(rm0, fmaxf(c[ni][0], c[ni][1]));
            rm1 = fmaxf(rm1, fmaxf(c[ni][2], c[ni][3]));
        }
        rm0 = fmaxf(rm0, __shfl_xor_sync(0xffffffffu, rm0, 1));
        rm0 = fmaxf(rm0, __shfl_xor_sync(0xffffffffu, rm0, 2));
        rm1 = fmaxf(rm1, __shfl_xor_sync(0xffffffffu, rm1, 1));
        rm1 = fmaxf(rm1, __shfl_xor_sync(0xffffffffu, rm1, 2));
        float mnew0 = fmaxf(mrun0, rm0), mnew1 = fmaxf(mrun1, rm1);
        float corr0 = __expf(mrun0 - mnew0), corr1 = __expf(mrun1 - mnew1);
        mrun0 = mnew0; mrun1 = mnew1;
        float rs0 = 0.f, rs1 = 0.f;
#pragma unroll
        for (int ni = 0; ni < 8; ni++) {
            c[ni][0] = __expf(c[ni][0] - mnew0);
            c[ni][1] = __expf(c[ni][1] - mnew0);
            c[ni][2] = __expf(c[ni][2] - mnew1);
            c[ni][3] = __expf(c[ni][3] - mnew1);
            rs0 += c[ni][0] + c[ni][1];
            rs1 += c[ni][2] + c[ni][3];
        }
        rs0 += __shfl_xor_sync(0xffffffffu, rs0, 1);
        rs0 += __shfl_xor_sync(0xffffffffu, rs0, 2);
        rs1 += __shfl_xor_sync(0xffffffffu, rs1, 1);
        rs1 += __shfl_xor_sync(0xffffffffu, rs1, 2);
        lrun0 = lrun0 * corr0 + rs0;
        lrun1 = lrun1 * corr1 + rs1;
#pragma unroll
        for (int nd = 0; nd < 4; nd++) {
            O[nd][0] *= corr0; O[nd][1] *= corr0;
            O[nd][2] *= corr1; O[nd][3] *= corr1;
        }

#pragma unroll
        for (int t = 0; t < 4; t++) {
            int j0 = 2*t, j1 = 2*t + 1;
            unsigned ph[4], pl[4];
            ph[0] = packbf(c[j0][1], c[j0][0]);
            ph[1] = packbf(c[j0][3], c[j0][2]);
            ph[2] = packbf(c[j1][1], c[j1][0]);
            ph[3] = packbf(c[j1][3], c[j1][2]);
            pl[0] = packbf(c[j0][1] - upperf(ph[0]), c[j0][0] - lowerf(ph[0]));
            pl[1] = packbf(c[j0][3] - upperf(ph[1]), c[j0][2] - lowerf(ph[1]));
            pl[2] = packbf(c[j1][1] - upperf(ph[2]), c[j1][0] - lowerf(ph[2]));
            pl[3] = packbf(c[j1][3] - upperf(ph[3]), c[j1][2] - lowerf(ph[3]));

            unsigned vb[4][2];
#pragma unroll
            for (int tp = 0; tp < 2; tp++) {
                unsigned t4[4];
                ldmatrix_x4(t4, vb0 + voff[tp] + t*16);
                vb[tp*2][0]=t4[0]; vb[tp*2][1]=t4[1];
                vb[tp*2+1][0]=t4[2]; vb[tp*2+1][1]=t4[3];
            }
#pragma unroll
            for (int nd = 0; nd < 4; nd++) {
                mma_bf16(O[nd], ph, vb[nd][0], vb[nd][1]);
                mma_bf16(O[nd], pl, vb[nd][0], vb[nd][1]);
            }
#pragma unroll
            for (int tp = 0; tp < 2; tp++) {
                unsigned t4[4];
                ldmatrix_x4(t4, vb1 + voff[tp] + t*16);
                vb[tp*2][0]=t4[0]; vb[tp*2][1]=t4[1];
                vb[tp*2+1][0]=t4[2]; vb[tp*2+1][1]=t4[3];
            }
#pragma unroll
            for (int nd = 0; nd < 4; nd++)
                mma_bf16(O[nd], ph, vb[nd][0], vb[nd][1]);
        }
        __syncthreads();
    }

    // epilogue: bf16 hi/lo split output [b][n][c]
    float il0 = 1.f / lrun0, il1 = 1.f / lrun1;
    const size_t base0 = ((size_t)b*1024 + qrow0)*128 + h*32 + 2*(lane & 3);
    const size_t base1 = base0 + 8*128;
#pragma unroll
    for (int nd = 0; nd < 4; nd++) {
        float a0 = O[nd][0]*il0, a1 = O[nd][1]*il0;
        float b0 = O[nd][2]*il1, b1 = O[nd][3]*il1;
        unsigned h0 = packbf(a1, a0);
        unsigned l0 = packbf(a1 - upperf(h0), a0 - lowerf(h0));
        unsigned h1 = packbf(b1, b0);
        unsigned l1 = packbf(b1 - upperf(h1), b0 - lowerf(h1));
        *reinterpret_cast<unsigned*>(&g_ao_hi[base0 + nd*8]) = h0;
        *reinterpret_cast<unsigned*>(&g_ao_lo[base0 + nd*8]) = l0;
        *reinterpret_cast<unsigned*>(&g_ao_hi[base1 + nd*8]) = h1;
        *reinterpret_cast<unsigned*>(&g_ao_lo[base1 + nd*8]) = l1;
    }
}

// =====================================================================
// 1x1 conv via tensor cores (bf16x3), + bias.
// =====================================================================
__global__ __launch_bounds__(256, 2) void outconv_mma_kernel(
    const float* __restrict__ bias, float* __restrict__ out)
{
    __shared__ __align__(16) ushort_t a_sm[2][128*40];
    __shared__ __align__(16) ushort_t b_sm[2][128*40];

    const int bx = blockIdx.x, b = blockIdx.y;
    const int n0 = bx * 128;
    const int tid = threadIdx.x, lane = tid & 31, wid = tid >> 5;
    const int wm = wid & 1, wn = wid >> 1;
    const int m_idx = lane >> 3;
    const int row_in = lane & 7;

    float acc[4][4][4];
#pragma unroll
    for (int mi = 0; mi < 4; mi++)
#pragma unroll
        for (int ni = 0; ni < 4; ni++)
#pragma unroll
            for (int j = 0; j < 4; j++) acc[mi][ni][j] = 0.f;

    int aoff[4];
#pragma unroll
    for (int mi = 0; mi < 4; mi++)
        aoff[mi] = (wm*64 + mi*16 + (lane & 15))*40 + (lane >> 4)*8;
    int boff[2];
#pragma unroll
    for (int tp = 0; tp < 2; tp++) {
        int tile = tp*2 + (m_idx >> 1);
        int n = wn*32 + tile*8 + row_in;
        boff[tp] = n*40 + (m_idx & 1)*8;
    }

    auto stage = [&](int ck, int bufi) {
        int c0 = ck * 16;
        for (int u = tid; u < 512; u += 256) {
            int half = u & 1, co = (u >> 1) & 127, split = u >> 8;
            const ushort_t* src = (split ? g_w2_lo : g_w2_hi) + co*128 + c0 + half*8;
            cp_async16(&a_sm[bufi][co*40 + split*16 + half*8], src);
        }
        for (int u = tid; u < 512; u += 256) {
            int half = u & 1, n = (u >> 1) & 127, split = u >> 8;
            const ushort_t* src = (split ? g_ao_lo : g_ao_hi)
                + ((size_t)b*1024 + n0 + n)*128 + c0 + half*8;
            cp_async16(&b_sm[bufi][n*40 + split*16 + half*8], src);
        }
        cp_async_commit();
    };

    stage(0, 0);
    for (int ck = 0; ck < 8; ck++) {
        const int buf = ck & 1;
        if (ck + 1 < 8) { stage(ck + 1, buf ^ 1); cp_async_wait1(); }
        else            { cp_async_wait0(); }
        __syncthreads();

        const ushort_t* ab = a_sm[buf];
        const ushort_t* bb = b_sm[buf];

        unsigned Ah[4][4], bf[4][2], bl[4][2];
#pragma unroll
        for (int mi = 0; mi < 4; mi++)
            ldmatrix_x4(Ah[mi], ab + aoff[mi]);
        {
            unsigned t4[4];
            ldmatrix_x4(t4, bb + boff[0]);
            bf[0][0]=t4[0]; bf[0][1]=t4[1]; bf[1][0]=t4[2]; bf[1][1]=t4[3];
            ldmatrix_x4(t4, bb + boff[1]);
            bf[2][0]=t4[0]; bf[2][1]=t4[1]; bf[3][0]=t4[2]; bf[3][1]=t4[3];
            ldmatrix_x4(t4, bb + boff[0] + 16);
            bl[0][0]=t4[0]; bl[0][1]=t4[1]; bl[1][0]=t4[2]; bl[1][1]=t4[3];
            ldmatrix_x4(t4, bb + boff[1] + 16);
            bl[2][0]=t4[0]; bl[2][1]=t4[1]; bl[3][0]=t4[2]; bl[3][1]=t4[3];
        }
#pragma unroll
        for (int ni = 0; ni < 4; ni++)
#pragma unroll
            for (int mi = 0; mi < 4; mi++) {
                mma_bf16(acc[mi][ni], Ah[mi], bf[ni][0], bf[ni][1]);
                mma_bf16(acc[mi][ni], Ah[mi], bl[ni][0], bl[ni][1]);
            }
#pragma unroll
        for (int mi = 0; mi < 4; mi++)
            ldmatrix_x4(Ah[mi], ab + aoff[mi] + 16);
#pragma unroll
        for (int ni = 0; ni < 4; ni++)
#pragma unroll
            for (int mi = 0; mi < 4; mi++)
                mma_bf16(acc[mi][ni], Ah[mi], bf[ni][0], bf[ni][1]);
        __syncthreads();
    }

#pragma unroll
    for (int mi = 0; mi < 4; mi++) {
        int row = wm*64 + mi*16 + (lane >> 2);
        float bv0 = bias[row], bv1 = bias[row + 8];
#pragma unroll
        for (int ni = 0; ni < 4; ni++) {
            int col = n0 + wn*32 + ni*8 + (lane & 3)*2;
            float2 v0; v0.x = acc[mi][ni][0] + bv0; v0.y = acc[mi][ni][1] + bv0;
            float2 v1; v1.x = acc[mi][ni][2] + bv1; v1.y = acc[mi][ni][3] + bv1;
            *reinterpret_cast<float2*>(&out[((size_t)b*128 + row)*1024 + col])     = v0;
            *reinterpret_cast<float2*>(&out[((size_t)b*128 + row + 8)*1024 + col]) = v1;
        }
    }
}

// =====================================================================
extern "C" void kernel_launch(void* const* d_in, const int* in_sizes, int n_in,
                              void* d_out, int out_size)
{
    const float* x      = (const float*)d_in[0];
    const float* wq     = (const float*)d_in[1];
    const float* gq     = (const float*)d_in[2];
    const float* bq     = (const float*)d_in[3];
    const float* wk     = (const float*)d_in[4];
    const float* gk     = (const float*)d_in[5];
    const float* bk     = (const float*)d_in[6];
    const float* wv     = (const float*)d_in[7];
    const float* gv     = (const float*)d_in[8];
    const float* bv     = (const float*)d_in[9];
    const float* table  = (const float*)d_in[10];
    const int*   relidx = (const int*)  d_in[11];
    const float* out_w  = (const float*)d_in[12];
    const float* out_b  = (const float*)d_in[13];
    float* out = (float*)d_out;

    prep_all_kernel<<<4864, 256>>>(x, wq, wk, wv, out_w, table, relidx); // 0
    conv_mma_kernel<<<dim3(8, 16, 3), 256>>>();                          // 1
    norm_gelu_kernel<<<dim3(16, 4, 48), 256>>>(gq, bq, gk, bk, gv, bv);  // 2
    attn_mma_kernel<<<dim3(8, 64), 256>>>();                             // 3  <- profiled
    outconv_mma_kernel<<<dim3(8, 16), 256>>>(out_b, out);                // 4
}

// round 10
// speedup vs baseline: 5.3668x; 1.0008x over previous
#include <cuda_runtime.h>
#include <cuda_bf16.h>
#include <math.h>

#define B_   16
#define C_   128
#define N_   1024
#define H_   4
#define D_   32
#define CN   (C_*N_)

typedef unsigned short ushort_t;

// ---------------- scratch (device globals; no allocations) ----------------
__device__ float g_conv[3][B_*CN];        // conv outputs, [p][b][c][n]
__device__ float g_part2[384][2];         // conv-block partial sums
__device__ ushort_t g_bias4[H_*N_*N_];    // [h][n][m]  (bf16 bits)

// padded input, transposed: [b][sp_pad(34*40)][ci(128)], hi/lo bf16 bits
__device__ __align__(16) ushort_t g_xpad_hi[B_*34*40*C_];
__device__ __align__(16) ushort_t g_xpad_lo[B_*34*40*C_];
// weights: [p][((ky*3+kx)*128+co)*128+ci]
__device__ __align__(16) __nv_bfloat16 g_w_hi[3][9*128*128];
__device__ __align__(16) __nv_bfloat16 g_w_lo[3][9*128*128];
// out_w split: [co][ci]
__device__ __align__(16) ushort_t g_w2_hi[128*128];
__device__ __align__(16) ushort_t g_w2_lo[128*128];

// attention operands (bf16 bits, hi/lo split)
__device__ __align__(16) ushort_t g_q_hi[64*N_*D_];   // [bh][n][d]
__device__ __align__(16) ushort_t g_q_lo[64*N_*D_];
__device__ __align__(16) ushort_t g_k_hi[64*N_*D_];   // [bh][n][d]
__device__ __align__(16) ushort_t g_k_lo[64*N_*D_];
__device__ __align__(16) ushort_t g_v_hi[64*D_*N_];   // [bh][d][n]  (transposed)
__device__ __align__(16) ushort_t g_v_lo[64*D_*N_];
// attention output, bf16 hi/lo: [b][n][c]
__device__ __align__(16) ushort_t g_ao_hi[B_*N_*C_];
__device__ __align__(16) ushort_t g_ao_lo[B_*N_*C_];

// =====================================================================
// helpers
// =====================================================================
__device__ __forceinline__ void mma_bf16(float* d, const unsigned* A,
                                         unsigned b0, unsigned b1)
{
    asm volatile(
        "mma.sync.aligned.m16n8k16.row.col.f32.bf16.bf16.f32 "
        "{%0,%1,%2,%3},{%4,%5,%6,%7},{%8,%9},{%0,%1,%2,%3};"
        : "+f"(d[0]), "+f"(d[1]), "+f"(d[2]), "+f"(d[3])
        : "r"(A[0]), "r"(A[1]), "r"(A[2]), "r"(A[3]), "r"(b0), "r"(b1));
}

__device__ __forceinline__ void ldmatrix_x4(unsigned* r, const ushort_t* p)
{
    unsigned addr = (unsigned)__cvta_generic_to_shared((void*)p);
    asm volatile("ldmatrix.sync.aligned.m8n8.x4.shared.b16 {%0,%1,%2,%3}, [%4];"
        : "=r"(r[0]), "=r"(r[1]), "=r"(r[2]), "=r"(r[3]) : "r"(addr));
}

__device__ __forceinline__ void cp_async16(void* smem, const void* gmem)
{
    unsigned s = (unsigned)__cvta_generic_to_shared(smem);
    asm volatile("cp.async.cg.shared.global [%0], [%1], 16;" :: "r"(s), "l"(gmem));
}
__device__ __forceinline__ void cp_async_commit(){ asm volatile("cp.async.commit_group;"); }
__device__ __forceinline__ void cp_async_wait0(){ asm volatile("cp.async.wait_group 0;" ::: "memory"); }
__device__ __forceinline__ void cp_async_wait1(){ asm volatile("cp.async.wait_group 1;" ::: "memory"); }

__device__ __forceinline__ unsigned packbf(float hi_elem, float lo_elem)
{
    unsigned d;
    asm("cvt.rn.bf16x2.f32 %0, %1, %2;" : "=r"(d) : "f"(hi_elem), "f"(lo_elem));
    return d;
}
__device__ __forceinline__ float upperf(unsigned u){ return __uint_as_float(u & 0xffff0000u); }
__device__ __forceinline__ float lowerf(unsigned u){ return __uint_as_float(u << 16); }

// =====================================================================
// prep_all
// =====================================================================
__global__ __launch_bounds__(256) void prep_all_kernel(
    const float* __restrict__ x,
    const float* __restrict__ wq, const float* __restrict__ wk,
    const float* __restrict__ wv, const float* __restrict__ w2,
    const float* __restrict__ table, const int* __restrict__ rel_index)
{
    const int blk = blockIdx.x;
    const int tid = threadIdx.x;

    if (blk < 2048) {
        const int total = B_*1360*128;
        for (int e = blk*256 + tid; e < total; e += 2048*256) {
            int ci = e & 127;
            int t  = e >> 7;
            int sp = t % 1360;
            int b  = t / 1360;
            int yy = sp / 40, xx = sp % 40;
            int y = yy - 1, c = xx - 1;
            float v = 0.f;
            if ((unsigned)y < 32u && (unsigned)c < 32u)
                v = x[((size_t)b*128 + ci)*1024 + y*32 + c];
            __nv_bfloat16 hb = __float2bfloat16(v);
            float lov = v - __bfloat162float(hb);
            __nv_bfloat16 lb = __float2bfloat16(lov);
            g_xpad_hi[e] = *(ushort_t*)&hb;
            g_xpad_lo[e] = *(ushort_t*)&lb;
        }
    } else if (blk < 3776) {
        int e = (blk - 2048)*256 + tid;
        if (e < 3*128*128*9) {
            int kx = e % 3; int t = e / 3;
            int ky = t % 3; t /= 3;
            int ci = t % 128; t /= 128;
            int co = t % 128;
            int p  = t / 128;
            const float* w = (p == 0) ? wq : (p == 1) ? wk : wv;
            float v = w[((co*128 + ci)*3 + ky)*3 + kx];
            __nv_bfloat16 h = __float2bfloat16(v);
            float lo = v - __bfloat162float(h);
            int dst = ((ky*3 + kx)*128 + co)*128 + ci;
            g_w_hi[p][dst] = h;
            g_w_lo[p][dst] = __float2bfloat16(lo);
        }
    } else if (blk < 3840) {
        int i = (blk - 3776)*256 + tid;
        if (i < 16384) {
            float v = w2[i];
            __nv_bfloat16 h = __float2bfloat16(v);
            float lo = v - __bfloat162float(h);
            __nv_bfloat16 lb = __float2bfloat16(lo);
            g_w2_hi[i] = *(ushort_t*)&h;
            g_w2_lo[i] = *(ushort_t*)&lb;
        }
    } else {
        const int n = blk - 3840;
        for (int m = tid; m < N_; m += 256) {
            int idx = rel_index[n * N_ + m];
            float4 t = *reinterpret_cast<const float4*>(table + idx * 4);
            __nv_bfloat16 b0 = __float2bfloat16(t.x);
            __nv_bfloat16 b1 = __float2bfloat16(t.y);
            __nv_bfloat16 b2 = __float2bfloat16(t.z);
            __nv_bfloat16 b3 = __float2bfloat16(t.w);
            g_bias4[(0 * N_ + n) * N_ + m] = *(ushort_t*)&b0;
            g_bias4[(1 * N_ + n) * N_ + m] = *(ushort_t*)&b1;
            g_bias4[(2 * N_ + n) * N_ + m] = *(ushort_t*)&b2;
            g_bias4[(3 * N_ + n) * N_ + m] = *(ushort_t*)&b3;
        }
    }
}

// =====================================================================
// conv3x3 as bf16x3 tensor-core GEMM (unchanged from R8/R9 best)
// =====================================================================
__global__ __launch_bounds__(256, 2) void conv_mma_kernel()
{
    __shared__ __align__(16) ushort_t a_sm[2][128*104];   // 53248 B
    __shared__ __align__(16) ushort_t b_sm[2][2*136*24];  // 26112 B

    const int sp = blockIdx.x, b = blockIdx.y, p = blockIdx.z;
    const int tid = threadIdx.x, lane = tid & 31, wid = tid >> 5;
    const int wm = wid & 1, wn = wid >> 1;
    const int r0 = sp * 4;
    const int n0 = sp * 128;

    const __nv_bfloat16* whi = g_w_hi[p];
    const __nv_bfloat16* wlo = g_w_lo[p];
    const ushort_t* xh = g_xpad_hi + (size_t)b * (1360*128);
    const ushort_t* xl = g_xpad_lo + (size_t)b * (1360*128);

    float acc[4][4][4];
#pragma unroll
    for (int mi = 0; mi < 4; mi++)
#pragma unroll
        for (int ni = 0; ni < 4; ni++)
#pragma unroll
            for (int j = 0; j < 4; j++) acc[mi][ni][j] = 0.f;

    const int m_idx = lane >> 3;
    const int row_in = lane & 7;
    int aoff[4];
#pragma unroll
    for (int mi = 0; mi < 4; mi++)
        aoff[mi] = (wm*64 + mi*16 + (lane & 15))*104 + (lane >> 4)*8;
    int boff[2];
#pragma unroll
    for (int tp = 0; tp < 2; tp++) {
        int tile = tp*2 + (m_idx >> 1);
        int n = wn*32 + tile*8 + row_in;
        int rr = n >> 5, cc = n & 31;
        boff[tp] = (rr*34 + cc)*24 + (m_idx & 1)*8;
    }

    int bsrc[3], bdst[3];
    unsigned bflag[3];
#pragma unroll
    for (int it = 0; it < 3; it++) {
        int u = tid + it*256;
        int valid = (u < 544);
        int uu = valid ? u : 0;
        int half = uu & 1;
        int idx  = uu >> 1;
        int pc = idx % 34;
        int t  = idx / 34;
        int r  = t & 3;
        int split = t >> 2;
        bsrc[it] = ((r0 + r)*40 + pc)*128 + half*8;
        bdst[it] = (split*136 + r*34 + pc)*24 + half*8;
        bflag[it] = valid | (split << 1);
    }

    auto stage = [&](int s, int bufi) {
        int ky = s >> 3, ci0 = (s & 7) << 4;
        for (int u = tid; u < 1536; u += 256) {
            int half = u & 1;
            int co   = (u >> 1) & 127;
            int sk   = u >> 8;
            int split = (sk >= 3), kx = split ? sk - 3 : sk;
            const __nv_bfloat16* src = (split ? wlo : whi)
                + ((ky*3 + kx)*128 + co)*128 + ci0 + half*8;
            cp_async16(&a_sm[bufi][co*104 + sk*16 + half*8], src);
        }
        int badd = ky*5120 + ci0;
#pragma unroll
        for (int it = 0; it < 3; it++) {
            if (bflag[it] & 1) {
                const ushort_t* base = (bflag[it] & 2) ? xl : xh;
                cp_async16(&b_sm[bufi][bdst[it]], base + bsrc[it] + badd);
            }
        }
        cp_async_commit();
    };

    stage(0, 0);
    for (int s = 0; s < 24; s++) {
        const int buf = s & 1;
        if (s + 1 < 24) { stage(s + 1, buf ^ 1); cp_async_wait1(); }
        else            { cp_async_wait0(); }
        __syncthreads();

        const ushort_t* ab = a_sm[buf];
        const ushort_t* bb = b_sm[buf];
#pragma unroll
        for (int kx = 0; kx < 3; kx++) {
            unsigned bf[4][2], Af[4][4];
            {
                unsigned t4[4];
                ldmatrix_x4(t4, bb + boff[0] + kx*24);
                bf[0][0]=t4[0]; bf[0][1]=t4[1]; bf[1][0]=t4[2]; bf[1][1]=t4[3];
                ldmatrix_x4(t4, bb + boff[1] + kx*24);
                bf[2][0]=t4[0]; bf[2][1]=t4[1]; bf[3][0]=t4[2]; bf[3][1]=t4[3];
            }
#pragma unroll
            for (int mi = 0; mi < 4; mi++)
                ldmatrix_x4(Af[mi], ab + aoff[mi] + kx*16);
#pragma unroll
            for (int ni = 0; ni < 4; ni++)
#pragma unroll
                for (int mi = 0; mi < 4; mi++)
                    mma_bf16(acc[mi][ni], Af[mi], bf[ni][0], bf[ni][1]);
            unsigned bl[4][2];
            {
                unsigned t4[4];
                ldmatrix_x4(t4, bb + 136*24 + boff[0] + kx*24);
                bl[0][0]=t4[0]; bl[0][1]=t4[1]; bl[1][0]=t4[2]; bl[1][1]=t4[3];
                ldmatrix_x4(t4, bb + 136*24 + boff[1] + kx*24);
                bl[2][0]=t4[0]; bl[2][1]=t4[1]; bl[3][0]=t4[2]; bl[3][1]=t4[3];
            }
#pragma unroll
            for (int ni = 0; ni < 4; ni++)
#pragma unroll
                for (int mi = 0; mi < 4; mi++)
                    mma_bf16(acc[mi][ni], Af[mi], bl[ni][0], bl[ni][1]);
#pragma unroll
            for (int mi = 0; mi < 4; mi++)
                ldmatrix_x4(Af[mi], ab + aoff[mi] + (3 + kx)*16);
#pragma unroll
            for (int ni = 0; ni < 4; ni++)
#pragma unroll
                for (int mi = 0; mi < 4; mi++)
                    mma_bf16(acc[mi][ni], Af[mi], bf[ni][0], bf[ni][1]);
        }
        __syncthreads();
    }

    float s1 = 0.f, s2 = 0.f;
    float* outb = &g_conv[p][(size_t)b * CN];
#pragma unroll
    for (int mi = 0; mi < 4; mi++) {
        int row = wm*64 + mi*16 + (lane >> 2);
#pragma unroll
        for (int ni = 0; ni < 4; ni++) {
            int col = n0 + wn*32 + ni*8 + (lane & 3)*2;
            float2 v0; v0.x = acc[mi][ni][0]; v0.y = acc[mi][ni][1];
            float2 v1; v1.x = acc[mi][ni][2]; v1.y = acc[mi][ni][3];
            *reinterpret_cast<float2*>(&outb[(size_t)row*1024 + col])     = v0;
            *reinterpret_cast<float2*>(&outb[(size_t)(row+8)*1024 + col]) = v1;
#pragma unroll
            for (int j = 0; j < 4; j++) {
                float v = acc[mi][ni][j];
                s1 += v; s2 = fmaf(v, v, s2);
            }
        }
    }
    float* red = reinterpret_cast<float*>(b_sm);
    red[tid] = s1; red[256 + tid] = s2;
    __syncthreads();
    for (int st = 128; st > 0; st >>= 1) {
        if (tid < st) { red[tid] += red[tid + st]; red[256 + tid] += red[256 + tid + st]; }
        __syncthreads();
    }
    if (tid == 0) {
        int slot = (p*16 + b)*8 + sp;
        g_part2[slot][0] = red[0];
        g_part2[slot][1] = red[256];
    }
}

// =====================================================================
// GroupNorm apply (inline finalize) + exact GELU -> bf16 hi/lo operands
// =====================================================================
__global__ __launch_bounds__(256) void norm_gelu_kernel(
    const float* __restrict__ gq, const float* __restrict__ bq,
    const float* __restrict__ gk, const float* __restrict__ bk,
    const float* __restrict__ gv, const float* __restrict__ bv)
{
    const int pb = blockIdx.z;
    const int p = pb >> 4, b = pb & 15;
    const int h = blockIdx.y;
    const int n0 = blockIdx.x * 64;
    const int tid = threadIdx.x;
    const int bhid = b*4 + h;

    const float* gamma = (p == 0) ? gq : (p == 1) ? gk : gv;
    const float* beta  = (p == 0) ? bq : (p == 1) ? bk : bv;

    float sa = 0.f, sb = 0.f;
#pragma unroll
    for (int i = 0; i < 8; i++) {
        sa += g_part2[pb*8 + i][0];
        sb += g_part2[pb*8 + i][1];
    }
    const float mean = sa / (float)CN;
    const float rstd = rsqrtf(sb / (float)CN - mean*mean + 1e-6f);

    __shared__ float s[32][65];
    const float* src = g_conv[p] + ((size_t)b * 128 + h * 32) * N_;

    if (p == 2) {
        for (int e = tid; e < 2048; e += 256) {
            int d = e >> 6, nn = e & 63;
            float v = src[(size_t)d * N_ + n0 + nn];
            int c = h * 32 + d;
            v = (v - mean) * rstd * gamma[c] + beta[c];
            v = 0.5f * v * (1.0f + erff(v * 0.70710678118654752f));
            __nv_bfloat16 hb = __float2bfloat16(v);
            float lov = v - __bfloat162float(hb);
            __nv_bfloat16 lb = __float2bfloat16(lov);
            size_t idx = ((size_t)bhid*32 + d)*1024 + n0 + nn;
            g_v_hi[idx] = *(ushort_t*)&hb;
            g_v_lo[idx] = *(ushort_t*)&lb;
        }
    } else {
        for (int e = tid; e < 2048; e += 256) {
            int d = e >> 6, nn = e & 63;
            float v = src[(size_t)d * N_ + n0 + nn];
            int c = h * 32 + d;
            v = (v - mean) * rstd * gamma[c] + beta[c];
            v = 0.5f * v * (1.0f + erff(v * 0.70710678118654752f));
            s[d][nn] = v;
        }
        __syncthreads();
        ushort_t* dhi = (p == 0) ? g_q_hi : g_k_hi;
        ushort_t* dlo = (p == 0) ? g_q_lo : g_k_lo;
        for (int e = tid; e < 2048; e += 256) {
            int nn = e >> 5, d = e & 31;
            float v = s[d][nn];
            __nv_bfloat16 hb = __float2bfloat16(v);
            float lov = v - __bfloat162float(hb);
            __nv_bfloat16 lb = __float2bfloat16(lov);
            size_t idx = ((size_t)bhid*1024 + n0 + nn)*32 + d;
            dhi[idx] = *(ushort_t*)&hb;
            dlo[idx] = *(ushort_t*)&lb;
        }
    }
}

// =====================================================================
// Attention v4: 4 warps x 32 q-rows (halved LDSM bytes), 128 threads.
// =====================================================================
__global__ __launch_bounds__(128, 2) void attn_mma_kernel()
{
    __shared__ __align__(16) ushort_t q_sm[2][128][40];      // 20480 B
    __shared__ __align__(16) ushort_t k_sm[2][2][64][40];    // 20480 B
    __shared__ __align__(16) ushort_t v_sm[2][2][32][72];    // 18432 B

    const int tid = threadIdx.x, lane = tid & 31, w = tid >> 5;   // w 0..3
    const int qt = blockIdx.x, bh = blockIdx.y;
    const int b = bh >> 2, h = bh & 3;

    auto stage_kv = [&](int kc, int bufi) {
        const int m0 = kc * 64;
        for (int u = tid; u < 512; u += 128) {
            int quarter = u & 3, row = (u >> 2) & 63, split = u >> 8;
            const ushort_t* src = (split ? g_k_lo : g_k_hi)
                + ((size_t)bh*1024 + m0 + row)*32 + quarter*8;
            cp_async16(&k_sm[bufi][split][row][quarter*8], src);
        }
        for (int u = tid; u < 512; u += 128) {
            int seg = u & 7, d = (u >> 3) & 31, split = u >> 8;
            const ushort_t* src = (split ? g_v_lo : g_v_hi)
                + ((size_t)bh*32 + d)*1024 + m0 + seg*8;
            cp_async16(&v_sm[bufi][split][d][seg*8], src);
        }
        cp_async_commit();
    };

    for (int u = tid; u < 1024; u += 128) {
        int quarter = u & 3, row = (u >> 2) & 127, split = u >> 9;
        const ushort_t* src = (split ? g_q_lo : g_q_hi)
            + ((size_t)bh*1024 + qt*128 + row)*32 + quarter*8;
        *reinterpret_cast<uint4*>(&q_sm[split][row][quarter*8]) =
            *reinterpret_cast<const uint4*>(src);
    }
    stage_kv(0, 0);
    __syncthreads();

    // Q fragments: 2 m-tiles of 16 rows each (warp owns 32 rows)
    unsigned qh[2][2][4], ql[2][2][4];
#pragma unroll
    for (int kit = 0; kit < 2; kit++)
#pragma unroll
        for (int mt = 0; mt < 2; mt++) {
            ldmatrix_x4(qh[kit][mt],
                &q_sm[0][w*32 + mt*16 + (lane & 15)][kit*16 + (lane >> 4)*8]);
            ldmatrix_x4(ql[kit][mt],
                &q_sm[1][w*32 + mt*16 + (lane & 15)][kit*16 + (lane >> 4)*8]);
        }

    const int m_idx = lane >> 3;
    const int row_in = lane & 7;
    int koff[4], voff[2];
#pragma unroll
    for (int tp = 0; tp < 4; tp++)
        koff[tp] = ((tp*2 + (m_idx >> 1))*8 + row_in)*40 + (m_idx & 1)*8;
#pragma unroll
    for (int tp = 0; tp < 2; tp++)
        voff[tp] = ((tp*2 + (m_idx >> 1))*8 + row_in)*72 + (m_idx & 1)*8;

    float O[2][4][4];
#pragma unroll
    for (int mt = 0; mt < 2; mt++)
#pragma unroll
        for (int nd = 0; nd < 4; nd++)
#pragma unroll
            for (int j = 0; j < 4; j++) O[mt][nd][j] = 0.f;
    float mr[2][2], lr[2][2];
#pragma unroll
    for (int mt = 0; mt < 2; mt++) {
        mr[mt][0] = -INFINITY; mr[mt][1] = -INFINITY;
        lr[mt][0] = 0.f; lr[mt][1] = 0.f;
    }

    int qrow0[2];
    const ushort_t* biasbase[2];
#pragma unroll
    for (int mt = 0; mt < 2; mt++) {
        qrow0[mt] = qt*128 + w*32 + mt*16 + (lane >> 2);
        biasbase[mt] = g_bias4 + ((size_t)h*1024 + qrow0[mt])*1024 + 2*(lane & 3);
    }

    for (int kc = 0; kc < 16; kc++) {
        const int m0 = kc * 64;
        const int buf = kc & 1;
        if (kc + 1 < 16) { stage_kv(kc + 1, buf ^ 1); cp_async_wait1(); }
        else             { cp_async_wait0(); }
        __syncthreads();

        const ushort_t* kb0 = &k_sm[buf][0][0][0];
        const ushort_t* kb1 = kb0 + 64*40;
        const ushort_t* vb0 = &v_sm[buf][0][0][0];
        const ushort_t* vb1 = vb0 + 32*72;

        // ---- S = Q K^T (3-term hi/lo), 2 m-tiles ----
        float c[2][8][4];
#pragma unroll
        for (int mt = 0; mt < 2; mt++)
#pragma unroll
            for (int ni = 0; ni < 8; ni++)
#pragma unroll
                for (int j = 0; j < 4; j++) c[mt][ni][j] = 0.f;

#pragma unroll
        for (int kit = 0; kit < 2; kit++) {
            unsigned kb[8][2];
#pragma unroll
            for (int tp = 0; tp < 4; tp++) {
                unsigned t4[4];
                ldmatrix_x4(t4, kb0 + koff[tp] + kit*16);
                kb[tp*2][0]=t4[0]; kb[tp*2][1]=t4[1];
                kb[tp*2+1][0]=t4[2]; kb[tp*2+1][1]=t4[3];
            }
#pragma unroll
            for (int ni = 0; ni < 8; ni++)
#pragma unroll
                for (int mt = 0; mt < 2; mt++) {
                    mma_bf16(c[mt][ni], qh[kit][mt], kb[ni][0], kb[ni][1]);
                    mma_bf16(c[mt][ni], ql[kit][mt], kb[ni][0], kb[ni][1]);
                }
#pragma unroll
            for (int tp = 0; tp < 4; tp++) {
                unsigned t4[4];
                ldmatrix_x4(t4, kb1 + koff[tp] + kit*16);
                kb[tp*2][0]=t4[0]; kb[tp*2][1]=t4[1];
                kb[tp*2+1][0]=t4[2]; kb[tp*2+1][1]=t4[3];
            }
#pragma unroll
            for (int ni = 0; ni < 8; ni++)
#pragma unroll
                for (int mt = 0; mt < 2; mt++)
                    mma_bf16(c[mt][ni], qh[kit][mt], kb[ni][0], kb[ni][1]);
        }

        // ---- bias (bf16) + online softmax per m-tile ----
#pragma unroll
        for (int mt = 0; mt < 2; mt++) {
            const ushort_t* b0p = biasbase[mt] + m0;
            const ushort_t* b1p = b0p + 8*1024;
            float rm0 = -INFINITY, rm1 = -INFINITY;
#pragma unroll
            for (int ni = 0; ni < 8; ni++) {
                unsigned u0 = *reinterpret_cast<const unsigned*>(b0p + ni*8);
                unsigned u1 = *reinterpret_cast<const unsigned*>(b1p + ni*8);
                c[mt][ni][0] += lowerf(u0); c[mt][ni][1] += upperf(u0);
                c[mt][ni][2] += lowerf(u1); c[mt][ni][3] += upperf(u1);
                rm0 = fmaxf(rm0, fmaxf(c[mt][ni][0], c[mt][ni][1]));
                rm1 = fmaxf(rm1, fmaxf(c[mt][ni][2], c[mt][ni][3]));
            }
            rm0 = fmaxf(rm0, __shfl_xor_sync(0xffffffffu, rm0, 1));
            rm0 = fmaxf(rm0, __shfl_xor_sync(0xffffffffu, rm0, 2));
            rm1 = fmaxf(rm1, __shfl_xor_sync(0xffffffffu, rm1, 1));
            rm1 = fmaxf(rm1, __shfl_xor_sync(0xffffffffu, rm1, 2));
            float mnew0 = fmaxf(mr[mt][0], rm0), mnew1 = fmaxf(mr[mt][1], rm1);
            float corr0 = __expf(mr[mt][0] - mnew0), corr1 = __expf(mr[mt][1] - mnew1);
            mr[mt][0] = mnew0; mr[mt][1] = mnew1;
            float rs0 = 0.f, rs1 = 0.f;
#pragma unroll
            for (int ni = 0; ni < 8; ni++) {
                c[mt][ni][0] = __expf(c[mt][ni][0] - mnew0);
                c[mt][ni][1] = __expf(c[mt][ni][1] - mnew0);
                c[mt][ni][2] = __expf(c[mt][ni][2] - mnew1);
                c[mt][ni][3] = __expf(c[mt][ni][3] - mnew1);
                rs0 += c[mt][ni][0] + c[mt][ni][1];
                rs1 += c[mt][ni][2] + c[mt][ni][3];
            }
            rs0 += __shfl_xor_sync(0xffffffffu, rs0, 1);
            rs0 += __shfl_xor_sync(0xffffffffu, rs0, 2);
            rs1 += __shfl_xor_sync(0xffffffffu, rs1, 1);
            rs1 += __shfl_xor_sync(0xffffffffu, rs1, 2);
            lr[mt][0] = lr[mt][0] * corr0 + rs0;
            lr[mt][1] = lr[mt][1] * corr1 + rs1;
#pragma unroll
            for (int nd = 0; nd < 4; nd++) {
                O[mt][nd][0] *= corr0; O[mt][nd][1] *= corr0;
                O[mt][nd][2] *= corr1; O[mt][nd][3] *= corr1;
            }
        }

        // ---- PV (3-term) ----
#pragma unroll
        for (int t = 0; t < 4; t++) {
            int j0 = 2*t, j1 = 2*t + 1;
            unsigned ph[2][4], pl[2][4];
#pragma unroll
            for (int mt = 0; mt < 2; mt++) {
                ph[mt][0] = packbf(c[mt][j0][1], c[mt][j0][0]);
                ph[mt][1] = packbf(c[mt][j0][3], c[mt][j0][2]);
                ph[mt][2] = packbf(c[mt][j1][1], c[mt][j1][0]);
                ph[mt][3] = packbf(c[mt][j1][3], c[mt][j1][2]);
                pl[mt][0] = packbf(c[mt][j0][1] - upperf(ph[mt][0]), c[mt][j0][0] - lowerf(ph[mt][0]));
                pl[mt][1] = packbf(c[mt][j0][3] - upperf(ph[mt][1]), c[mt][j0][2] - lowerf(ph[mt][1]));
                pl[mt][2] = packbf(c[mt][j1][1] - upperf(ph[mt][2]), c[mt][j1][0] - lowerf(ph[mt][2]));
                pl[mt][3] = packbf(c[mt][j1][3] - upperf(ph[mt][3]), c[mt][j1][2] - lowerf(ph[mt][3]));
            }

            unsigned vb[4][2];
#pragma unroll
            for (int tp = 0; tp < 2; tp++) {
                unsigned t4[4];
                ldmatrix_x4(t4, vb0 + voff[tp] + t*16);
                vb[tp*2][0]=t4[0]; vb[tp*2][1]=t4[1];
                vb[tp*2+1][0]=t4[2]; vb[tp*2+1][1]=t4[3];
            }
#pragma unroll
            for (int nd = 0; nd < 4; nd++)
#pragma unroll
                for (int mt = 0; mt < 2; mt++) {
                    mma_bf16(O[mt][nd], ph[mt], vb[nd][0], vb[nd][1]);
                    mma_bf16(O[mt][nd], pl[mt], vb[nd][0], vb[nd][1]);
                }
#pragma unroll
            for (int tp = 0; tp < 2; tp++) {
                unsigned t4[4];
                ldmatrix_x4(t4, vb1 + voff[tp] + t*16);
                vb[tp*2][0]=t4[0]; vb[tp*2][1]=t4[1];
                vb[tp*2+1][0]=t4[2]; vb[tp*2+1][1]=t4[3];
            }
#pragma unroll
            for (int nd = 0; nd < 4; nd++)
#pragma unroll
                for (int mt = 0; mt < 2; mt++)
                    mma_bf16(O[mt][nd], ph[mt], vb[nd][0], vb[nd][1]);
        }
        __syncthreads();
    }

    // epilogue: bf16 hi/lo split output [b][n][c]
#pragma unroll
    for (int mt = 0; mt < 2; mt++) {
        float il0 = 1.f / lr[mt][0], il1 = 1.f / lr[mt][1];
        const size_t base0 = ((size_t)b*1024 + qrow0[mt])*128 + h*32 + 2*(lane & 3);
        const size_t base1 = base0 + 8*128;
#pragma unroll
        for (int nd = 0; nd < 4; nd++) {
            float a0 = O[mt][nd][0]*il0, a1 = O[mt][nd][1]*il0;
            float b0 = O[mt][nd][2]*il1, b1 = O[mt][nd][3]*il1;
            unsigned h0 = packbf(a1, a0);
            unsigned l0 = packbf(a1 - upperf(h0), a0 - lowerf(h0));
            unsigned h1 = packbf(b1, b0);
            unsigned l1 = packbf(b1 - upperf(h1), b0 - lowerf(h1));
            *reinterpret_cast<unsigned*>(&g_ao_hi[base0 + nd*8]) = h0;
            *reinterpret_cast<unsigned*>(&g_ao_lo[base0 + nd*8]) = l0;
            *reinterpret_cast<unsigned*>(&g_ao_hi[base1 + nd*8]) = h1;
            *reinterpret_cast<unsigned*>(&g_ao_lo[base1 + nd*8]) = l1;
        }
    }
}

// =====================================================================
// 1x1 conv via tensor cores (bf16x3), + bias.
// =====================================================================
__global__ __launch_bounds__(256, 2) void outconv_mma_kernel(
    const float* __restrict__ bias, float* __restrict__ out)
{
    __shared__ __align__(16) ushort_t a_sm[2][128*40];
    __shared__ __align__(16) ushort_t b_sm[2][128*40];

    const int bx = blockIdx.x, b = blockIdx.y;
    const int n0 = bx * 128;
    const int tid = threadIdx.x, lane = tid & 31, wid = tid >> 5;
    const int wm = wid & 1, wn = wid >> 1;
    const int m_idx = lane >> 3;
    const int row_in = lane & 7;

    float acc[4][4][4];
#pragma unroll
    for (int mi = 0; mi < 4; mi++)
#pragma unroll
        for (int ni = 0; ni < 4; ni++)
#pragma unroll
            for (int j = 0; j < 4; j++) acc[mi][ni][j] = 0.f;

    int aoff[4];
#pragma unroll
    for (int mi = 0; mi < 4; mi++)
        aoff[mi] = (wm*64 + mi*16 + (lane & 15))*40 + (lane >> 4)*8;
    int boff[2];
#pragma unroll
    for (int tp = 0; tp < 2; tp++) {
        int tile = tp*2 + (m_idx >> 1);
        int n = wn*32 + tile*8 + row_in;
        boff[tp] = n*40 + (m_idx & 1)*8;
    }

    auto stage = [&](int ck, int bufi) {
        int c0 = ck * 16;
        for (int u = tid; u < 512; u += 256) {
            int half = u & 1, co = (u >> 1) & 127, split = u >> 8;
            const ushort_t* src = (split ? g_w2_lo : g_w2_hi) + co*128 + c0 + half*8;
            cp_async16(&a_sm[bufi][co*40 + split*16 + half*8], src);
        }
        for (int u = tid; u < 512; u += 256) {
            int half = u & 1, n = (u >> 1) & 127, split = u >> 8;
            const ushort_t* src = (split ? g_ao_lo : g_ao_hi)
                + ((size_t)b*1024 + n0 + n)*128 + c0 + half*8;
            cp_async16(&b_sm[bufi][n*40 + split*16 + half*8], src);
        }
        cp_async_commit();
    };

    stage(0, 0);
    for (int ck = 0; ck < 8; ck++) {
        const int buf = ck & 1;
        if (ck + 1 < 8) { stage(ck + 1, buf ^ 1); cp_async_wait1(); }
        else            { cp_async_wait0(); }
        __syncthreads();

        const ushort_t* ab = a_sm[buf];
        const ushort_t* bb = b_sm[buf];

        unsigned Ah[4][4], bf[4][2], bl[4][2];
#pragma unroll
        for (int mi = 0; mi < 4; mi++)
            ldmatrix_x4(Ah[mi], ab + aoff[mi]);
        {
            unsigned t4[4];
            ldmatrix_x4(t4, bb + boff[0]);
            bf[0][0]=t4[0]; bf[0][1]=t4[1]; bf[1][0]=t4[2]; bf[1][1]=t4[3];
            ldmatrix_x4(t4, bb + boff[1]);
            bf[2][0]=t4[0]; bf[2][1]=t4[1]; bf[3][0]=t4[2]; bf[3][1]=t4[3];
            ldmatrix_x4(t4, bb + boff[0] + 16);
            bl[0][0]=t4[0]; bl[0][1]=t4[1]; bl[1][0]=t4[2]; bl[1][1]=t4[3];
            ldmatrix_x4(t4, bb + boff[1] + 16);
            bl[2][0]=t4[0]; bl[2][1]=t4[1]; bl[3][0]=t4[2]; bl[3][1]=t4[3];
        }
#pragma unroll
        for (int ni = 0; ni < 4; ni++)
#pragma unroll
            for (int mi = 0; mi < 4; mi++) {
                mma_bf16(acc[mi][ni], Ah[mi], bf[ni][0], bf[ni][1]);
                mma_bf16(acc[mi][ni], Ah[mi], bl[ni][0], bl[ni][1]);
            }
#pragma unroll
        for (int mi = 0; mi < 4; mi++)
            ldmatrix_x4(Ah[mi], ab + aoff[mi] + 16);
#pragma unroll
        for (int ni = 0; ni < 4; ni++)
#pragma unroll
            for (int mi = 0; mi < 4; mi++)
                mma_bf16(acc[mi][ni], Ah[mi], bf[ni][0], bf[ni][1]);
        __syncthreads();
    }

#pragma unroll
    for (int mi = 0; mi < 4; mi++) {
        int row = wm*64 + mi*16 + (lane >> 2);
        float bv0 = bias[row], bv1 = bias[row + 8];
#pragma unroll
        for (int ni = 0; ni < 4; ni++) {
            int col = n0 + wn*32 + ni*8 + (lane & 3)*2;
            float2 v0; v0.x = acc[mi][ni][0] + bv0; v0.y = acc[mi][ni][1] + bv0;
            float2 v1; v1.x = acc[mi][ni][2] + bv1; v1.y = acc[mi][ni][3] + bv1;
            *reinterpret_cast<float2*>(&out[((size_t)b*128 + row)*1024 + col])     = v0;
            *reinterpret_cast<float2*>(&out[((size_t)b*128 + row + 8)*1024 + col]) = v1;
        }
    }
}

// =====================================================================
extern "C" void kernel_launch(void* const* d_in, const int* in_sizes, int n_in,
                              void* d_out, int out_size)
{
    const float* x      = (const float*)d_in[0];
    const float* wq     = (const float*)d_in[1];
    const float* gq     = (const float*)d_in[2];
    const float* bq     = (const float*)d_in[3];
    const float* wk     = (const float*)d_in[4];
    const float* gk     = (const float*)d_in[5];
    const float* bk     = (const float*)d_in[6];
    const float* wv     = (const float*)d_in[7];
    const float* gv     = (const float*)d_in[8];
    const float* bv     = (const float*)d_in[9];
    const float* table  = (const float*)d_in[10];
    const int*   relidx = (const int*)  d_in[11];
    const float* out_w  = (const float*)d_in[12];
    const float* out_b  = (const float*)d_in[13];
    float* out = (float*)d_out;

    prep_all_kernel<<<4864, 256>>>(x, wq, wk, wv, out_w, table, relidx); // 0
    conv_mma_kernel<<<dim3(8, 16, 3), 256>>>();                          // 1
    norm_gelu_kernel<<<dim3(16, 4, 48), 256>>>(gq, bq, gk, bk, gv, bv);  // 2
    attn_mma_kernel<<<dim3(8, 64), 128>>>();                             // 3  <- profiled
    outconv_mma_kernel<<<dim3(8, 16), 256>>>(out_b, out);                // 4
}

// round 11
// speedup vs baseline: 5.5053x; 1.0258x over previous
#include <cuda_runtime.h>
#include <cuda_bf16.h>
#include <math.h>

#define B_   16
#define C_   128
#define N_   1024
#define H_   4
#define D_   32
#define CN   (C_*N_)
#define LOG2E 1.4426950408889634f

typedef unsigned short ushort_t;

// ---------------- scratch (device globals; no allocations) ----------------
__device__ float g_conv[3][B_*CN];        // conv outputs, [p][b][c][n]
__device__ float g_part2[384][2];         // conv-block partial sums
__device__ ushort_t g_bias4[H_*N_*N_];    // [h][n][m]  (bf16 bits, pre-scaled by log2e)

// padded input, transposed: [b][sp_pad(34*40)][ci(128)], hi/lo bf16 bits
__device__ __align__(16) ushort_t g_xpad_hi[B_*34*40*C_];
__device__ __align__(16) ushort_t g_xpad_lo[B_*34*40*C_];
// weights: [p][((ky*3+kx)*128+co)*128+ci]
__device__ __align__(16) __nv_bfloat16 g_w_hi[3][9*128*128];
__device__ __align__(16) __nv_bfloat16 g_w_lo[3][9*128*128];
// out_w split: [co][ci]
__device__ __align__(16) ushort_t g_w2_hi[128*128];
__device__ __align__(16) ushort_t g_w2_lo[128*128];

// attention operands (bf16 bits, hi/lo split).  Q pre-scaled by log2e.
__device__ __align__(16) ushort_t g_q_hi[64*N_*D_];   // [bh][n][d]
__device__ __align__(16) ushort_t g_q_lo[64*N_*D_];
__device__ __align__(16) ushort_t g_k_hi[64*N_*D_];   // [bh][n][d]
__device__ __align__(16) ushort_t g_k_lo[64*N_*D_];
__device__ __align__(16) ushort_t g_v_hi[64*D_*N_];   // [bh][d][n]  (transposed)
__device__ __align__(16) ushort_t g_v_lo[64*D_*N_];
// attention output, bf16 hi/lo: [b][n][c]
__device__ __align__(16) ushort_t g_ao_hi[B_*N_*C_];
__device__ __align__(16) ushort_t g_ao_lo[B_*N_*C_];

// =====================================================================
// helpers
// =====================================================================
__device__ __forceinline__ void mma_bf16(float* d, const unsigned* A,
                                         unsigned b0, unsigned b1)
{
    asm volatile(
        "mma.sync.aligned.m16n8k16.row.col.f32.bf16.bf16.f32 "
        "{%0,%1,%2,%3},{%4,%5,%6,%7},{%8,%9},{%0,%1,%2,%3};"
        : "+f"(d[0]), "+f"(d[1]), "+f"(d[2]), "+f"(d[3])
        : "r"(A[0]), "r"(A[1]), "r"(A[2]), "r"(A[3]), "r"(b0), "r"(b1));
}

__device__ __forceinline__ void ldmatrix_x4(unsigned* r, const ushort_t* p)
{
    unsigned addr = (unsigned)__cvta_generic_to_shared((void*)p);
    asm volatile("ldmatrix.sync.aligned.m8n8.x4.shared.b16 {%0,%1,%2,%3}, [%4];"
        : "=r"(r[0]), "=r"(r[1]), "=r"(r[2]), "=r"(r[3]) : "r"(addr));
}

__device__ __forceinline__ void cp_async16(void* smem, const void* gmem)
{
    unsigned s = (unsigned)__cvta_generic_to_shared(smem);
    asm volatile("cp.async.cg.shared.global [%0], [%1], 16;" :: "r"(s), "l"(gmem));
}
__device__ __forceinline__ void cp_async_commit(){ asm volatile("cp.async.commit_group;"); }
__device__ __forceinline__ void cp_async_wait0(){ asm volatile("cp.async.wait_group 0;" ::: "memory"); }
__device__ __forceinline__ void cp_async_wait1(){ asm volatile("cp.async.wait_group 1;" ::: "memory"); }

__device__ __forceinline__ unsigned packbf(float hi_elem, float lo_elem)
{
    unsigned d;
    asm("cvt.rn.bf16x2.f32 %0, %1, %2;" : "=r"(d) : "f"(hi_elem), "f"(lo_elem));
    return d;
}
__device__ __forceinline__ float upperf(unsigned u){ return __uint_as_float(u & 0xffff0000u); }
__device__ __forceinline__ float lowerf(unsigned u){ return __uint_as_float(u << 16); }
__device__ __forceinline__ float ex2(float x)
{
    float r;
    asm("ex2.approx.ftz.f32 %0, %1;" : "=f"(r) : "f"(x));
    return r;
}

// =====================================================================
// prep_all
// =====================================================================
__global__ __launch_bounds__(256) void prep_all_kernel(
    const float* __restrict__ x,
    const float* __restrict__ wq, const float* __restrict__ wk,
    const float* __restrict__ wv, const float* __restrict__ w2,
    const float* __restrict__ table, const int* __restrict__ rel_index)
{
    const int blk = blockIdx.x;
    const int tid = threadIdx.x;

    if (blk < 2048) {
        const int total = B_*1360*128;
        for (int e = blk*256 + tid; e < total; e += 2048*256) {
            int ci = e & 127;
            int t  = e >> 7;
            int sp = t % 1360;
            int b  = t / 1360;
            int yy = sp / 40, xx = sp % 40;
            int y = yy - 1, c = xx - 1;
            float v = 0.f;
            if ((unsigned)y < 32u && (unsigned)c < 32u)
                v = x[((size_t)b*128 + ci)*1024 + y*32 + c];
            __nv_bfloat16 hb = __float2bfloat16(v);
            float lov = v - __bfloat162float(hb);
            __nv_bfloat16 lb = __float2bfloat16(lov);
            g_xpad_hi[e] = *(ushort_t*)&hb;
            g_xpad_lo[e] = *(ushort_t*)&lb;
        }
    } else if (blk < 3776) {
        int e = (blk - 2048)*256 + tid;
        if (e < 3*128*128*9) {
            int kx = e % 3; int t = e / 3;
            int ky = t % 3; t /= 3;
            int ci = t % 128; t /= 128;
            int co = t % 128;
            int p  = t / 128;
            const float* w = (p == 0) ? wq : (p == 1) ? wk : wv;
            float v = w[((co*128 + ci)*3 + ky)*3 + kx];
            __nv_bfloat16 h = __float2bfloat16(v);
            float lo = v - __bfloat162float(h);
            int dst = ((ky*3 + kx)*128 + co)*128 + ci;
            g_w_hi[p][dst] = h;
            g_w_lo[p][dst] = __float2bfloat16(lo);
        }
    } else if (blk < 3840) {
        int i = (blk - 3776)*256 + tid;
        if (i < 16384) {
            float v = w2[i];
            __nv_bfloat16 h = __float2bfloat16(v);
            float lo = v - __bfloat162float(h);
            __nv_bfloat16 lb = __float2bfloat16(lo);
            g_w2_hi[i] = *(ushort_t*)&h;
            g_w2_lo[i] = *(ushort_t*)&lb;
        }
    } else {
        const int n = blk - 3840;
        for (int m = tid; m < N_; m += 256) {
            int idx = rel_index[n * N_ + m];
            float4 t = *reinterpret_cast<const float4*>(table + idx * 4);
            // pre-scale by log2e for exp2-domain softmax
            __nv_bfloat16 b0 = __float2bfloat16(t.x * LOG2E);
            __nv_bfloat16 b1 = __float2bfloat16(t.y * LOG2E);
            __nv_bfloat16 b2 = __float2bfloat16(t.z * LOG2E);
            __nv_bfloat16 b3 = __float2bfloat16(t.w * LOG2E);
            g_bias4[(0 * N_ + n) * N_ + m] = *(ushort_t*)&b0;
            g_bias4[(1 * N_ + n) * N_ + m] = *(ushort_t*)&b1;
            g_bias4[(2 * N_ + n) * N_ + m] = *(ushort_t*)&b2;
            g_bias4[(3 * N_ + n) * N_ + m] = *(ushort_t*)&b3;
        }
    }
}

// =====================================================================
// conv3x3 as bf16x3 tensor-core GEMM (unchanged)
// =====================================================================
__global__ __launch_bounds__(256, 2) void conv_mma_kernel()
{
    __shared__ __align__(16) ushort_t a_sm[2][128*104];   // 53248 B
    __shared__ __align__(16) ushort_t b_sm[2][2*136*24];  // 26112 B

    const int sp = blockIdx.x, b = blockIdx.y, p = blockIdx.z;
    const int tid = threadIdx.x, lane = tid & 31, wid = tid >> 5;
    const int wm = wid & 1, wn = wid >> 1;
    const int r0 = sp * 4;
    const int n0 = sp * 128;

    const __nv_bfloat16* whi = g_w_hi[p];
    const __nv_bfloat16* wlo = g_w_lo[p];
    const ushort_t* xh = g_xpad_hi + (size_t)b * (1360*128);
    const ushort_t* xl = g_xpad_lo + (size_t)b * (1360*128);

    float acc[4][4][4];
#pragma unroll
    for (int mi = 0; mi < 4; mi++)
#pragma unroll
        for (int ni = 0; ni < 4; ni++)
#pragma unroll
            for (int j = 0; j < 4; j++) acc[mi][ni][j] = 0.f;

    const int m_idx = lane >> 3;
    const int row_in = lane & 7;
    int aoff[4];
#pragma unroll
    for (int mi = 0; mi < 4; mi++)
        aoff[mi] = (wm*64 + mi*16 + (lane & 15))*104 + (lane >> 4)*8;
    int boff[2];
#pragma unroll
    for (int tp = 0; tp < 2; tp++) {
        int tile = tp*2 + (m_idx >> 1);
        int n = wn*32 + tile*8 + row_in;
        int rr = n >> 5, cc = n & 31;
        boff[tp] = (rr*34 + cc)*24 + (m_idx & 1)*8;
    }

    int bsrc[3], bdst[3];
    unsigned bflag[3];
#pragma unroll
    for (int it = 0; it < 3; it++) {
        int u = tid + it*256;
        int valid = (u < 544);
        int uu = valid ? u : 0;
        int half = uu & 1;
        int idx  = uu >> 1;
        int pc = idx % 34;
        int t  = idx / 34;
        int r  = t & 3;
        int split = t >> 2;
        bsrc[it] = ((r0 + r)*40 + pc)*128 + half*8;
        bdst[it] = (split*136 + r*34 + pc)*24 + half*8;
        bflag[it] = valid | (split << 1);
    }

    auto stage = [&](int s, int bufi) {
        int ky = s >> 3, ci0 = (s & 7) << 4;
        for (int u = tid; u < 1536; u += 256) {
            int half = u & 1;
            int co   = (u >> 1) & 127;
            int sk   = u >> 8;
            int split = (sk >= 3), kx = split ? sk - 3 : sk;
            const __nv_bfloat16* src = (split ? wlo : whi)
                + ((ky*3 + kx)*128 + co)*128 + ci0 + half*8;
            cp_async16(&a_sm[bufi][co*104 + sk*16 + half*8], src);
        }
        int badd = ky*5120 + ci0;
#pragma unroll
        for (int it = 0; it < 3; it++) {
            if (bflag[it] & 1) {
                const ushort_t* base = (bflag[it] & 2) ? xl : xh;
                cp_async16(&b_sm[bufi][bdst[it]], base + bsrc[it] + badd);
            }
        }
        cp_async_commit();
    };

    stage(0, 0);
    for (int s = 0; s < 24; s++) {
        const int buf = s & 1;
        if (s + 1 < 24) { stage(s + 1, buf ^ 1); cp_async_wait1(); }
        else            { cp_async_wait0(); }
        __syncthreads();

        const ushort_t* ab = a_sm[buf];
        const ushort_t* bb = b_sm[buf];
#pragma unroll
        for (int kx = 0; kx < 3; kx++) {
            unsigned bf[4][2], Af[4][4];
            {
                unsigned t4[4];
                ldmatrix_x4(t4, bb + boff[0] + kx*24);
                bf[0][0]=t4[0]; bf[0][1]=t4[1]; bf[1][0]=t4[2]; bf[1][1]=t4[3];
                ldmatrix_x4(t4, bb + boff[1] + kx*24);
                bf[2][0]=t4[0]; bf[2][1]=t4[1]; bf[3][0]=t4[2]; bf[3][1]=t4[3];
            }
#pragma unroll
            for (int mi = 0; mi < 4; mi++)
                ldmatrix_x4(Af[mi], ab + aoff[mi] + kx*16);
#pragma unroll
            for (int ni = 0; ni < 4; ni++)
#pragma unroll
                for (int mi = 0; mi < 4; mi++)
                    mma_bf16(acc[mi][ni], Af[mi], bf[ni][0], bf[ni][1]);
            unsigned bl[4][2];
            {
                unsigned t4[4];
                ldmatrix_x4(t4, bb + 136*24 + boff[0] + kx*24);
                bl[0][0]=t4[0]; bl[0][1]=t4[1]; bl[1][0]=t4[2]; bl[1][1]=t4[3];
                ldmatrix_x4(t4, bb + 136*24 + boff[1] + kx*24);
                bl[2][0]=t4[0]; bl[2][1]=t4[1]; bl[3][0]=t4[2]; bl[3][1]=t4[3];
            }
#pragma unroll
            for (int ni = 0; ni < 4; ni++)
#pragma unroll
                for (int mi = 0; mi < 4; mi++)
                    mma_bf16(acc[mi][ni], Af[mi], bl[ni][0], bl[ni][1]);
#pragma unroll
            for (int mi = 0; mi < 4; mi++)
                ldmatrix_x4(Af[mi], ab + aoff[mi] + (3 + kx)*16);
#pragma unroll
            for (int ni = 0; ni < 4; ni++)
#pragma unroll
                for (int mi = 0; mi < 4; mi++)
                    mma_bf16(acc[mi][ni], Af[mi], bf[ni][0], bf[ni][1]);
        }
        __syncthreads();
    }

    float s1 = 0.f, s2 = 0.f;
    float* outb = &g_conv[p][(size_t)b * CN];
#pragma unroll
    for (int mi = 0; mi < 4; mi++) {
        int row = wm*64 + mi*16 + (lane >> 2);
#pragma unroll
        for (int ni = 0; ni < 4; ni++) {
            int col = n0 + wn*32 + ni*8 + (lane & 3)*2;
            float2 v0; v0.x = acc[mi][ni][0]; v0.y = acc[mi][ni][1];
            float2 v1; v1.x = acc[mi][ni][2]; v1.y = acc[mi][ni][3];
            *reinterpret_cast<float2*>(&outb[(size_t)row*1024 + col])     = v0;
            *reinterpret_cast<float2*>(&outb[(size_t)(row+8)*1024 + col]) = v1;
#pragma unroll
            for (int j = 0; j < 4; j++) {
                float v = acc[mi][ni][j];
                s1 += v; s2 = fmaf(v, v, s2);
            }
        }
    }
    float* red = reinterpret_cast<float*>(b_sm);
    red[tid] = s1; red[256 + tid] = s2;
    __syncthreads();
    for (int st = 128; st > 0; st >>= 1) {
        if (tid < st) { red[tid] += red[tid + st]; red[256 + tid] += red[256 + tid + st]; }
        __syncthreads();
    }
    if (tid == 0) {
        int slot = (p*16 + b)*8 + sp;
        g_part2[slot][0] = red[0];
        g_part2[slot][1] = red[256];
    }
}

// =====================================================================
// GroupNorm apply (inline finalize) + exact GELU -> bf16 hi/lo operands
// Q additionally scaled by log2e (exp2-domain softmax).
// =====================================================================
__global__ __launch_bounds__(256) void norm_gelu_kernel(
    const float* __restrict__ gq, const float* __restrict__ bq,
    const float* __restrict__ gk, const float* __restrict__ bk,
    const float* __restrict__ gv, const float* __restrict__ bv)
{
    const int pb = blockIdx.z;
    const int p = pb >> 4, b = pb & 15;
    const int h = blockIdx.y;
    const int n0 = blockIdx.x * 64;
    const int tid = threadIdx.x;
    const int bhid = b*4 + h;

    const float* gamma = (p == 0) ? gq : (p == 1) ? gk : gv;
    const float* beta  = (p == 0) ? bq : (p == 1) ? bk : bv;

    float sa = 0.f, sb = 0.f;
#pragma unroll
    for (int i = 0; i < 8; i++) {
        sa += g_part2[pb*8 + i][0];
        sb += g_part2[pb*8 + i][1];
    }
    const float mean = sa / (float)CN;
    const float rstd = rsqrtf(sb / (float)CN - mean*mean + 1e-6f);

    __shared__ float s[32][65];
    const float* src = g_conv[p] + ((size_t)b * 128 + h * 32) * N_;

    if (p == 2) {
        for (int e = tid; e < 2048; e += 256) {
            int d = e >> 6, nn = e & 63;
            float v = src[(size_t)d * N_ + n0 + nn];
            int c = h * 32 + d;
            v = (v - mean) * rstd * gamma[c] + beta[c];
            v = 0.5f * v * (1.0f + erff(v * 0.70710678118654752f));
            __nv_bfloat16 hb = __float2bfloat16(v);
            float lov = v - __bfloat162float(hb);
            __nv_bfloat16 lb = __float2bfloat16(lov);
            size_t idx = ((size_t)bhid*32 + d)*1024 + n0 + nn;
            g_v_hi[idx] = *(ushort_t*)&hb;
            g_v_lo[idx] = *(ushort_t*)&lb;
        }
    } else {
        const float qscale = (p == 0) ? LOG2E : 1.0f;
        for (int e = tid; e < 2048; e += 256) {
            int d = e >> 6, nn = e & 63;
            float v = src[(size_t)d * N_ + n0 + nn];
            int c = h * 32 + d;
            v = (v - mean) * rstd * gamma[c] + beta[c];
            v = 0.5f * v * (1.0f + erff(v * 0.70710678118654752f));
            s[d][nn] = v * qscale;
        }
        __syncthreads();
        ushort_t* dhi = (p == 0) ? g_q_hi : g_k_hi;
        ushort_t* dlo = (p == 0) ? g_q_lo : g_k_lo;
        for (int e = tid; e < 2048; e += 256) {
            int nn = e >> 5, d = e & 31;
            float v = s[d][nn];
            __nv_bfloat16 hb = __float2bfloat16(v);
            float lov = v - __bfloat162float(hb);
            __nv_bfloat16 lb = __float2bfloat16(lov);
            size_t idx = ((size_t)bhid*1024 + n0 + nn)*32 + d;
            dhi[idx] = *(ushort_t*)&hb;
            dlo[idx] = *(ushort_t*)&lb;
        }
    }
}

// =====================================================================
// Attention v5: R9 shape (8 warps x 16 q-rows, 256 thr) +
// strength-reduced KV staging pointers + exp2-domain softmax.
// =====================================================================
__global__ __launch_bounds__(256, 2) void attn_mma_kernel()
{
    __shared__ __align__(16) ushort_t q_sm[2][128][40];      // 20480 B
    __shared__ __align__(16) ushort_t k_sm[2][2*64*40];      // 20480 B
    __shared__ __align__(16) ushort_t v_sm[2][2*32*72];      // 18432 B

    const int tid = threadIdx.x, lane = tid & 31, w = tid >> 5;
    const int qt = blockIdx.x, bh = blockIdx.y;
    const int b = bh >> 2, h = bh & 3;

    // precomputed staging pointers: 2 iters each for K and V
    const ushort_t* ksrc[2];
    const ushort_t* vsrc[2];
    int kdst[2], vdst[2];
#pragma unroll
    for (int i = 0; i < 2; i++) {
        int u = tid + i*256;
        {
            int quarter = u & 3, row = (u >> 2) & 63, split = u >> 8;
            ksrc[i] = (split ? g_k_lo : g_k_hi) + ((size_t)bh*1024 + row)*32 + quarter*8;
            kdst[i] = (split*64 + row)*40 + quarter*8;
        }
        {
            int seg = u & 7, d = (u >> 3) & 31, split = u >> 8;
            vsrc[i] = (split ? g_v_lo : g_v_hi) + ((size_t)bh*32 + d)*1024 + seg*8;
            vdst[i] = (split*32 + d)*72 + seg*8;
        }
    }

    auto stage_kv = [&](int kc, int bufi) {
#pragma unroll
        for (int i = 0; i < 2; i++)
            cp_async16(&k_sm[bufi][kdst[i]], ksrc[i] + kc*2048);
#pragma unroll
        for (int i = 0; i < 2; i++)
            cp_async16(&v_sm[bufi][vdst[i]], vsrc[i] + kc*64);
        cp_async_commit();
    };

    for (int u = tid; u < 1024; u += 256) {
        int quarter = u & 3, row = (u >> 2) & 127, split = u >> 9;
        const ushort_t* src = (split ? g_q_lo : g_q_hi)
            + ((size_t)bh*1024 + qt*128 + row)*32 + quarter*8;
        *reinterpret_cast<uint4*>(&q_sm[split][row][quarter*8]) =
            *reinterpret_cast<const uint4*>(src);
    }
    stage_kv(0, 0);
    __syncthreads();

    unsigned qh[2][4], ql[2][4];
#pragma unroll
    for (int kit = 0; kit < 2; kit++) {
        ldmatrix_x4(qh[kit], &q_sm[0][w*16 + (lane & 15)][kit*16 + (lane >> 4)*8]);
        ldmatrix_x4(ql[kit], &q_sm[1][w*16 + (lane & 15)][kit*16 + (lane >> 4)*8]);
    }

    const int m_idx = lane >> 3;
    const int row_in = lane & 7;
    int koff[4], voff[2];
#pragma unroll
    for (int tp = 0; tp < 4; tp++)
        koff[tp] = ((tp*2 + (m_idx >> 1))*8 + row_in)*40 + (m_idx & 1)*8;
#pragma unroll
    for (int tp = 0; tp < 2; tp++)
        voff[tp] = ((tp*2 + (m_idx >> 1))*8 + row_in)*72 + (m_idx & 1)*8;

    float O[4][4];
#pragma unroll
    for (int nd = 0; nd < 4; nd++)
#pragma unroll
        for (int j = 0; j < 4; j++) O[nd][j] = 0.f;
    float mrun0 = -INFINITY, mrun1 = -INFINITY, lrun0 = 0.f, lrun1 = 0.f;

    const int qrow0 = qt*128 + w*16 + (lane >> 2);
    const ushort_t* biasbase = g_bias4 + ((size_t)h*1024 + qrow0)*1024 + 2*(lane & 3);

    for (int kc = 0; kc < 16; kc++) {
        const int m0 = kc * 64;
        const int buf = kc & 1;
        if (kc + 1 < 16) { stage_kv(kc + 1, buf ^ 1); cp_async_wait1(); }
        else             { cp_async_wait0(); }
        __syncthreads();

        const ushort_t* kb0 = k_sm[buf];
        const ushort_t* kb1 = kb0 + 64*40;
        const ushort_t* vb0 = v_sm[buf];
        const ushort_t* vb1 = vb0 + 32*72;

        float c[8][4];
#pragma unroll
        for (int ni = 0; ni < 8; ni++)
#pragma unroll
            for (int j = 0; j < 4; j++) c[ni][j] = 0.f;

#pragma unroll
        for (int kit = 0; kit < 2; kit++) {
            unsigned kb[8][2];
#pragma unroll
            for (int tp = 0; tp < 4; tp++) {
                unsigned t4[4];
                ldmatrix_x4(t4, kb0 + koff[tp] + kit*16);
                kb[tp*2][0]=t4[0]; kb[tp*2][1]=t4[1];
                kb[tp*2+1][0]=t4[2]; kb[tp*2+1][1]=t4[3];
            }
#pragma unroll
            for (int ni = 0; ni < 8; ni++) {
                mma_bf16(c[ni], qh[kit], kb[ni][0], kb[ni][1]);
                mma_bf16(c[ni], ql[kit], kb[ni][0], kb[ni][1]);
            }
#pragma unroll
            for (int tp = 0; tp < 4; tp++) {
                unsigned t4[4];
                ldmatrix_x4(t4, kb1 + koff[tp] + kit*16);
                kb[tp*2][0]=t4[0]; kb[tp*2][1]=t4[1];
                kb[tp*2+1][0]=t4[2]; kb[tp*2+1][1]=t4[3];
            }
#pragma unroll
            for (int ni = 0; ni < 8; ni++)
                mma_bf16(c[ni], qh[kit], kb[ni][0], kb[ni][1]);
        }

        // bias (bf16, log2-domain) + online softmax via exp2
        const ushort_t* b0p = biasbase + m0;
        const ushort_t* b1p = b0p + 8*1024;
        float rm0 = -INFINITY, rm1 = -INFINITY;
#pragma unroll
        for (int ni = 0; ni < 8; ni++) {
            unsigned u0 = *reinterpret_cast<const unsigned*>(b0p + ni*8);
            unsigned u1 = *reinterpret_cast<const unsigned*>(b1p + ni*8);
            c[ni][0] += lowerf(u0); c[ni][1] += upperf(u0);
            c[ni][2] += lowerf(u1); c[ni][3] += upperf(u1);
            rm0 = fmaxf(rm0, fmaxf(c[ni][0], c[ni][1]));
            rm1 = fmaxf(rm1, fmaxf(c[ni][2], c[ni][3]));
        }
        rm0 = fmaxf(rm0, __shfl_xor_sync(0xffffffffu, rm0, 1));
        rm0 = fmaxf(rm0, __shfl_xor_sync(0xffffffffu, rm0, 2));
        rm1 = fmaxf(rm1, __shfl_xor_sync(0xffffffffu, rm1, 1));
        rm1 = fmaxf(rm1, __shfl_xor_sync(0xffffffffu, rm1, 2));
        float mnew0 = fmaxf(mrun0, rm0), mnew1 = fmaxf(mrun1, rm1);
        float corr0 = ex2(mrun0 - mnew0), corr1 = ex2(mrun1 - mnew1);
        mrun0 = mnew0; mrun1 = mnew1;
        float rs0 = 0.f, rs1 = 0.f;
#pragma unroll
        for (int ni = 0; ni < 8; ni++) {
            c[ni][0] = ex2(c[ni][0] - mnew0);
            c[ni][1] = ex2(c[ni][1] - mnew0);
            c[ni][2] = ex2(c[ni][2] - mnew1);
            c[ni][3] = ex2(c[ni][3] - mnew1);
            rs0 += c[ni][0] + c[ni][1];
            rs1 += c[ni][2] + c[ni][3];
        }
        rs0 += __shfl_xor_sync(0xffffffffu, rs0, 1);
        rs0 += __shfl_xor_sync(0xffffffffu, rs0, 2);
        rs1 += __shfl_xor_sync(0xffffffffu, rs1, 1);
        rs1 += __shfl_xor_sync(0xffffffffu, rs1, 2);
        lrun0 = lrun0 * corr0 + rs0;
        lrun1 = lrun1 * corr1 + rs1;
#pragma unroll
        for (int nd = 0; nd < 4; nd++) {
            O[nd][0] *= corr0; O[nd][1] *= corr0;
            O[nd][2] *= corr1; O[nd][3] *= corr1;
        }

#pragma unroll
        for (int t = 0; t < 4; t++) {
            int j0 = 2*t, j1 = 2*t + 1;
            unsigned ph[4], pl[4];
            ph[0] = packbf(c[j0][1], c[j0][0]);
            ph[1] = packbf(c[j0][3], c[j0][2]);
            ph[2] = packbf(c[j1][1], c[j1][0]);
            ph[3] = packbf(c[j1][3], c[j1][2]);
            pl[0] = packbf(c[j0][1] - upperf(ph[0]), c[j0][0] - lowerf(ph[0]));
            pl[1] = packbf(c[j0][3] - upperf(ph[1]), c[j0][2] - lowerf(ph[1]));
            pl[2] = packbf(c[j1][1] - upperf(ph[2]), c[j1][0] - lowerf(ph[2]));
            pl[3] = packbf(c[j1][3] - upperf(ph[3]), c[j1][2] - lowerf(ph[3]));

            unsigned vb[4][2];
#pragma unroll
            for (int tp = 0; tp < 2; tp++) {
                unsigned t4[4];
                ldmatrix_x4(t4, vb0 + voff[tp] + t*16);
                vb[tp*2][0]=t4[0]; vb[tp*2][1]=t4[1];
                vb[tp*2+1][0]=t4[2]; vb[tp*2+1][1]=t4[3];
            }
#pragma unroll
            for (int nd = 0; nd < 4; nd++) {
                mma_bf16(O[nd], ph, vb[nd][0], vb[nd][1]);
                mma_bf16(O[nd], pl, vb[nd][0], vb[nd][1]);
            }
#pragma unroll
            for (int tp = 0; tp < 2; tp++) {
                unsigned t4[4];
                ldmatrix_x4(t4, vb1 + voff[tp] + t*16);
                vb[tp*2][0]=t4[0]; vb[tp*2][1]=t4[1];
                vb[tp*2+1][0]=t4[2]; vb[tp*2+1][1]=t4[3];
            }
#pragma unroll
            for (int nd = 0; nd < 4; nd++)
                mma_bf16(O[nd], ph, vb[nd][0], vb[nd][1]);
        }
        __syncthreads();
    }

    // epilogue: bf16 hi/lo split output [b][n][c]
    float il0 = 1.f / lrun0, il1 = 1.f / lrun1;
    const size_t base0 = ((size_t)b*1024 + qrow0)*128 + h*32 + 2*(lane & 3);
    const size_t base1 = base0 + 8*128;
#pragma unroll
    for (int nd = 0; nd < 4; nd++) {
        float a0 = O[nd][0]*il0, a1 = O[nd][1]*il0;
        float b0 = O[nd][2]*il1, b1 = O[nd][3]*il1;
        unsigned h0 = packbf(a1, a0);
        unsigned l0 = packbf(a1 - upperf(h0), a0 - lowerf(h0));
        unsigned h1 = packbf(b1, b0);
        unsigned l1 = packbf(b1 - upperf(h1), b0 - lowerf(h1));
        *reinterpret_cast<unsigned*>(&g_ao_hi[base0 + nd*8]) = h0;
        *reinterpret_cast<unsigned*>(&g_ao_lo[base0 + nd*8]) = l0;
        *reinterpret_cast<unsigned*>(&g_ao_hi[base1 + nd*8]) = h1;
        *reinterpret_cast<unsigned*>(&g_ao_lo[base1 + nd*8]) = l1;
    }
}

// =====================================================================
// 1x1 conv via tensor cores (bf16x3), + bias.
// =====================================================================
__global__ __launch_bounds__(256, 2) void outconv_mma_kernel(
    const float* __restrict__ bias, float* __restrict__ out)
{
    __shared__ __align__(16) ushort_t a_sm[2][128*40];
    __shared__ __align__(16) ushort_t b_sm[2][128*40];

    const int bx = blockIdx.x, b = blockIdx.y;
    const int n0 = bx * 128;
    const int tid = threadIdx.x, lane = tid & 31, wid = tid >> 5;
    const int wm = wid & 1, wn = wid >> 1;
    const int m_idx = lane >> 3;
    const int row_in = lane & 7;

    float acc[4][4][4];
#pragma unroll
    for (int mi = 0; mi < 4; mi++)
#pragma unroll
        for (int ni = 0; ni < 4; ni++)
#pragma unroll
            for (int j = 0; j < 4; j++) acc[mi][ni][j] = 0.f;

    int aoff[4];
#pragma unroll
    for (int mi = 0; mi < 4; mi++)
        aoff[mi] = (wm*64 + mi*16 + (lane & 15))*40 + (lane >> 4)*8;
    int boff[2];
#pragma unroll
    for (int tp = 0; tp < 2; tp++) {
        int tile = tp*2 + (m_idx >> 1);
        int n = wn*32 + tile*8 + row_in;
        boff[tp] = n*40 + (m_idx & 1)*8;
    }

    auto stage = [&](int ck, int bufi) {
        int c0 = ck * 16;
        for (int u = tid; u < 512; u += 256) {
            int half = u & 1, co = (u >> 1) & 127, split = u >> 8;
            const ushort_t* src = (split ? g_w2_lo : g_w2_hi) + co*128 + c0 + half*8;
            cp_async16(&a_sm[bufi][co*40 + split*16 + half*8], src);
        }
        for (int u = tid; u < 512; u += 256) {
            int half = u & 1, n = (u >> 1) & 127, split = u >> 8;
            const ushort_t* src = (split ? g_ao_lo : g_ao_hi)
                + ((size_t)b*1024 + n0 + n)*128 + c0 + half*8;
            cp_async16(&b_sm[bufi][n*40 + split*16 + half*8], src);
        }
        cp_async_commit();
    };

    stage(0, 0);
    for (int ck = 0; ck < 8; ck++) {
        const int buf = ck & 1;
        if (ck + 1 < 8) { stage(ck + 1, buf ^ 1); cp_async_wait1(); }
        else            { cp_async_wait0(); }
        __syncthreads();

        const ushort_t* ab = a_sm[buf];
        const ushort_t* bb = b_sm[buf];

        unsigned Ah[4][4], bf[4][2], bl[4][2];
#pragma unroll
        for (int mi = 0; mi < 4; mi++)
            ldmatrix_x4(Ah[mi], ab + aoff[mi]);
        {
            unsigned t4[4];
            ldmatrix_x4(t4, bb + boff[0]);
            bf[0][0]=t4[0]; bf[0][1]=t4[1]; bf[1][0]=t4[2]; bf[1][1]=t4[3];
            ldmatrix_x4(t4, bb + boff[1]);
            bf[2][0]=t4[0]; bf[2][1]=t4[1]; bf[3][0]=t4[2]; bf[3][1]=t4[3];
            ldmatrix_x4(t4, bb + boff[0] + 16);
            bl[0][0]=t4[0]; bl[0][1]=t4[1]; bl[1][0]=t4[2]; bl[1][1]=t4[3];
            ldmatrix_x4(t4, bb + boff[1] + 16);
            bl[2][0]=t4[0]; bl[2][1]=t4[1]; bl[3][0]=t4[2]; bl[3][1]=t4[3];
        }
#pragma unroll
        for (int ni = 0; ni < 4; ni++)
#pragma unroll
            for (int mi = 0; mi < 4; mi++) {
                mma_bf16(acc[mi][ni], Ah[mi], bf[ni][0], bf[ni][1]);
                mma_bf16(acc[mi][ni], Ah[mi], bl[ni][0], bl[ni][1]);
            }
#pragma unroll
        for (int mi = 0; mi < 4; mi++)
            ldmatrix_x4(Ah[mi], ab + aoff[mi] + 16);
#pragma unroll
        for (int ni = 0; ni < 4; ni++)
#pragma unroll
            for (int mi = 0; mi < 4; mi++)
                mma_bf16(acc[mi][ni], Ah[mi], bf[ni][0], bf[ni][1]);
        __syncthreads();
    }

#pragma unroll
    for (int mi = 0; mi < 4; mi++) {
        int row = wm*64 + mi*16 + (lane >> 2);
        float bv0 = bias[row], bv1 = bias[row + 8];
#pragma unroll
        for (int ni = 0; ni < 4; ni++) {
            int col = n0 + wn*32 + ni*8 + (lane & 3)*2;
            float2 v0; v0.x = acc[mi][ni][0] + bv0; v0.y = acc[mi][ni][1] + bv0;
            float2 v1; v1.x = acc[mi][ni][2] + bv1; v1.y = acc[mi][ni][3] + bv1;
            *reinterpret_cast<float2*>(&out[((size_t)b*128 + row)*1024 + col])     = v0;
            *reinterpret_cast<float2*>(&out[((size_t)b*128 + row + 8)*1024 + col]) = v1;
        }
    }
}

// =====================================================================
extern "C" void kernel_launch(void* const* d_in, const int* in_sizes, int n_in,
                              void* d_out, int out_size)
{
    const float* x      = (const float*)d_in[0];
    const float* wq     = (const float*)d_in[1];
    const float* gq     = (const float*)d_in[2];
    const float* bq     = (const float*)d_in[3];
    const float* wk     = (const float*)d_in[4];
    const float* gk     = (const float*)d_in[5];
    const float* bk     = (const float*)d_in[6];
    const float* wv     = (const float*)d_in[7];
    const float* gv     = (const float*)d_in[8];
    const float* bv     = (const float*)d_in[9];
    const float* table  = (const float*)d_in[10];
    const int*   relidx = (const int*)  d_in[11];
    const float* out_w  = (const float*)d_in[12];
    const float* out_b  = (const float*)d_in[13];
    float* out = (float*)d_out;

    prep_all_kernel<<<4864, 256>>>(x, wq, wk, wv, out_w, table, relidx); // 0
    conv_mma_kernel<<<dim3(8, 16, 3), 256>>>();                          // 1
    norm_gelu_kernel<<<dim3(16, 4, 48), 256>>>(gq, bq, gk, bk, gv, bv);  // 2
    attn_mma_kernel<<<dim3(8, 64), 256>>>();                             // 3  <- profiled
    outconv_mma_kernel<<<dim3(8, 16), 256>>>(out_b, out);                // 4
}